// round 10
// baseline (speedup 1.0000x reference)
#include <cuda_runtime.h>
#include <cuda_bf16.h>
#include <math.h>
#include <stdint.h>

// Problem constants
#define BB 8
#define SS 1024
#define DIN 512
#define HH 1024
#define NHEAD 16
#define HD 64
#define NLAYER 4
#define MROWS (BB * SS)   // 8192

// ---------------------------------------------------------------------------
// Scratch (device globals; no allocation allowed)
// ---------------------------------------------------------------------------
__device__ float g_h[MROWS * HH];
__device__ float g_tmp[MROWS * HH];
__device__ float g_pool[BB * HH];
__device__ float g_fin[BB * HH];

__device__ __nv_bfloat16 g_ah[MROWS * HH];
__device__ __nv_bfloat16 g_al[MROWS * HH];
__device__ __nv_bfloat16 g_hh[MROWS * HH];
__device__ __nv_bfloat16 g_hl[MROWS * HH];
__device__ __nv_bfloat16 g_qh[MROWS * 3 * HH];
__device__ __nv_bfloat16 g_ql[MROWS * 3 * HH];
__device__ __nv_bfloat16 g_ch[MROWS * HH];
__device__ __nv_bfloat16 g_cl[MROWS * HH];

#define W_TOTAL (DIN * HH + NLAYER * HH * 3 * HH + NLAYER * HH * HH)
__device__ __nv_bfloat16 g_wh[W_TOTAL];
__device__ __nv_bfloat16 g_wl[W_TOTAL];

#define OFF_WIN  0
#define OFF_WQKV ((size_t)DIN * HH)
#define OFF_WO   (OFF_WQKV + (size_t)NLAYER * HH * 3 * HH)

// ---------------------------------------------------------------------------
// PTX wrappers (sm_80-portable)
// ---------------------------------------------------------------------------
__device__ __forceinline__ uint32_t smem_u32(const void* p) {
    uint32_t a;
    asm("{ .reg .u64 t; cvta.to.shared.u64 t, %1; cvt.u32.u64 %0, t; }"
        : "=r"(a) : "l"(p));
    return a;
}
__device__ __forceinline__ void cp_async16(uint32_t dst, const void* src) {
    asm volatile("cp.async.cg.shared.global [%0], [%1], 16;" :: "r"(dst), "l"(src));
}
__device__ __forceinline__ void cp_commit() {
    asm volatile("cp.async.commit_group;");
}
template <int N>
__device__ __forceinline__ void cp_wait() {
    asm volatile("cp.async.wait_group %0;" :: "n"(N));
}
__device__ __forceinline__ void ldsm_x4(uint32_t addr, uint32_t r[4]) {
    asm volatile("ldmatrix.sync.aligned.m8n8.x4.shared.b16 {%0,%1,%2,%3}, [%4];"
                 : "=r"(r[0]), "=r"(r[1]), "=r"(r[2]), "=r"(r[3]) : "r"(addr));
}
__device__ __forceinline__ void ldsm_x4_t(uint32_t addr, uint32_t r[4]) {
    asm volatile("ldmatrix.sync.aligned.m8n8.x4.trans.shared.b16 {%0,%1,%2,%3}, [%4];"
                 : "=r"(r[0]), "=r"(r[1]), "=r"(r[2]), "=r"(r[3]) : "r"(addr));
}
__device__ __forceinline__ void mma_bf16(
    float c[4], const uint32_t a[4], const uint32_t b0, const uint32_t b1)
{
    asm volatile(
        "mma.sync.aligned.m16n8k16.row.col.f32.bf16.bf16.f32 "
        "{%0,%1,%2,%3}, {%4,%5,%6,%7}, {%8,%9}, {%0,%1,%2,%3};"
        : "+f"(c[0]), "+f"(c[1]), "+f"(c[2]), "+f"(c[3])
        : "r"(a[0]), "r"(a[1]), "r"(a[2]), "r"(a[3]), "r"(b0), "r"(b1));
}
__device__ __forceinline__ void split2(float a, float b, uint32_t& hi, uint32_t& lo) {
    __nv_bfloat16 ha = __float2bfloat16(a), hb = __float2bfloat16(b);
    __nv_bfloat162 h2; h2.x = ha; h2.y = hb;
    hi = *(uint32_t*)&h2;
    __nv_bfloat162 l2;
    l2.x = __float2bfloat16(a - __bfloat162float(ha));
    l2.y = __float2bfloat16(b - __bfloat162float(hb));
    lo = *(uint32_t*)&l2;
}

// ---------------------------------------------------------------------------
// Batched weight transpose + split (single launch, all 9 matrices)
// ---------------------------------------------------------------------------
#define T_WIN   512
#define T_WQKV  3072
#define T_WO    1024
#define T_TOTAL (T_WIN + NLAYER * T_WQKV + NLAYER * T_WO)

__global__ void __launch_bounds__(256) transpose_split_all(
    const float* __restrict__ W_in, const float* __restrict__ W_qkv,
    const float* __restrict__ W_o,
    __nv_bfloat16* __restrict__ wh, __nv_bfloat16* __restrict__ wl)
{
    __shared__ float tile[32][33];
    int idx = blockIdx.x;
    const float* W;
    int K, N, t;
    size_t woff;
    if (idx < T_WIN) {
        W = W_in; K = DIN; N = HH; woff = OFF_WIN; t = idx;
    } else if (idx < T_WIN + NLAYER * T_WQKV) {
        const int l = (idx - T_WIN) / T_WQKV;
        t = (idx - T_WIN) % T_WQKV;
        W = W_qkv + (size_t)l * HH * 3 * HH;
        K = HH; N = 3 * HH;
        woff = OFF_WQKV + (size_t)l * 3 * HH * HH;
    } else {
        const int l = (idx - T_WIN - NLAYER * T_WQKV) / T_WO;
        t = (idx - T_WIN - NLAYER * T_WQKV) % T_WO;
        W = W_o + (size_t)l * HH * HH;
        K = HH; N = HH;
        woff = OFF_WO + (size_t)l * HH * HH;
    }
    const int tpr = N / 32;
    const int n0 = (t % tpr) * 32;
    const int k0 = (t / tpr) * 32;
    const int tx = threadIdx.x & 31;
    const int ty = threadIdx.x >> 5;

#pragma unroll
    for (int r = 0; r < 32; r += 8)
        tile[ty + r][tx] = W[(size_t)(k0 + ty + r) * N + n0 + tx];
    __syncthreads();
#pragma unroll
    for (int r = 0; r < 32; r += 8) {
        const float v = tile[tx][ty + r];
        const __nv_bfloat16 h = __float2bfloat16(v);
        const float lo = v - __bfloat162float(h);
        const size_t o = woff + (size_t)(n0 + ty + r) * K + k0 + tx;
        wh[o] = h;
        wl[o] = __float2bfloat16(lo);
    }
}

// ---------------------------------------------------------------------------
// Activation split (x only)
// ---------------------------------------------------------------------------
__global__ void split_act_kernel(
    const float* __restrict__ in,
    __nv_bfloat16* __restrict__ hi, __nv_bfloat16* __restrict__ lo, int n4)
{
    const int i = blockIdx.x * 256 + threadIdx.x;
    if (i >= n4) return;
    const float4 v = ((const float4*)in)[i];
    uint32_t h0, l0, h1, l1;
    split2(v.x, v.y, h0, l0);
    split2(v.z, v.w, h1, l1);
    ((uint32_t*)hi)[i * 2]     = h0;
    ((uint32_t*)hi)[i * 2 + 1] = h1;
    ((uint32_t*)lo)[i * 2]     = l0;
    ((uint32_t*)lo)[i * 2 + 1] = l1;
}

// ---------------------------------------------------------------------------
// Split-bf16 HMMA GEMM — R10: 64x64 warp tiles, 4 warps (128 threads),
// 2-stage / 2-barrier schedule (R4-verified). LDSM per HMMA cut 33%.
// ---------------------------------------------------------------------------
#define MBM 128
#define MBN 128
#define MBK 32
#define MSTR 40
#define MTILE (128 * MSTR * 2)    // 10240 B per tile (128 rows x 80 B)
#define MSTAGE (4 * MTILE)        // Ah, Al, Bh, Bl
#define MM_SMEM (2 * MSTAGE)      // 81920 B -> 2 CTAs/SM

__global__ void __launch_bounds__(128)
mma_gemm_kernel(
    const __nv_bfloat16* __restrict__ Ah, const __nv_bfloat16* __restrict__ Al,
    const __nv_bfloat16* __restrict__ Bh, const __nv_bfloat16* __restrict__ Bl,
    const float* __restrict__ bias, const float* __restrict__ res,
    float* __restrict__ Cf,
    __nv_bfloat16* __restrict__ Ch, __nv_bfloat16* __restrict__ Cl,
    int M, int N, int K, int hasRes, int mode)
{
    extern __shared__ __align__(16) char smem[];
    const uint32_t sbase = smem_u32(smem);

    const int t    = threadIdx.x;
    const int wid  = t >> 5;
    const int lane = t & 31;
    const int m0 = blockIdx.y * MBM;
    const int n0 = blockIdx.x * MBN;

    const int warp_m = (wid >> 1) * 64;   // 0 or 64
    const int warp_n = (wid & 1) * 64;    // 0 or 64

    // copy indexing: thread t loads row t of each of the 4 tiles, 4 granules
    const __nv_bfloat16* gsrc[4];
    gsrc[0] = Ah + (size_t)(m0 + t) * K;
    gsrc[1] = Al + (size_t)(m0 + t) * K;
    gsrc[2] = Bh + (size_t)(n0 + t) * K;
    gsrc[3] = Bl + (size_t)(n0 + t) * K;
    const uint32_t sdst_row = (uint32_t)t * (MSTR * 2);

    const int nc = K / MBK;

    {
#pragma unroll
        for (int tl = 0; tl < 4; tl++) {
            const uint32_t d = sbase + tl * MTILE + sdst_row;
#pragma unroll
            for (int i = 0; i < 4; i++)
                cp_async16(d + i * 16, gsrc[tl] + i * 8);
        }
        cp_commit();
    }

    float acc[4][8][4];
#pragma unroll
    for (int mi = 0; mi < 4; mi++)
#pragma unroll
        for (int ni = 0; ni < 8; ni++)
#pragma unroll
            for (int r = 0; r < 4; r++) acc[mi][ni][r] = 0.0f;

    const int lrow = lane & 15;
    const int lcolq = (lane >> 4) << 3;

    for (int c = 0; c < nc; c++) {
        const int st = c & 1;
        if (c + 1 < nc) {
            const int k0 = (c + 1) * MBK;
            const uint32_t so = ((c + 1) & 1) * MSTAGE;
#pragma unroll
            for (int tl = 0; tl < 4; tl++) {
                const uint32_t d = sbase + so + tl * MTILE + sdst_row;
#pragma unroll
                for (int i = 0; i < 4; i++)
                    cp_async16(d + i * 16, gsrc[tl] + k0 + i * 8);
            }
            cp_commit();
            cp_wait<1>();
        } else {
            cp_wait<0>();
        }
        __syncthreads();

        const uint32_t sAh = sbase + st * MSTAGE + 0 * MTILE;
        const uint32_t sAl = sbase + st * MSTAGE + 1 * MTILE;
        const uint32_t sBh = sbase + st * MSTAGE + 2 * MTILE;
        const uint32_t sBl = sbase + st * MSTAGE + 3 * MTILE;

#pragma unroll
        for (int ks = 0; ks < 2; ks++) {
            const int col = ks * 16 + lcolq;
            uint32_t afh[4][4], afl[4][4];
#pragma unroll
            for (int mi = 0; mi < 4; mi++) {
                const uint32_t off =
                    (uint32_t)(warp_m + mi * 16 + lrow) * (MSTR * 2) + col * 2;
                ldsm_x4(sAh + off, afh[mi]);
                ldsm_x4(sAl + off, afl[mi]);
            }
            // B loaded per n2 to bound live registers; each fragment feeds
            // 4 mi x 2 nb x 3 split-terms = 24 HMMA.
#pragma unroll
            for (int n2 = 0; n2 < 4; n2++) {
                const uint32_t off =
                    (uint32_t)(warp_n + n2 * 16 + lrow) * (MSTR * 2) + col * 2;
                uint32_t rh[4], rl[4];
                ldsm_x4(sBh + off, rh);
                ldsm_x4(sBl + off, rl);
                const int nb0 = n2 * 2, nb1 = n2 * 2 + 1;
#pragma unroll
                for (int mi = 0; mi < 4; mi++) {
                    mma_bf16(acc[mi][nb0], afh[mi], rh[0], rh[2]);
                    mma_bf16(acc[mi][nb1], afh[mi], rh[1], rh[3]);
                    mma_bf16(acc[mi][nb0], afh[mi], rl[0], rl[2]);
                    mma_bf16(acc[mi][nb1], afh[mi], rl[1], rl[3]);
                    mma_bf16(acc[mi][nb0], afl[mi], rh[0], rh[2]);
                    mma_bf16(acc[mi][nb1], afl[mi], rh[1], rh[3]);
                }
            }
        }
        __syncthreads();   // WAR guard: next iter's prefetch overwrites the
                           // other stage, which warps may still be reading.
    }

    const int g  = lane >> 2;
    const int tg = lane & 3;
#pragma unroll
    for (int mi = 0; mi < 4; mi++) {
#pragma unroll
        for (int ni = 0; ni < 8; ni++) {
            const int colg = n0 + warp_n + ni * 8 + tg * 2;
            const float bx = bias[colg], by = bias[colg + 1];
            const int r0 = m0 + warp_m + mi * 16 + g;
            const int r1 = r0 + 8;
            float2 o0, o1;
            o0.x = acc[mi][ni][0] + bx; o0.y = acc[mi][ni][1] + by;
            o1.x = acc[mi][ni][2] + bx; o1.y = acc[mi][ni][3] + by;
            if (hasRes) {
                const float2 v0 = *(const float2*)(res + (size_t)r0 * N + colg);
                const float2 v1 = *(const float2*)(res + (size_t)r1 * N + colg);
                o0.x += v0.x; o0.y += v0.y;
                o1.x += v1.x; o1.y += v1.y;
            }
            if (mode & 1) {
                *(float2*)(Cf + (size_t)r0 * N + colg) = o0;
                *(float2*)(Cf + (size_t)r1 * N + colg) = o1;
            }
            if (mode & 2) {
                uint32_t hi, lo;
                split2(o0.x, o0.y, hi, lo);
                *(uint32_t*)(Ch + (size_t)r0 * N + colg) = hi;
                *(uint32_t*)(Cl + (size_t)r0 * N + colg) = lo;
                split2(o1.x, o1.y, hi, lo);
                *(uint32_t*)(Ch + (size_t)r1 * N + colg) = hi;
                *(uint32_t*)(Cl + (size_t)r1 * N + colg) = lo;
            }
        }
    }
}

// ---------------------------------------------------------------------------
// Tensor-core flash attention, split-bf16 operands.
// 128-row Q tiles, 256 threads (8 warps x 16 q-rows). (R7/R9 — passing.)
// ---------------------------------------------------------------------------
#define APAD 144
#define ATILE (64 * APAD)                    // K/V tile: 64 rows
#define AQTILE (128 * APAD)                  // Q tile: 128 rows
#define AQ_H 0
#define AQ_L AQTILE
#define AST0 (2 * AQTILE)
#define ASTG (4 * ATILE)
#define AT_SMEM (2 * AQTILE + 2 * ASTG)      // 110592

__global__ void __launch_bounds__(256)
attn_mma_kernel(
    const __nv_bfloat16* __restrict__ qh, const __nv_bfloat16* __restrict__ ql,
    __nv_bfloat16* __restrict__ cth, __nv_bfloat16* __restrict__ ctl)
{
    extern __shared__ __align__(16) char smem[];
    const uint32_t sbase = smem_u32(smem);

    const int b  = blockIdx.z;
    const int nh = blockIdx.y;
    const int qt = blockIdx.x;
    const int t  = threadIdx.x;
    const int wid  = t >> 5;
    const int lane = t & 31;
    const int g  = lane >> 2;
    const int tg = lane & 3;
    const int lrow  = lane & 15;
    const int lcolq = (lane >> 4) << 3;

    const size_t bS = (size_t)b * SS;
    const int hoff = nh * HD;

    {
        const int crw = t >> 1;
        const int cqq = (t & 1) * 4;
        const size_t grow = (bS + qt * 128 + crw) * (3 * HH) + hoff;
        const uint32_t d = sbase + crw * APAD + cqq * 16;
#pragma unroll
        for (int i = 0; i < 4; i++) {
            cp_async16(d + AQ_H + i * 16, qh + grow + (cqq + i) * 8);
            cp_async16(d + AQ_L + i * 16, ql + grow + (cqq + i) * 8);
        }
    }

    const int tt   = t & 127;
    const int kv   = t >> 7;
    const int crow = tt >> 1;
    const int cq0  = (tt & 1) * 4;
    const int srcoff = (kv + 1) * HH;
    const uint32_t tile_h = (kv * 2 + 0) * ATILE;
    const uint32_t tile_l = (kv * 2 + 1) * ATILE;

#pragma unroll
    for (int p = 0; p < 2; p++) {
        const size_t grow = (bS + p * 64 + crow) * (3 * HH) + hoff + srcoff;
        const uint32_t d = sbase + AST0 + p * ASTG + crow * APAD + cq0 * 16;
#pragma unroll
        for (int i = 0; i < 4; i++) {
            cp_async16(d + tile_h + i * 16, qh + grow + (cq0 + i) * 8);
            cp_async16(d + tile_l + i * 16, ql + grow + (cq0 + i) * 8);
        }
        cp_commit();
    }

    float acc_o[8][4];
#pragma unroll
    for (int nb = 0; nb < 8; nb++)
#pragma unroll
        for (int r = 0; r < 4; r++) acc_o[nb][r] = 0.0f;

    uint32_t aqh[4][4], aql[4][4];
    float m0 = -INFINITY, m1 = -INFINITY;
    float l0 = 0.0f, l1 = 0.0f;
    const float SC = 0.125f;

    for (int kt = 0; kt < SS / 64; kt++) {
        if (kt == SS / 64 - 1) { cp_wait<0>(); } else { cp_wait<1>(); }
        __syncthreads();

        if (kt == 0) {
#pragma unroll
            for (int kb = 0; kb < 4; kb++) {
                const uint32_t off =
                    (uint32_t)(wid * 16 + lrow) * APAD + (kb * 16 + lcolq) * 2;
                ldsm_x4(sbase + AQ_H + off, aqh[kb]);
                ldsm_x4(sbase + AQ_L + off, aql[kb]);
            }
        }

        const uint32_t sK_h = sbase + AST0 + (kt & 1) * ASTG + 0 * ATILE;
        const uint32_t sK_l = sbase + AST0 + (kt & 1) * ASTG + 1 * ATILE;
        const uint32_t sV_h = sbase + AST0 + (kt & 1) * ASTG + 2 * ATILE;
        const uint32_t sV_l = sbase + AST0 + (kt & 1) * ASTG + 3 * ATILE;

        float s[8][4];
#pragma unroll
        for (int nb = 0; nb < 8; nb++)
#pragma unroll
            for (int r = 0; r < 4; r++) s[nb][r] = 0.0f;

#pragma unroll
        for (int n2 = 0; n2 < 4; n2++) {
#pragma unroll
            for (int kb = 0; kb < 4; kb++) {
                const uint32_t off =
                    (uint32_t)(n2 * 16 + lrow) * APAD + (kb * 16 + lcolq) * 2;
                uint32_t kh4[4], kl4[4];
                ldsm_x4(sK_h + off, kh4);
                ldsm_x4(sK_l + off, kl4);
                mma_bf16(s[n2 * 2 + 0], aqh[kb], kh4[0], kh4[2]);
                mma_bf16(s[n2 * 2 + 1], aqh[kb], kh4[1], kh4[3]);
                mma_bf16(s[n2 * 2 + 0], aqh[kb], kl4[0], kl4[2]);
                mma_bf16(s[n2 * 2 + 1], aqh[kb], kl4[1], kl4[3]);
                mma_bf16(s[n2 * 2 + 0], aql[kb], kh4[0], kh4[2]);
                mma_bf16(s[n2 * 2 + 1], aql[kb], kh4[1], kh4[3]);
            }
        }

        float mx0 = -INFINITY, mx1 = -INFINITY;
#pragma unroll
        for (int nb = 0; nb < 8; nb++) {
            s[nb][0] *= SC; s[nb][1] *= SC; s[nb][2] *= SC; s[nb][3] *= SC;
            mx0 = fmaxf(mx0, fmaxf(s[nb][0], s[nb][1]));
            mx1 = fmaxf(mx1, fmaxf(s[nb][2], s[nb][3]));
        }
        mx0 = fmaxf(mx0, __shfl_xor_sync(0xffffffffu, mx0, 1));
        mx0 = fmaxf(mx0, __shfl_xor_sync(0xffffffffu, mx0, 2));
        mx1 = fmaxf(mx1, __shfl_xor_sync(0xffffffffu, mx1, 1));
        mx1 = fmaxf(mx1, __shfl_xor_sync(0xffffffffu, mx1, 2));
        const float mn0 = fmaxf(m0, mx0);
        const float mn1 = fmaxf(m1, mx1);
        const float f0 = __expf(m0 - mn0);
        const float f1 = __expf(m1 - mn1);
        m0 = mn0; m1 = mn1;
        l0 *= f0; l1 *= f1;
#pragma unroll
        for (int nb = 0; nb < 8; nb++) {
            s[nb][0] = __expf(s[nb][0] - mn0);
            s[nb][1] = __expf(s[nb][1] - mn0);
            s[nb][2] = __expf(s[nb][2] - mn1);
            s[nb][3] = __expf(s[nb][3] - mn1);
            l0 += s[nb][0] + s[nb][1];
            l1 += s[nb][2] + s[nb][3];
            acc_o[nb][0] *= f0; acc_o[nb][1] *= f0;
            acc_o[nb][2] *= f1; acc_o[nb][3] *= f1;
        }

        uint32_t ph[4][4], pl[4][4];
#pragma unroll
        for (int kb = 0; kb < 4; kb++) {
            split2(s[2 * kb][0],     s[2 * kb][1],     ph[kb][0], pl[kb][0]);
            split2(s[2 * kb][2],     s[2 * kb][3],     ph[kb][1], pl[kb][1]);
            split2(s[2 * kb + 1][0], s[2 * kb + 1][1], ph[kb][2], pl[kb][2]);
            split2(s[2 * kb + 1][2], s[2 * kb + 1][3], ph[kb][3], pl[kb][3]);
        }

#pragma unroll
        for (int kb = 0; kb < 4; kb++) {
#pragma unroll
            for (int n2 = 0; n2 < 4; n2++) {
                const uint32_t off =
                    (uint32_t)(kb * 16 + lrow) * APAD + (n2 * 16 + lcolq) * 2;
                uint32_t vh4[4], vl4[4];
                ldsm_x4_t(sV_h + off, vh4);
                ldsm_x4_t(sV_l + off, vl4);
                mma_bf16(acc_o[n2 * 2 + 0], ph[kb], vh4[0], vh4[1]);
                mma_bf16(acc_o[n2 * 2 + 1], ph[kb], vh4[2], vh4[3]);
                mma_bf16(acc_o[n2 * 2 + 0], ph[kb], vl4[0], vl4[1]);
                mma_bf16(acc_o[n2 * 2 + 1], ph[kb], vl4[2], vl4[3]);
                mma_bf16(acc_o[n2 * 2 + 0], pl[kb], vh4[0], vh4[1]);
                mma_bf16(acc_o[n2 * 2 + 1], pl[kb], vh4[2], vh4[3]);
            }
        }

        __syncthreads();   // WAR guard: prefetch below writes the stage read above
        if (kt + 2 < SS / 64) {
            const size_t grow = (bS + (kt + 2) * 64 + crow) * (3 * HH) + hoff + srcoff;
            const uint32_t d = sbase + AST0 + (kt & 1) * ASTG + crow * APAD + cq0 * 16;
#pragma unroll
            for (int i = 0; i < 4; i++) {
                cp_async16(d + tile_h + i * 16, qh + grow + (cq0 + i) * 8);
                cp_async16(d + tile_l + i * 16, ql + grow + (cq0 + i) * 8);
            }
        }
        cp_commit();
    }

    l0 += __shfl_xor_sync(0xffffffffu, l0, 1);
    l0 += __shfl_xor_sync(0xffffffffu, l0, 2);
    l1 += __shfl_xor_sync(0xffffffffu, l1, 1);
    l1 += __shfl_xor_sync(0xffffffffu, l1, 2);
    const float inv0 = 1.0f / l0;
    const float inv1 = 1.0f / l1;

    const size_t r0 = bS + qt * 128 + wid * 16 + g;
    const size_t r1 = r0 + 8;
#pragma unroll
    for (int nb = 0; nb < 8; nb++) {
        const int col = hoff + nb * 8 + tg * 2;
        uint32_t hi, lo;
        split2(acc_o[nb][0] * inv0, acc_o[nb][1] * inv0, hi, lo);
        *(uint32_t*)(cth + r0 * HH + col) = hi;
        *(uint32_t*)(ctl + r0 * HH + col) = lo;
        split2(acc_o[nb][2] * inv1, acc_o[nb][3] * inv1, hi, lo);
        *(uint32_t*)(cth + r1 * HH + col) = hi;
        *(uint32_t*)(ctl + r1 * HH + col) = lo;
    }
}

// ---------------------------------------------------------------------------
// One-pass warp-per-row LayerNorm (row = 1024 floats = 32/lane in regs).
// ---------------------------------------------------------------------------
__global__ void __launch_bounds__(256) ln_kernel(
    const float* __restrict__ in, const float* __restrict__ gamma,
    const float* __restrict__ beta, float* __restrict__ out,
    __nv_bfloat16* __restrict__ outh, __nv_bfloat16* __restrict__ outl,
    int doSplit)
{
    const int warp = threadIdx.x >> 5;
    const int lane = threadIdx.x & 31;
    const int row  = blockIdx.x * 8 + warp;
    const float* x = in + (size_t)row * HH;

    float v[32];
    float s = 0.0f;
#pragma unroll
    for (int k = 0; k < 8; k++) {
        const float4 t4 = *(const float4*)&x[(k * 32 + lane) * 4];
        v[k * 4 + 0] = t4.x; v[k * 4 + 1] = t4.y;
        v[k * 4 + 2] = t4.z; v[k * 4 + 3] = t4.w;
        s += (t4.x + t4.y) + (t4.z + t4.w);
    }
#pragma unroll
    for (int o = 16; o > 0; o >>= 1) s += __shfl_xor_sync(0xffffffffu, s, o);
    const float mean = s * (1.0f / HH);

    float var = 0.0f;
#pragma unroll
    for (int i = 0; i < 32; i++) {
        const float d = v[i] - mean;
        var += d * d;
    }
#pragma unroll
    for (int o = 16; o > 0; o >>= 1) var += __shfl_xor_sync(0xffffffffu, var, o);
    const float rstd = rsqrtf(var * (1.0f / HH) + 1e-5f);

#pragma unroll
    for (int k = 0; k < 8; k++) {
        const int i0 = (k * 32 + lane) * 4;
        const float4 gv = *(const float4*)&gamma[i0];
        const float4 bv = *(const float4*)&beta[i0];
        float4 o;
        o.x = (v[k * 4 + 0] - mean) * rstd * gv.x + bv.x;
        o.y = (v[k * 4 + 1] - mean) * rstd * gv.y + bv.y;
        o.z = (v[k * 4 + 2] - mean) * rstd * gv.z + bv.z;
        o.w = (v[k * 4 + 3] - mean) * rstd * gv.w + bv.w;
        *(float4*)&out[(size_t)row * HH + i0] = o;
        if (doSplit) {
            uint32_t h0, lo0, h1, lo1;
            split2(o.x, o.y, h0, lo0);
            split2(o.z, o.w, h1, lo1);
            uint2 hv; hv.x = h0; hv.y = h1;
            uint2 lv; lv.x = lo0; lv.y = lo1;
            *(uint2*)(outh + (size_t)row * HH + i0) = hv;
            *(uint2*)(outl + (size_t)row * HH + i0) = lv;
        }
    }
}

__global__ void __launch_bounds__(256) pool_kernel(
    const float* __restrict__ h, float* __restrict__ pooled)
{
    const int j = blockIdx.x * 256 + threadIdx.x;
    const int b = blockIdx.y;
    float s = 0.0f;
#pragma unroll 8
    for (int ss = 0; ss < SS; ss++)
        s += h[((size_t)b * SS + ss) * HH + j];
    pooled[b * HH + j] = s * (1.0f / SS);
}

__global__ void __launch_bounds__(256) final_gemm_kernel(
    const float* __restrict__ pooled, const float* __restrict__ W,
    const float* __restrict__ bias, float* __restrict__ out)
{
    __shared__ float pr[HH];
    const int b   = blockIdx.y;
    const int col = blockIdx.x * 256 + threadIdx.x;
    for (int i = threadIdx.x; i < HH; i += 256) pr[i] = pooled[b * HH + i];
    __syncthreads();
    float s = bias[col];
#pragma unroll 8
    for (int k = 0; k < HH; k++)
        s += pr[k] * W[(size_t)k * HH + col];
    out[b * HH + col] = s;
}

// ---------------------------------------------------------------------------
// Launch
// ---------------------------------------------------------------------------
extern "C" void kernel_launch(void* const* d_in, const int* in_sizes, int n_in,
                              void* d_out, int out_size)
{
    const float* x     = (const float*)d_in[0];
    const float* W_in  = (const float*)d_in[1];
    const float* b_in  = (const float*)d_in[2];
    const float* W_qkv = (const float*)d_in[3];
    const float* b_qkv = (const float*)d_in[4];
    const float* W_o   = (const float*)d_in[5];
    const float* b_o   = (const float*)d_in[6];
    const float* g1    = (const float*)d_in[7];
    const float* be1   = (const float*)d_in[8];
    const float* W_out = (const float*)d_in[9];
    const float* b_out = (const float*)d_in[10];
    const float* g2    = (const float*)d_in[11];
    const float* be2   = (const float*)d_in[12];
    float* out = (float*)d_out;

    float *h, *tmp, *pool, *fin;
    cudaGetSymbolAddress((void**)&h,    g_h);
    cudaGetSymbolAddress((void**)&tmp,  g_tmp);
    cudaGetSymbolAddress((void**)&pool, g_pool);
    cudaGetSymbolAddress((void**)&fin,  g_fin);

    __nv_bfloat16 *ah, *al, *hh, *hl, *qh, *ql, *ch, *cl, *wh, *wl;
    cudaGetSymbolAddress((void**)&ah, g_ah);
    cudaGetSymbolAddress((void**)&al, g_al);
    cudaGetSymbolAddress((void**)&hh, g_hh);
    cudaGetSymbolAddress((void**)&hl, g_hl);
    cudaGetSymbolAddress((void**)&qh, g_qh);
    cudaGetSymbolAddress((void**)&ql, g_ql);
    cudaGetSymbolAddress((void**)&ch, g_ch);
    cudaGetSymbolAddress((void**)&cl, g_cl);
    cudaGetSymbolAddress((void**)&wh, g_wh);
    cudaGetSymbolAddress((void**)&wl, g_wl);

    cudaFuncSetAttribute(mma_gemm_kernel, cudaFuncAttributeMaxDynamicSharedMemorySize, MM_SMEM);
    cudaFuncSetAttribute(attn_mma_kernel, cudaFuncAttributeMaxDynamicSharedMemorySize, AT_SMEM);

    // 0. batched weight transpose+split
    transpose_split_all<<<T_TOTAL, 256>>>(W_in, W_qkv, W_o, wh, wl);

    // 1. split x; in-proj -> h fp32 + split
    {
        const int n4 = MROWS * DIN / 4;
        split_act_kernel<<<(n4 + 255) / 256, 256>>>(x, ah, al, n4);
        mma_gemm_kernel<<<dim3(HH / MBN, MROWS / MBM), 128, MM_SMEM>>>(
            ah, al, wh + OFF_WIN, wl + OFF_WIN, b_in, nullptr,
            h, hh, hl, MROWS, HH, DIN, 0, 3);
    }

    // 2. layers
    for (int l = 0; l < NLAYER; l++) {
        const __nv_bfloat16* WqH = wh + OFF_WQKV + (size_t)l * 3 * HH * HH;
        const __nv_bfloat16* WqL = wl + OFF_WQKV + (size_t)l * 3 * HH * HH;
        const __nv_bfloat16* WoH = wh + OFF_WO + (size_t)l * HH * HH;
        const __nv_bfloat16* WoL = wl + OFF_WO + (size_t)l * HH * HH;
        const float* bq = b_qkv + (size_t)l * 3 * HH;
        const float* bo = b_o + (size_t)l * HH;
        const float* gg = g1 + (size_t)l * HH;
        const float* bb = be1 + (size_t)l * HH;

        mma_gemm_kernel<<<dim3(3 * HH / MBN, MROWS / MBM), 128, MM_SMEM>>>(
            hh, hl, WqH, WqL, bq, nullptr,
            nullptr, qh, ql, MROWS, 3 * HH, HH, 0, 2);

        attn_mma_kernel<<<dim3(SS / 128, NHEAD, BB), 256, AT_SMEM>>>(qh, ql, ch, cl);

        mma_gemm_kernel<<<dim3(HH / MBN, MROWS / MBM), 128, MM_SMEM>>>(
            ch, cl, WoH, WoL, bo, h,
            tmp, nullptr, nullptr, MROWS, HH, HH, 1, 1);

        ln_kernel<<<MROWS / 8, 256>>>(tmp, gg, bb, h, hh, hl, 1);
    }

    // 3. mean pool, final projection + LN (8 rows, 8 warps, 1 block)
    pool_kernel<<<dim3(HH / 256, BB), 256>>>(h, pool);
    final_gemm_kernel<<<dim3(HH / 256, BB), 256>>>(pool, W_out, b_out, fin);
    ln_kernel<<<1, 256>>>(fin, g2, be2, out, nullptr, nullptr, 0);
}

// round 11
// speedup vs baseline: 1.0662x; 1.0662x over previous
#include <cuda_runtime.h>
#include <cuda_bf16.h>
#include <math.h>
#include <stdint.h>

// Problem constants
#define BB 8
#define SS 1024
#define DIN 512
#define HH 1024
#define NHEAD 16
#define HD 64
#define NLAYER 4
#define MROWS (BB * SS)   // 8192

// ---------------------------------------------------------------------------
// Scratch (device globals; no allocation allowed)
// ---------------------------------------------------------------------------
__device__ float g_h[MROWS * HH];
__device__ float g_tmp[MROWS * HH];
__device__ float g_pool[BB * HH];
__device__ float g_fin[BB * HH];

__device__ __nv_bfloat16 g_ah[MROWS * HH];
__device__ __nv_bfloat16 g_al[MROWS * HH];
__device__ __nv_bfloat16 g_hh[MROWS * HH];
__device__ __nv_bfloat16 g_hl[MROWS * HH];
__device__ __nv_bfloat16 g_qh[MROWS * 3 * HH];
__device__ __nv_bfloat16 g_ql[MROWS * 3 * HH];
__device__ __nv_bfloat16 g_ch[MROWS * HH];
__device__ __nv_bfloat16 g_cl[MROWS * HH];

#define W_TOTAL (DIN * HH + NLAYER * HH * 3 * HH + NLAYER * HH * HH)
__device__ __nv_bfloat16 g_wh[W_TOTAL];
__device__ __nv_bfloat16 g_wl[W_TOTAL];

#define OFF_WIN  0
#define OFF_WQKV ((size_t)DIN * HH)
#define OFF_WO   (OFF_WQKV + (size_t)NLAYER * HH * 3 * HH)

// ---------------------------------------------------------------------------
// PTX wrappers (sm_80-portable)
// ---------------------------------------------------------------------------
__device__ __forceinline__ uint32_t smem_u32(const void* p) {
    uint32_t a;
    asm("{ .reg .u64 t; cvta.to.shared.u64 t, %1; cvt.u32.u64 %0, t; }"
        : "=r"(a) : "l"(p));
    return a;
}
__device__ __forceinline__ void cp_async16(uint32_t dst, const void* src) {
    asm volatile("cp.async.cg.shared.global [%0], [%1], 16;" :: "r"(dst), "l"(src));
}
__device__ __forceinline__ void cp_commit() {
    asm volatile("cp.async.commit_group;");
}
template <int N>
__device__ __forceinline__ void cp_wait() {
    asm volatile("cp.async.wait_group %0;" :: "n"(N));
}
__device__ __forceinline__ void ldsm_x4(uint32_t addr, uint32_t r[4]) {
    asm volatile("ldmatrix.sync.aligned.m8n8.x4.shared.b16 {%0,%1,%2,%3}, [%4];"
                 : "=r"(r[0]), "=r"(r[1]), "=r"(r[2]), "=r"(r[3]) : "r"(addr));
}
__device__ __forceinline__ void ldsm_x4_t(uint32_t addr, uint32_t r[4]) {
    asm volatile("ldmatrix.sync.aligned.m8n8.x4.trans.shared.b16 {%0,%1,%2,%3}, [%4];"
                 : "=r"(r[0]), "=r"(r[1]), "=r"(r[2]), "=r"(r[3]) : "r"(addr));
}
__device__ __forceinline__ void mma_bf16(
    float c[4], const uint32_t a[4], const uint32_t b0, const uint32_t b1)
{
    asm volatile(
        "mma.sync.aligned.m16n8k16.row.col.f32.bf16.bf16.f32 "
        "{%0,%1,%2,%3}, {%4,%5,%6,%7}, {%8,%9}, {%0,%1,%2,%3};"
        : "+f"(c[0]), "+f"(c[1]), "+f"(c[2]), "+f"(c[3])
        : "r"(a[0]), "r"(a[1]), "r"(a[2]), "r"(a[3]), "r"(b0), "r"(b1));
}
__device__ __forceinline__ float ex2f(float x) {
    float r;
    asm("ex2.approx.f32 %0, %1;" : "=f"(r) : "f"(x));
    return r;
}
__device__ __forceinline__ void split2(float a, float b, uint32_t& hi, uint32_t& lo) {
    __nv_bfloat16 ha = __float2bfloat16(a), hb = __float2bfloat16(b);
    __nv_bfloat162 h2; h2.x = ha; h2.y = hb;
    hi = *(uint32_t*)&h2;
    __nv_bfloat162 l2;
    l2.x = __float2bfloat16(a - __bfloat162float(ha));
    l2.y = __float2bfloat16(b - __bfloat162float(hb));
    lo = *(uint32_t*)&l2;
}

// ---------------------------------------------------------------------------
// Batched weight transpose + split (single launch, all 9 matrices)
// ---------------------------------------------------------------------------
#define T_WIN   512
#define T_WQKV  3072
#define T_WO    1024
#define T_TOTAL (T_WIN + NLAYER * T_WQKV + NLAYER * T_WO)

__global__ void __launch_bounds__(256) transpose_split_all(
    const float* __restrict__ W_in, const float* __restrict__ W_qkv,
    const float* __restrict__ W_o,
    __nv_bfloat16* __restrict__ wh, __nv_bfloat16* __restrict__ wl)
{
    __shared__ float tile[32][33];
    int idx = blockIdx.x;
    const float* W;
    int K, N, t;
    size_t woff;
    if (idx < T_WIN) {
        W = W_in; K = DIN; N = HH; woff = OFF_WIN; t = idx;
    } else if (idx < T_WIN + NLAYER * T_WQKV) {
        const int l = (idx - T_WIN) / T_WQKV;
        t = (idx - T_WIN) % T_WQKV;
        W = W_qkv + (size_t)l * HH * 3 * HH;
        K = HH; N = 3 * HH;
        woff = OFF_WQKV + (size_t)l * 3 * HH * HH;
    } else {
        const int l = (idx - T_WIN - NLAYER * T_WQKV) / T_WO;
        t = (idx - T_WIN - NLAYER * T_WQKV) % T_WO;
        W = W_o + (size_t)l * HH * HH;
        K = HH; N = HH;
        woff = OFF_WO + (size_t)l * HH * HH;
    }
    const int tpr = N / 32;
    const int n0 = (t % tpr) * 32;
    const int k0 = (t / tpr) * 32;
    const int tx = threadIdx.x & 31;
    const int ty = threadIdx.x >> 5;

#pragma unroll
    for (int r = 0; r < 32; r += 8)
        tile[ty + r][tx] = W[(size_t)(k0 + ty + r) * N + n0 + tx];
    __syncthreads();
#pragma unroll
    for (int r = 0; r < 32; r += 8) {
        const float v = tile[tx][ty + r];
        const __nv_bfloat16 h = __float2bfloat16(v);
        const float lo = v - __bfloat162float(h);
        const size_t o = woff + (size_t)(n0 + ty + r) * K + k0 + tx;
        wh[o] = h;
        wl[o] = __float2bfloat16(lo);
    }
}

// ---------------------------------------------------------------------------
// Activation split (x only)
// ---------------------------------------------------------------------------
__global__ void split_act_kernel(
    const float* __restrict__ in,
    __nv_bfloat16* __restrict__ hi, __nv_bfloat16* __restrict__ lo, int n4)
{
    const int i = blockIdx.x * 256 + threadIdx.x;
    if (i >= n4) return;
    const float4 v = ((const float4*)in)[i];
    uint32_t h0, l0, h1, l1;
    split2(v.x, v.y, h0, l0);
    split2(v.z, v.w, h1, l1);
    ((uint32_t*)hi)[i * 2]     = h0;
    ((uint32_t*)hi)[i * 2 + 1] = h1;
    ((uint32_t*)lo)[i * 2]     = l0;
    ((uint32_t*)lo)[i * 2 + 1] = l1;
}

// ---------------------------------------------------------------------------
// Split-bf16 HMMA GEMM — R9 config (best measured): 64x32 warp tiles,
// 8 warps, 2-stage/2-barrier. R11: per-warp ks order stagger to decorrelate
// LDSM vs HMMA phases across warps.
// ---------------------------------------------------------------------------
#define MBM 128
#define MBN 128
#define MBK 32
#define MSTR 40
#define MTILE (128 * MSTR * 2)
#define MSTAGE (4 * MTILE)
#define MM_SMEM (2 * MSTAGE)

__global__ void __launch_bounds__(256)
mma_gemm_kernel(
    const __nv_bfloat16* __restrict__ Ah, const __nv_bfloat16* __restrict__ Al,
    const __nv_bfloat16* __restrict__ Bh, const __nv_bfloat16* __restrict__ Bl,
    const float* __restrict__ bias, const float* __restrict__ res,
    float* __restrict__ Cf,
    __nv_bfloat16* __restrict__ Ch, __nv_bfloat16* __restrict__ Cl,
    int M, int N, int K, int hasRes, int mode)
{
    extern __shared__ __align__(16) char smem[];
    const uint32_t sbase = smem_u32(smem);

    const int t    = threadIdx.x;
    const int wid  = t >> 5;
    const int lane = t & 31;
    const int m0 = blockIdx.y * MBM;
    const int n0 = blockIdx.x * MBN;

    const int warp_m = (wid >> 2) * 64;
    const int warp_n = (wid & 3) * 32;
    const int ksx    = wid & 1;       // ks phase stagger by warp parity

    const int crow  = t >> 1;
    const int cq    = (t & 1) * 2;

    const __nv_bfloat16* gsrc[4];
    gsrc[0] = Ah + (size_t)(m0 + crow) * K;
    gsrc[1] = Al + (size_t)(m0 + crow) * K;
    gsrc[2] = Bh + (size_t)(n0 + crow) * K;
    gsrc[3] = Bl + (size_t)(n0 + crow) * K;
    const uint32_t sdst_row = crow * (MSTR * 2);

    const int nc = K / MBK;

    {
#pragma unroll
        for (int tl = 0; tl < 4; tl++) {
            const uint32_t d = sbase + tl * MTILE + sdst_row;
            cp_async16(d + (cq + 0) * 16, gsrc[tl] + (cq + 0) * 8);
            cp_async16(d + (cq + 1) * 16, gsrc[tl] + (cq + 1) * 8);
        }
        cp_commit();
    }

    float acc[4][4][4];
#pragma unroll
    for (int mi = 0; mi < 4; mi++)
#pragma unroll
        for (int ni = 0; ni < 4; ni++)
#pragma unroll
            for (int r = 0; r < 4; r++) acc[mi][ni][r] = 0.0f;

    const int lrow = lane & 15;
    const int lcolq = (lane >> 4) << 3;

    for (int c = 0; c < nc; c++) {
        const int st = c & 1;
        if (c + 1 < nc) {
            const int k0 = (c + 1) * MBK;
            const uint32_t so = ((c + 1) & 1) * MSTAGE;
#pragma unroll
            for (int tl = 0; tl < 4; tl++) {
                const uint32_t d = sbase + so + tl * MTILE + sdst_row;
                cp_async16(d + (cq + 0) * 16, gsrc[tl] + k0 + (cq + 0) * 8);
                cp_async16(d + (cq + 1) * 16, gsrc[tl] + k0 + (cq + 1) * 8);
            }
            cp_commit();
            cp_wait<1>();
        } else {
            cp_wait<0>();
        }
        __syncthreads();

        const uint32_t sAh = sbase + st * MSTAGE + 0 * MTILE;
        const uint32_t sAl = sbase + st * MSTAGE + 1 * MTILE;
        const uint32_t sBh = sbase + st * MSTAGE + 2 * MTILE;
        const uint32_t sBl = sbase + st * MSTAGE + 3 * MTILE;

#pragma unroll
        for (int ksi = 0; ksi < 2; ksi++) {
            const int ks = ksi ^ ksx;        // stagger: odd warps run ks=1 first
            const int col = ks * 16 + lcolq;
            uint32_t afh[4][4], afl[4][4];
#pragma unroll
            for (int mi = 0; mi < 4; mi++) {
                const uint32_t off =
                    (uint32_t)(warp_m + mi * 16 + lrow) * (MSTR * 2) + col * 2;
                ldsm_x4(sAh + off, afh[mi]);
                ldsm_x4(sAl + off, afl[mi]);
            }
            uint32_t bfh[4][2], bfl[4][2];
#pragma unroll
            for (int n2 = 0; n2 < 2; n2++) {
                const uint32_t off =
                    (uint32_t)(warp_n + n2 * 16 + lrow) * (MSTR * 2) + col * 2;
                uint32_t r4[4];
                ldsm_x4(sBh + off, r4);
                bfh[n2 * 2 + 0][0] = r4[0]; bfh[n2 * 2 + 1][0] = r4[1];
                bfh[n2 * 2 + 0][1] = r4[2]; bfh[n2 * 2 + 1][1] = r4[3];
                ldsm_x4(sBl + off, r4);
                bfl[n2 * 2 + 0][0] = r4[0]; bfl[n2 * 2 + 1][0] = r4[1];
                bfl[n2 * 2 + 0][1] = r4[2]; bfl[n2 * 2 + 1][1] = r4[3];
            }
#pragma unroll
            for (int mi = 0; mi < 4; mi++)
#pragma unroll
                for (int ni = 0; ni < 4; ni++) {
                    mma_bf16(acc[mi][ni], afh[mi], bfh[ni][0], bfh[ni][1]);
                    mma_bf16(acc[mi][ni], afh[mi], bfl[ni][0], bfl[ni][1]);
                    mma_bf16(acc[mi][ni], afl[mi], bfh[ni][0], bfh[ni][1]);
                }
        }
        __syncthreads();   // WAR guard on the recycled stage
    }

    const int g  = lane >> 2;
    const int tg = lane & 3;
#pragma unroll
    for (int mi = 0; mi < 4; mi++) {
#pragma unroll
        for (int ni = 0; ni < 4; ni++) {
            const int colg = n0 + warp_n + ni * 8 + tg * 2;
            const float bx = bias[colg], by = bias[colg + 1];
            const int r0 = m0 + warp_m + mi * 16 + g;
            const int r1 = r0 + 8;
            float2 o0, o1;
            o0.x = acc[mi][ni][0] + bx; o0.y = acc[mi][ni][1] + by;
            o1.x = acc[mi][ni][2] + bx; o1.y = acc[mi][ni][3] + by;
            if (hasRes) {
                const float2 v0 = *(const float2*)(res + (size_t)r0 * N + colg);
                const float2 v1 = *(const float2*)(res + (size_t)r1 * N + colg);
                o0.x += v0.x; o0.y += v0.y;
                o1.x += v1.x; o1.y += v1.y;
            }
            if (mode & 1) {
                *(float2*)(Cf + (size_t)r0 * N + colg) = o0;
                *(float2*)(Cf + (size_t)r1 * N + colg) = o1;
            }
            if (mode & 2) {
                uint32_t hi, lo;
                split2(o0.x, o0.y, hi, lo);
                *(uint32_t*)(Ch + (size_t)r0 * N + colg) = hi;
                *(uint32_t*)(Cl + (size_t)r0 * N + colg) = lo;
                split2(o1.x, o1.y, hi, lo);
                *(uint32_t*)(Ch + (size_t)r1 * N + colg) = hi;
                *(uint32_t*)(Cl + (size_t)r1 * N + colg) = lo;
            }
        }
    }
}

// ---------------------------------------------------------------------------
// Tensor-core flash attention, split-bf16 operands.
// 128-row Q tiles, 256 threads. R11: base-2 softmax (ex2.approx).
// ---------------------------------------------------------------------------
#define APAD 144
#define ATILE (64 * APAD)
#define AQTILE (128 * APAD)
#define AQ_H 0
#define AQ_L AQTILE
#define AST0 (2 * AQTILE)
#define ASTG (4 * ATILE)
#define AT_SMEM (2 * AQTILE + 2 * ASTG)      // 110592

__global__ void __launch_bounds__(256)
attn_mma_kernel(
    const __nv_bfloat16* __restrict__ qh, const __nv_bfloat16* __restrict__ ql,
    __nv_bfloat16* __restrict__ cth, __nv_bfloat16* __restrict__ ctl)
{
    extern __shared__ __align__(16) char smem[];
    const uint32_t sbase = smem_u32(smem);

    const int b  = blockIdx.z;
    const int nh = blockIdx.y;
    const int qt = blockIdx.x;
    const int t  = threadIdx.x;
    const int wid  = t >> 5;
    const int lane = t & 31;
    const int g  = lane >> 2;
    const int tg = lane & 3;
    const int lrow  = lane & 15;
    const int lcolq = (lane >> 4) << 3;

    const size_t bS = (size_t)b * SS;
    const int hoff = nh * HD;

    {
        const int crw = t >> 1;
        const int cqq = (t & 1) * 4;
        const size_t grow = (bS + qt * 128 + crw) * (3 * HH) + hoff;
        const uint32_t d = sbase + crw * APAD + cqq * 16;
#pragma unroll
        for (int i = 0; i < 4; i++) {
            cp_async16(d + AQ_H + i * 16, qh + grow + (cqq + i) * 8);
            cp_async16(d + AQ_L + i * 16, ql + grow + (cqq + i) * 8);
        }
    }

    const int tt   = t & 127;
    const int kv   = t >> 7;
    const int crow = tt >> 1;
    const int cq0  = (tt & 1) * 4;
    const int srcoff = (kv + 1) * HH;
    const uint32_t tile_h = (kv * 2 + 0) * ATILE;
    const uint32_t tile_l = (kv * 2 + 1) * ATILE;

#pragma unroll
    for (int p = 0; p < 2; p++) {
        const size_t grow = (bS + p * 64 + crow) * (3 * HH) + hoff + srcoff;
        const uint32_t d = sbase + AST0 + p * ASTG + crow * APAD + cq0 * 16;
#pragma unroll
        for (int i = 0; i < 4; i++) {
            cp_async16(d + tile_h + i * 16, qh + grow + (cq0 + i) * 8);
            cp_async16(d + tile_l + i * 16, ql + grow + (cq0 + i) * 8);
        }
        cp_commit();
    }

    float acc_o[8][4];
#pragma unroll
    for (int nb = 0; nb < 8; nb++)
#pragma unroll
        for (int r = 0; r < 4; r++) acc_o[nb][r] = 0.0f;

    uint32_t aqh[4][4], aql[4][4];
    float m0 = -INFINITY, m1 = -INFINITY;
    float l0 = 0.0f, l1 = 0.0f;
    const float SC2 = 0.125f * 1.4426950408889634f;   // SCALE * log2(e)

    for (int kt = 0; kt < SS / 64; kt++) {
        if (kt == SS / 64 - 1) { cp_wait<0>(); } else { cp_wait<1>(); }
        __syncthreads();

        if (kt == 0) {
#pragma unroll
            for (int kb = 0; kb < 4; kb++) {
                const uint32_t off =
                    (uint32_t)(wid * 16 + lrow) * APAD + (kb * 16 + lcolq) * 2;
                ldsm_x4(sbase + AQ_H + off, aqh[kb]);
                ldsm_x4(sbase + AQ_L + off, aql[kb]);
            }
        }

        const uint32_t sK_h = sbase + AST0 + (kt & 1) * ASTG + 0 * ATILE;
        const uint32_t sK_l = sbase + AST0 + (kt & 1) * ASTG + 1 * ATILE;
        const uint32_t sV_h = sbase + AST0 + (kt & 1) * ASTG + 2 * ATILE;
        const uint32_t sV_l = sbase + AST0 + (kt & 1) * ASTG + 3 * ATILE;

        float s[8][4];
#pragma unroll
        for (int nb = 0; nb < 8; nb++)
#pragma unroll
            for (int r = 0; r < 4; r++) s[nb][r] = 0.0f;

#pragma unroll
        for (int n2 = 0; n2 < 4; n2++) {
#pragma unroll
            for (int kb = 0; kb < 4; kb++) {
                const uint32_t off =
                    (uint32_t)(n2 * 16 + lrow) * APAD + (kb * 16 + lcolq) * 2;
                uint32_t kh4[4], kl4[4];
                ldsm_x4(sK_h + off, kh4);
                ldsm_x4(sK_l + off, kl4);
                mma_bf16(s[n2 * 2 + 0], aqh[kb], kh4[0], kh4[2]);
                mma_bf16(s[n2 * 2 + 1], aqh[kb], kh4[1], kh4[3]);
                mma_bf16(s[n2 * 2 + 0], aqh[kb], kl4[0], kl4[2]);
                mma_bf16(s[n2 * 2 + 1], aqh[kb], kl4[1], kl4[3]);
                mma_bf16(s[n2 * 2 + 0], aql[kb], kh4[0], kh4[2]);
                mma_bf16(s[n2 * 2 + 1], aql[kb], kh4[1], kh4[3]);
            }
        }

        // base-2 online softmax (all values in log2 domain)
        float mx0 = -INFINITY, mx1 = -INFINITY;
#pragma unroll
        for (int nb = 0; nb < 8; nb++) {
            s[nb][0] *= SC2; s[nb][1] *= SC2; s[nb][2] *= SC2; s[nb][3] *= SC2;
            mx0 = fmaxf(mx0, fmaxf(s[nb][0], s[nb][1]));
            mx1 = fmaxf(mx1, fmaxf(s[nb][2], s[nb][3]));
        }
        mx0 = fmaxf(mx0, __shfl_xor_sync(0xffffffffu, mx0, 1));
        mx0 = fmaxf(mx0, __shfl_xor_sync(0xffffffffu, mx0, 2));
        mx1 = fmaxf(mx1, __shfl_xor_sync(0xffffffffu, mx1, 1));
        mx1 = fmaxf(mx1, __shfl_xor_sync(0xffffffffu, mx1, 2));
        const float mn0 = fmaxf(m0, mx0);
        const float mn1 = fmaxf(m1, mx1);
        const float f0 = ex2f(m0 - mn0);
        const float f1 = ex2f(m1 - mn1);
        m0 = mn0; m1 = mn1;
        l0 *= f0; l1 *= f1;
#pragma unroll
        for (int nb = 0; nb < 8; nb++) {
            s[nb][0] = ex2f(s[nb][0] - mn0);
            s[nb][1] = ex2f(s[nb][1] - mn0);
            s[nb][2] = ex2f(s[nb][2] - mn1);
            s[nb][3] = ex2f(s[nb][3] - mn1);
            l0 += s[nb][0] + s[nb][1];
            l1 += s[nb][2] + s[nb][3];
            acc_o[nb][0] *= f0; acc_o[nb][1] *= f0;
            acc_o[nb][2] *= f1; acc_o[nb][3] *= f1;
        }

        uint32_t ph[4][4], pl[4][4];
#pragma unroll
        for (int kb = 0; kb < 4; kb++) {
            split2(s[2 * kb][0],     s[2 * kb][1],     ph[kb][0], pl[kb][0]);
            split2(s[2 * kb][2],     s[2 * kb][3],     ph[kb][1], pl[kb][1]);
            split2(s[2 * kb + 1][0], s[2 * kb + 1][1], ph[kb][2], pl[kb][2]);
            split2(s[2 * kb + 1][2], s[2 * kb + 1][3], ph[kb][3], pl[kb][3]);
        }

#pragma unroll
        for (int kb = 0; kb < 4; kb++) {
#pragma unroll
            for (int n2 = 0; n2 < 4; n2++) {
                const uint32_t off =
                    (uint32_t)(kb * 16 + lrow) * APAD + (n2 * 16 + lcolq) * 2;
                uint32_t vh4[4], vl4[4];
                ldsm_x4_t(sV_h + off, vh4);
                ldsm_x4_t(sV_l + off, vl4);
                mma_bf16(acc_o[n2 * 2 + 0], ph[kb], vh4[0], vh4[1]);
                mma_bf16(acc_o[n2 * 2 + 1], ph[kb], vh4[2], vh4[3]);
                mma_bf16(acc_o[n2 * 2 + 0], ph[kb], vl4[0], vl4[1]);
                mma_bf16(acc_o[n2 * 2 + 1], ph[kb], vl4[2], vl4[3]);
                mma_bf16(acc_o[n2 * 2 + 0], pl[kb], vh4[0], vh4[1]);
                mma_bf16(acc_o[n2 * 2 + 1], pl[kb], vh4[2], vh4[3]);
            }
        }

        __syncthreads();   // WAR guard: prefetch below writes the stage read above
        if (kt + 2 < SS / 64) {
            const size_t grow = (bS + (kt + 2) * 64 + crow) * (3 * HH) + hoff + srcoff;
            const uint32_t d = sbase + AST0 + (kt & 1) * ASTG + crow * APAD + cq0 * 16;
#pragma unroll
            for (int i = 0; i < 4; i++) {
                cp_async16(d + tile_h + i * 16, qh + grow + (cq0 + i) * 8);
                cp_async16(d + tile_l + i * 16, ql + grow + (cq0 + i) * 8);
            }
        }
        cp_commit();
    }

    l0 += __shfl_xor_sync(0xffffffffu, l0, 1);
    l0 += __shfl_xor_sync(0xffffffffu, l0, 2);
    l1 += __shfl_xor_sync(0xffffffffu, l1, 1);
    l1 += __shfl_xor_sync(0xffffffffu, l1, 2);
    const float inv0 = 1.0f / l0;
    const float inv1 = 1.0f / l1;

    const size_t r0 = bS + qt * 128 + wid * 16 + g;
    const size_t r1 = r0 + 8;
#pragma unroll
    for (int nb = 0; nb < 8; nb++) {
        const int col = hoff + nb * 8 + tg * 2;
        uint32_t hi, lo;
        split2(acc_o[nb][0] * inv0, acc_o[nb][1] * inv0, hi, lo);
        *(uint32_t*)(cth + r0 * HH + col) = hi;
        *(uint32_t*)(ctl + r0 * HH + col) = lo;
        split2(acc_o[nb][2] * inv1, acc_o[nb][3] * inv1, hi, lo);
        *(uint32_t*)(cth + r1 * HH + col) = hi;
        *(uint32_t*)(ctl + r1 * HH + col) = lo;
    }
}

// ---------------------------------------------------------------------------
// One-pass warp-per-row LayerNorm
// ---------------------------------------------------------------------------
__global__ void __launch_bounds__(256) ln_kernel(
    const float* __restrict__ in, const float* __restrict__ gamma,
    const float* __restrict__ beta, float* __restrict__ out,
    __nv_bfloat16* __restrict__ outh, __nv_bfloat16* __restrict__ outl,
    int doSplit)
{
    const int warp = threadIdx.x >> 5;
    const int lane = threadIdx.x & 31;
    const int row  = blockIdx.x * 8 + warp;
    const float* x = in + (size_t)row * HH;

    float v[32];
    float s = 0.0f;
#pragma unroll
    for (int k = 0; k < 8; k++) {
        const float4 t4 = *(const float4*)&x[(k * 32 + lane) * 4];
        v[k * 4 + 0] = t4.x; v[k * 4 + 1] = t4.y;
        v[k * 4 + 2] = t4.z; v[k * 4 + 3] = t4.w;
        s += (t4.x + t4.y) + (t4.z + t4.w);
    }
#pragma unroll
    for (int o = 16; o > 0; o >>= 1) s += __shfl_xor_sync(0xffffffffu, s, o);
    const float mean = s * (1.0f / HH);

    float var = 0.0f;
#pragma unroll
    for (int i = 0; i < 32; i++) {
        const float d = v[i] - mean;
        var += d * d;
    }
#pragma unroll
    for (int o = 16; o > 0; o >>= 1) var += __shfl_xor_sync(0xffffffffu, var, o);
    const float rstd = rsqrtf(var * (1.0f / HH) + 1e-5f);

#pragma unroll
    for (int k = 0; k < 8; k++) {
        const int i0 = (k * 32 + lane) * 4;
        const float4 gv = *(const float4*)&gamma[i0];
        const float4 bv = *(const float4*)&beta[i0];
        float4 o;
        o.x = (v[k * 4 + 0] - mean) * rstd * gv.x + bv.x;
        o.y = (v[k * 4 + 1] - mean) * rstd * gv.y + bv.y;
        o.z = (v[k * 4 + 2] - mean) * rstd * gv.z + bv.z;
        o.w = (v[k * 4 + 3] - mean) * rstd * gv.w + bv.w;
        *(float4*)&out[(size_t)row * HH + i0] = o;
        if (doSplit) {
            uint32_t h0, lo0, h1, lo1;
            split2(o.x, o.y, h0, lo0);
            split2(o.z, o.w, h1, lo1);
            uint2 hv; hv.x = h0; hv.y = h1;
            uint2 lv; lv.x = lo0; lv.y = lo1;
            *(uint2*)(outh + (size_t)row * HH + i0) = hv;
            *(uint2*)(outl + (size_t)row * HH + i0) = lv;
        }
    }
}

__global__ void __launch_bounds__(256) pool_kernel(
    const float* __restrict__ h, float* __restrict__ pooled)
{
    const int j = blockIdx.x * 256 + threadIdx.x;
    const int b = blockIdx.y;
    float s = 0.0f;
#pragma unroll 8
    for (int ss = 0; ss < SS; ss++)
        s += h[((size_t)b * SS + ss) * HH + j];
    pooled[b * HH + j] = s * (1.0f / SS);
}

__global__ void __launch_bounds__(256) final_gemm_kernel(
    const float* __restrict__ pooled, const float* __restrict__ W,
    const float* __restrict__ bias, float* __restrict__ out)
{
    __shared__ float pr[HH];
    const int b   = blockIdx.y;
    const int col = blockIdx.x * 256 + threadIdx.x;
    for (int i = threadIdx.x; i < HH; i += 256) pr[i] = pooled[b * HH + i];
    __syncthreads();
    float s = bias[col];
#pragma unroll 8
    for (int k = 0; k < HH; k++)
        s += pr[k] * W[(size_t)k * HH + col];
    out[b * HH + col] = s;
}

// ---------------------------------------------------------------------------
// Launch
// ---------------------------------------------------------------------------
extern "C" void kernel_launch(void* const* d_in, const int* in_sizes, int n_in,
                              void* d_out, int out_size)
{
    const float* x     = (const float*)d_in[0];
    const float* W_in  = (const float*)d_in[1];
    const float* b_in  = (const float*)d_in[2];
    const float* W_qkv = (const float*)d_in[3];
    const float* b_qkv = (const float*)d_in[4];
    const float* W_o   = (const float*)d_in[5];
    const float* b_o   = (const float*)d_in[6];
    const float* g1    = (const float*)d_in[7];
    const float* be1   = (const float*)d_in[8];
    const float* W_out = (const float*)d_in[9];
    const float* b_out = (const float*)d_in[10];
    const float* g2    = (const float*)d_in[11];
    const float* be2   = (const float*)d_in[12];
    float* out = (float*)d_out;

    float *h, *tmp, *pool, *fin;
    cudaGetSymbolAddress((void**)&h,    g_h);
    cudaGetSymbolAddress((void**)&tmp,  g_tmp);
    cudaGetSymbolAddress((void**)&pool, g_pool);
    cudaGetSymbolAddress((void**)&fin,  g_fin);

    __nv_bfloat16 *ah, *al, *hh, *hl, *qh, *ql, *ch, *cl, *wh, *wl;
    cudaGetSymbolAddress((void**)&ah, g_ah);
    cudaGetSymbolAddress((void**)&al, g_al);
    cudaGetSymbolAddress((void**)&hh, g_hh);
    cudaGetSymbolAddress((void**)&hl, g_hl);
    cudaGetSymbolAddress((void**)&qh, g_qh);
    cudaGetSymbolAddress((void**)&ql, g_ql);
    cudaGetSymbolAddress((void**)&ch, g_ch);
    cudaGetSymbolAddress((void**)&cl, g_cl);
    cudaGetSymbolAddress((void**)&wh, g_wh);
    cudaGetSymbolAddress((void**)&wl, g_wl);

    cudaFuncSetAttribute(mma_gemm_kernel, cudaFuncAttributeMaxDynamicSharedMemorySize, MM_SMEM);
    cudaFuncSetAttribute(attn_mma_kernel, cudaFuncAttributeMaxDynamicSharedMemorySize, AT_SMEM);

    // 0. batched weight transpose+split
    transpose_split_all<<<T_TOTAL, 256>>>(W_in, W_qkv, W_o, wh, wl);

    // 1. split x; in-proj -> h fp32 + split
    {
        const int n4 = MROWS * DIN / 4;
        split_act_kernel<<<(n4 + 255) / 256, 256>>>(x, ah, al, n4);
        mma_gemm_kernel<<<dim3(HH / MBN, MROWS / MBM), 256, MM_SMEM>>>(
            ah, al, wh + OFF_WIN, wl + OFF_WIN, b_in, nullptr,
            h, hh, hl, MROWS, HH, DIN, 0, 3);
    }

    // 2. layers
    for (int l = 0; l < NLAYER; l++) {
        const __nv_bfloat16* WqH = wh + OFF_WQKV + (size_t)l * 3 * HH * HH;
        const __nv_bfloat16* WqL = wl + OFF_WQKV + (size_t)l * 3 * HH * HH;
        const __nv_bfloat16* WoH = wh + OFF_WO + (size_t)l * HH * HH;
        const __nv_bfloat16* WoL = wl + OFF_WO + (size_t)l * HH * HH;
        const float* bq = b_qkv + (size_t)l * 3 * HH;
        const float* bo = b_o + (size_t)l * HH;
        const float* gg = g1 + (size_t)l * HH;
        const float* bb = be1 + (size_t)l * HH;

        mma_gemm_kernel<<<dim3(3 * HH / MBN, MROWS / MBM), 256, MM_SMEM>>>(
            hh, hl, WqH, WqL, bq, nullptr,
            nullptr, qh, ql, MROWS, 3 * HH, HH, 0, 2);

        attn_mma_kernel<<<dim3(SS / 128, NHEAD, BB), 256, AT_SMEM>>>(qh, ql, ch, cl);

        mma_gemm_kernel<<<dim3(HH / MBN, MROWS / MBM), 256, MM_SMEM>>>(
            ch, cl, WoH, WoL, bo, h,
            tmp, nullptr, nullptr, MROWS, HH, HH, 1, 1);

        ln_kernel<<<MROWS / 8, 256>>>(tmp, gg, bb, h, hh, hl, 1);
    }

    // 3. mean pool, final projection + LN
    pool_kernel<<<dim3(HH / 256, BB), 256>>>(h, pool);
    final_gemm_kernel<<<dim3(HH / 256, BB), 256>>>(pool, W_out, b_out, fin);
    ln_kernel<<<1, 256>>>(fin, g2, be2, out, nullptr, nullptr, 0);
}

// round 12
// speedup vs baseline: 1.1676x; 1.0951x over previous
#include <cuda_runtime.h>
#include <cuda_bf16.h>
#include <math.h>
#include <stdint.h>

// Problem constants
#define BB 8
#define SS 1024
#define DIN 512
#define HH 1024
#define NHEAD 16
#define HD 64
#define NLAYER 4
#define MROWS (BB * SS)   // 8192

// ---------------------------------------------------------------------------
// Scratch (device globals; no allocation allowed)
// ---------------------------------------------------------------------------
__device__ float g_h[MROWS * HH];
__device__ float g_tmp[MROWS * HH];
__device__ float g_pool[BB * HH];
__device__ float g_fin[BB * HH];

__device__ __nv_bfloat16 g_ah[MROWS * HH];
__device__ __nv_bfloat16 g_al[MROWS * HH];
__device__ __nv_bfloat16 g_hh[MROWS * HH];
__device__ __nv_bfloat16 g_hl[MROWS * HH];
__device__ __nv_bfloat16 g_qh[MROWS * 3 * HH];
__device__ __nv_bfloat16 g_ql[MROWS * 3 * HH];
__device__ __nv_bfloat16 g_ch[MROWS * HH];
__device__ __nv_bfloat16 g_cl[MROWS * HH];

#define W_TOTAL (DIN * HH + NLAYER * HH * 3 * HH + NLAYER * HH * HH)
__device__ __nv_bfloat16 g_wh[W_TOTAL];
__device__ __nv_bfloat16 g_wl[W_TOTAL];

#define OFF_WIN  0
#define OFF_WQKV ((size_t)DIN * HH)
#define OFF_WO   (OFF_WQKV + (size_t)NLAYER * HH * 3 * HH)

// ---------------------------------------------------------------------------
// PTX wrappers (sm_80-portable)
// ---------------------------------------------------------------------------
__device__ __forceinline__ uint32_t smem_u32(const void* p) {
    uint32_t a;
    asm("{ .reg .u64 t; cvta.to.shared.u64 t, %1; cvt.u32.u64 %0, t; }"
        : "=r"(a) : "l"(p));
    return a;
}
__device__ __forceinline__ void cp_async16(uint32_t dst, const void* src) {
    asm volatile("cp.async.cg.shared.global [%0], [%1], 16;" :: "r"(dst), "l"(src));
}
__device__ __forceinline__ void cp_commit() {
    asm volatile("cp.async.commit_group;");
}
template <int N>
__device__ __forceinline__ void cp_wait() {
    asm volatile("cp.async.wait_group %0;" :: "n"(N));
}
__device__ __forceinline__ void ldsm_x4(uint32_t addr, uint32_t r[4]) {
    asm volatile("ldmatrix.sync.aligned.m8n8.x4.shared.b16 {%0,%1,%2,%3}, [%4];"
                 : "=r"(r[0]), "=r"(r[1]), "=r"(r[2]), "=r"(r[3]) : "r"(addr));
}
__device__ __forceinline__ void ldsm_x4_t(uint32_t addr, uint32_t r[4]) {
    asm volatile("ldmatrix.sync.aligned.m8n8.x4.trans.shared.b16 {%0,%1,%2,%3}, [%4];"
                 : "=r"(r[0]), "=r"(r[1]), "=r"(r[2]), "=r"(r[3]) : "r"(addr));
}
__device__ __forceinline__ void mma_bf16(
    float c[4], const uint32_t a[4], const uint32_t b0, const uint32_t b1)
{
    asm volatile(
        "mma.sync.aligned.m16n8k16.row.col.f32.bf16.bf16.f32 "
        "{%0,%1,%2,%3}, {%4,%5,%6,%7}, {%8,%9}, {%0,%1,%2,%3};"
        : "+f"(c[0]), "+f"(c[1]), "+f"(c[2]), "+f"(c[3])
        : "r"(a[0]), "r"(a[1]), "r"(a[2]), "r"(a[3]), "r"(b0), "r"(b1));
}
__device__ __forceinline__ float ex2f(float x) {
    float r;
    asm("ex2.approx.f32 %0, %1;" : "=f"(r) : "f"(x));
    return r;
}
__device__ __forceinline__ void split2(float a, float b, uint32_t& hi, uint32_t& lo) {
    __nv_bfloat16 ha = __float2bfloat16(a), hb = __float2bfloat16(b);
    __nv_bfloat162 h2; h2.x = ha; h2.y = hb;
    hi = *(uint32_t*)&h2;
    __nv_bfloat162 l2;
    l2.x = __float2bfloat16(a - __bfloat162float(ha));
    l2.y = __float2bfloat16(b - __bfloat162float(hb));
    lo = *(uint32_t*)&l2;
}

// ---------------------------------------------------------------------------
// Batched weight transpose + split (single launch, all 9 matrices)
// ---------------------------------------------------------------------------
#define T_WIN   512
#define T_WQKV  3072
#define T_WO    1024
#define T_TOTAL (T_WIN + NLAYER * T_WQKV + NLAYER * T_WO)

__global__ void __launch_bounds__(256) transpose_split_all(
    const float* __restrict__ W_in, const float* __restrict__ W_qkv,
    const float* __restrict__ W_o,
    __nv_bfloat16* __restrict__ wh, __nv_bfloat16* __restrict__ wl)
{
    __shared__ float tile[32][33];
    int idx = blockIdx.x;
    const float* W;
    int K, N, t;
    size_t woff;
    if (idx < T_WIN) {
        W = W_in; K = DIN; N = HH; woff = OFF_WIN; t = idx;
    } else if (idx < T_WIN + NLAYER * T_WQKV) {
        const int l = (idx - T_WIN) / T_WQKV;
        t = (idx - T_WIN) % T_WQKV;
        W = W_qkv + (size_t)l * HH * 3 * HH;
        K = HH; N = 3 * HH;
        woff = OFF_WQKV + (size_t)l * 3 * HH * HH;
    } else {
        const int l = (idx - T_WIN - NLAYER * T_WQKV) / T_WO;
        t = (idx - T_WIN - NLAYER * T_WQKV) % T_WO;
        W = W_o + (size_t)l * HH * HH;
        K = HH; N = HH;
        woff = OFF_WO + (size_t)l * HH * HH;
    }
    const int tpr = N / 32;
    const int n0 = (t % tpr) * 32;
    const int k0 = (t / tpr) * 32;
    const int tx = threadIdx.x & 31;
    const int ty = threadIdx.x >> 5;

#pragma unroll
    for (int r = 0; r < 32; r += 8)
        tile[ty + r][tx] = W[(size_t)(k0 + ty + r) * N + n0 + tx];
    __syncthreads();
#pragma unroll
    for (int r = 0; r < 32; r += 8) {
        const float v = tile[tx][ty + r];
        const __nv_bfloat16 h = __float2bfloat16(v);
        const float lo = v - __bfloat162float(h);
        const size_t o = woff + (size_t)(n0 + ty + r) * K + k0 + tx;
        wh[o] = h;
        wl[o] = __float2bfloat16(lo);
    }
}

// ---------------------------------------------------------------------------
// Activation split (x only)
// ---------------------------------------------------------------------------
__global__ void split_act_kernel(
    const float* __restrict__ in,
    __nv_bfloat16* __restrict__ hi, __nv_bfloat16* __restrict__ lo, int n4)
{
    const int i = blockIdx.x * 256 + threadIdx.x;
    if (i >= n4) return;
    const float4 v = ((const float4*)in)[i];
    uint32_t h0, l0, h1, l1;
    split2(v.x, v.y, h0, l0);
    split2(v.z, v.w, h1, l1);
    ((uint32_t*)hi)[i * 2]     = h0;
    ((uint32_t*)hi)[i * 2 + 1] = h1;
    ((uint32_t*)lo)[i * 2]     = l0;
    ((uint32_t*)lo)[i * 2 + 1] = l1;
}

// ---------------------------------------------------------------------------
// Split-bf16 HMMA GEMM — EXACT R9 config (best measured): 64x32 warp tiles,
// 8 warps, 2-stage/2-barrier. __launch_bounds__(256,2) pins 128 regs /
// 2 CTAs per SM (the measured optimum; R10/R11 showed any reg increase
// collapses residency).
// ---------------------------------------------------------------------------
#define MBM 128
#define MBN 128
#define MBK 32
#define MSTR 40
#define MTILE (128 * MSTR * 2)
#define MSTAGE (4 * MTILE)
#define MM_SMEM (2 * MSTAGE)

__global__ void __launch_bounds__(256, 2)
mma_gemm_kernel(
    const __nv_bfloat16* __restrict__ Ah, const __nv_bfloat16* __restrict__ Al,
    const __nv_bfloat16* __restrict__ Bh, const __nv_bfloat16* __restrict__ Bl,
    const float* __restrict__ bias, const float* __restrict__ res,
    float* __restrict__ Cf,
    __nv_bfloat16* __restrict__ Ch, __nv_bfloat16* __restrict__ Cl,
    int M, int N, int K, int hasRes, int mode)
{
    extern __shared__ __align__(16) char smem[];
    const uint32_t sbase = smem_u32(smem);

    const int t    = threadIdx.x;
    const int wid  = t >> 5;
    const int lane = t & 31;
    const int m0 = blockIdx.y * MBM;
    const int n0 = blockIdx.x * MBN;

    const int warp_m = (wid >> 2) * 64;
    const int warp_n = (wid & 3) * 32;

    const int crow  = t >> 1;
    const int cq    = (t & 1) * 2;

    const __nv_bfloat16* gsrc[4];
    gsrc[0] = Ah + (size_t)(m0 + crow) * K;
    gsrc[1] = Al + (size_t)(m0 + crow) * K;
    gsrc[2] = Bh + (size_t)(n0 + crow) * K;
    gsrc[3] = Bl + (size_t)(n0 + crow) * K;
    const uint32_t sdst_row = crow * (MSTR * 2);

    const int nc = K / MBK;

    {
#pragma unroll
        for (int tl = 0; tl < 4; tl++) {
            const uint32_t d = sbase + tl * MTILE + sdst_row;
            cp_async16(d + (cq + 0) * 16, gsrc[tl] + (cq + 0) * 8);
            cp_async16(d + (cq + 1) * 16, gsrc[tl] + (cq + 1) * 8);
        }
        cp_commit();
    }

    float acc[4][4][4];
#pragma unroll
    for (int mi = 0; mi < 4; mi++)
#pragma unroll
        for (int ni = 0; ni < 4; ni++)
#pragma unroll
            for (int r = 0; r < 4; r++) acc[mi][ni][r] = 0.0f;

    const int lrow = lane & 15;
    const int lcolq = (lane >> 4) << 3;

    for (int c = 0; c < nc; c++) {
        const int st = c & 1;
        if (c + 1 < nc) {
            const int k0 = (c + 1) * MBK;
            const uint32_t so = ((c + 1) & 1) * MSTAGE;
#pragma unroll
            for (int tl = 0; tl < 4; tl++) {
                const uint32_t d = sbase + so + tl * MTILE + sdst_row;
                cp_async16(d + (cq + 0) * 16, gsrc[tl] + k0 + (cq + 0) * 8);
                cp_async16(d + (cq + 1) * 16, gsrc[tl] + k0 + (cq + 1) * 8);
            }
            cp_commit();
            cp_wait<1>();
        } else {
            cp_wait<0>();
        }
        __syncthreads();

        const uint32_t sAh = sbase + st * MSTAGE + 0 * MTILE;
        const uint32_t sAl = sbase + st * MSTAGE + 1 * MTILE;
        const uint32_t sBh = sbase + st * MSTAGE + 2 * MTILE;
        const uint32_t sBl = sbase + st * MSTAGE + 3 * MTILE;

#pragma unroll
        for (int ks = 0; ks < 2; ks++) {
            const int col = ks * 16 + lcolq;
            uint32_t afh[4][4], afl[4][4];
#pragma unroll
            for (int mi = 0; mi < 4; mi++) {
                const uint32_t off =
                    (uint32_t)(warp_m + mi * 16 + lrow) * (MSTR * 2) + col * 2;
                ldsm_x4(sAh + off, afh[mi]);
                ldsm_x4(sAl + off, afl[mi]);
            }
            uint32_t bfh[4][2], bfl[4][2];
#pragma unroll
            for (int n2 = 0; n2 < 2; n2++) {
                const uint32_t off =
                    (uint32_t)(warp_n + n2 * 16 + lrow) * (MSTR * 2) + col * 2;
                uint32_t r4[4];
                ldsm_x4(sBh + off, r4);
                bfh[n2 * 2 + 0][0] = r4[0]; bfh[n2 * 2 + 1][0] = r4[1];
                bfh[n2 * 2 + 0][1] = r4[2]; bfh[n2 * 2 + 1][1] = r4[3];
                ldsm_x4(sBl + off, r4);
                bfl[n2 * 2 + 0][0] = r4[0]; bfl[n2 * 2 + 1][0] = r4[1];
                bfl[n2 * 2 + 0][1] = r4[2]; bfl[n2 * 2 + 1][1] = r4[3];
            }
#pragma unroll
            for (int mi = 0; mi < 4; mi++)
#pragma unroll
                for (int ni = 0; ni < 4; ni++) {
                    mma_bf16(acc[mi][ni], afh[mi], bfh[ni][0], bfh[ni][1]);
                    mma_bf16(acc[mi][ni], afh[mi], bfl[ni][0], bfl[ni][1]);
                    mma_bf16(acc[mi][ni], afl[mi], bfh[ni][0], bfh[ni][1]);
                }
        }
        __syncthreads();   // WAR guard on the recycled stage
    }

    const int g  = lane >> 2;
    const int tg = lane & 3;
#pragma unroll
    for (int mi = 0; mi < 4; mi++) {
#pragma unroll
        for (int ni = 0; ni < 4; ni++) {
            const int colg = n0 + warp_n + ni * 8 + tg * 2;
            const float bx = bias[colg], by = bias[colg + 1];
            const int r0 = m0 + warp_m + mi * 16 + g;
            const int r1 = r0 + 8;
            float2 o0, o1;
            o0.x = acc[mi][ni][0] + bx; o0.y = acc[mi][ni][1] + by;
            o1.x = acc[mi][ni][2] + bx; o1.y = acc[mi][ni][3] + by;
            if (hasRes) {
                const float2 v0 = *(const float2*)(res + (size_t)r0 * N + colg);
                const float2 v1 = *(const float2*)(res + (size_t)r1 * N + colg);
                o0.x += v0.x; o0.y += v0.y;
                o1.x += v1.x; o1.y += v1.y;
            }
            if (mode & 1) {
                *(float2*)(Cf + (size_t)r0 * N + colg) = o0;
                *(float2*)(Cf + (size_t)r1 * N + colg) = o1;
            }
            if (mode & 2) {
                uint32_t hi, lo;
                split2(o0.x, o0.y, hi, lo);
                *(uint32_t*)(Ch + (size_t)r0 * N + colg) = hi;
                *(uint32_t*)(Cl + (size_t)r0 * N + colg) = lo;
                split2(o1.x, o1.y, hi, lo);
                *(uint32_t*)(Ch + (size_t)r1 * N + colg) = hi;
                *(uint32_t*)(Cl + (size_t)r1 * N + colg) = lo;
            }
        }
    }
}

// ---------------------------------------------------------------------------
// Tensor-core flash attention, split-bf16 operands.
// 128-row Q tiles, 256 threads, base-2 softmax (ex2.approx).
// ---------------------------------------------------------------------------
#define APAD 144
#define ATILE (64 * APAD)
#define AQTILE (128 * APAD)
#define AQ_H 0
#define AQ_L AQTILE
#define AST0 (2 * AQTILE)
#define ASTG (4 * ATILE)
#define AT_SMEM (2 * AQTILE + 2 * ASTG)      // 110592

__global__ void __launch_bounds__(256)
attn_mma_kernel(
    const __nv_bfloat16* __restrict__ qh, const __nv_bfloat16* __restrict__ ql,
    __nv_bfloat16* __restrict__ cth, __nv_bfloat16* __restrict__ ctl)
{
    extern __shared__ __align__(16) char smem[];
    const uint32_t sbase = smem_u32(smem);

    const int b  = blockIdx.z;
    const int nh = blockIdx.y;
    const int qt = blockIdx.x;
    const int t  = threadIdx.x;
    const int wid  = t >> 5;
    const int lane = t & 31;
    const int g  = lane >> 2;
    const int tg = lane & 3;
    const int lrow  = lane & 15;
    const int lcolq = (lane >> 4) << 3;

    const size_t bS = (size_t)b * SS;
    const int hoff = nh * HD;

    {
        const int crw = t >> 1;
        const int cqq = (t & 1) * 4;
        const size_t grow = (bS + qt * 128 + crw) * (3 * HH) + hoff;
        const uint32_t d = sbase + crw * APAD + cqq * 16;
#pragma unroll
        for (int i = 0; i < 4; i++) {
            cp_async16(d + AQ_H + i * 16, qh + grow + (cqq + i) * 8);
            cp_async16(d + AQ_L + i * 16, ql + grow + (cqq + i) * 8);
        }
    }

    const int tt   = t & 127;
    const int kv   = t >> 7;
    const int crow = tt >> 1;
    const int cq0  = (tt & 1) * 4;
    const int srcoff = (kv + 1) * HH;
    const uint32_t tile_h = (kv * 2 + 0) * ATILE;
    const uint32_t tile_l = (kv * 2 + 1) * ATILE;

#pragma unroll
    for (int p = 0; p < 2; p++) {
        const size_t grow = (bS + p * 64 + crow) * (3 * HH) + hoff + srcoff;
        const uint32_t d = sbase + AST0 + p * ASTG + crow * APAD + cq0 * 16;
#pragma unroll
        for (int i = 0; i < 4; i++) {
            cp_async16(d + tile_h + i * 16, qh + grow + (cq0 + i) * 8);
            cp_async16(d + tile_l + i * 16, ql + grow + (cq0 + i) * 8);
        }
        cp_commit();
    }

    float acc_o[8][4];
#pragma unroll
    for (int nb = 0; nb < 8; nb++)
#pragma unroll
        for (int r = 0; r < 4; r++) acc_o[nb][r] = 0.0f;

    uint32_t aqh[4][4], aql[4][4];
    float m0 = -INFINITY, m1 = -INFINITY;
    float l0 = 0.0f, l1 = 0.0f;
    const float SC2 = 0.125f * 1.4426950408889634f;   // SCALE * log2(e)

    for (int kt = 0; kt < SS / 64; kt++) {
        if (kt == SS / 64 - 1) { cp_wait<0>(); } else { cp_wait<1>(); }
        __syncthreads();

        if (kt == 0) {
#pragma unroll
            for (int kb = 0; kb < 4; kb++) {
                const uint32_t off =
                    (uint32_t)(wid * 16 + lrow) * APAD + (kb * 16 + lcolq) * 2;
                ldsm_x4(sbase + AQ_H + off, aqh[kb]);
                ldsm_x4(sbase + AQ_L + off, aql[kb]);
            }
        }

        const uint32_t sK_h = sbase + AST0 + (kt & 1) * ASTG + 0 * ATILE;
        const uint32_t sK_l = sbase + AST0 + (kt & 1) * ASTG + 1 * ATILE;
        const uint32_t sV_h = sbase + AST0 + (kt & 1) * ASTG + 2 * ATILE;
        const uint32_t sV_l = sbase + AST0 + (kt & 1) * ASTG + 3 * ATILE;

        float s[8][4];
#pragma unroll
        for (int nb = 0; nb < 8; nb++)
#pragma unroll
            for (int r = 0; r < 4; r++) s[nb][r] = 0.0f;

#pragma unroll
        for (int n2 = 0; n2 < 4; n2++) {
#pragma unroll
            for (int kb = 0; kb < 4; kb++) {
                const uint32_t off =
                    (uint32_t)(n2 * 16 + lrow) * APAD + (kb * 16 + lcolq) * 2;
                uint32_t kh4[4], kl4[4];
                ldsm_x4(sK_h + off, kh4);
                ldsm_x4(sK_l + off, kl4);
                mma_bf16(s[n2 * 2 + 0], aqh[kb], kh4[0], kh4[2]);
                mma_bf16(s[n2 * 2 + 1], aqh[kb], kh4[1], kh4[3]);
                mma_bf16(s[n2 * 2 + 0], aqh[kb], kl4[0], kl4[2]);
                mma_bf16(s[n2 * 2 + 1], aqh[kb], kl4[1], kl4[3]);
                mma_bf16(s[n2 * 2 + 0], aql[kb], kh4[0], kh4[2]);
                mma_bf16(s[n2 * 2 + 1], aql[kb], kh4[1], kh4[3]);
            }
        }

        // base-2 online softmax
        float mx0 = -INFINITY, mx1 = -INFINITY;
#pragma unroll
        for (int nb = 0; nb < 8; nb++) {
            s[nb][0] *= SC2; s[nb][1] *= SC2; s[nb][2] *= SC2; s[nb][3] *= SC2;
            mx0 = fmaxf(mx0, fmaxf(s[nb][0], s[nb][1]));
            mx1 = fmaxf(mx1, fmaxf(s[nb][2], s[nb][3]));
        }
        mx0 = fmaxf(mx0, __shfl_xor_sync(0xffffffffu, mx0, 1));
        mx0 = fmaxf(mx0, __shfl_xor_sync(0xffffffffu, mx0, 2));
        mx1 = fmaxf(mx1, __shfl_xor_sync(0xffffffffu, mx1, 1));
        mx1 = fmaxf(mx1, __shfl_xor_sync(0xffffffffu, mx1, 2));
        const float mn0 = fmaxf(m0, mx0);
        const float mn1 = fmaxf(m1, mx1);
        const float f0 = ex2f(m0 - mn0);
        const float f1 = ex2f(m1 - mn1);
        m0 = mn0; m1 = mn1;
        l0 *= f0; l1 *= f1;
#pragma unroll
        for (int nb = 0; nb < 8; nb++) {
            s[nb][0] = ex2f(s[nb][0] - mn0);
            s[nb][1] = ex2f(s[nb][1] - mn0);
            s[nb][2] = ex2f(s[nb][2] - mn1);
            s[nb][3] = ex2f(s[nb][3] - mn1);
            l0 += s[nb][0] + s[nb][1];
            l1 += s[nb][2] + s[nb][3];
            acc_o[nb][0] *= f0; acc_o[nb][1] *= f0;
            acc_o[nb][2] *= f1; acc_o[nb][3] *= f1;
        }

        uint32_t ph[4][4], pl[4][4];
#pragma unroll
        for (int kb = 0; kb < 4; kb++) {
            split2(s[2 * kb][0],     s[2 * kb][1],     ph[kb][0], pl[kb][0]);
            split2(s[2 * kb][2],     s[2 * kb][3],     ph[kb][1], pl[kb][1]);
            split2(s[2 * kb + 1][0], s[2 * kb + 1][1], ph[kb][2], pl[kb][2]);
            split2(s[2 * kb + 1][2], s[2 * kb + 1][3], ph[kb][3], pl[kb][3]);
        }

#pragma unroll
        for (int kb = 0; kb < 4; kb++) {
#pragma unroll
            for (int n2 = 0; n2 < 4; n2++) {
                const uint32_t off =
                    (uint32_t)(kb * 16 + lrow) * APAD + (n2 * 16 + lcolq) * 2;
                uint32_t vh4[4], vl4[4];
                ldsm_x4_t(sV_h + off, vh4);
                ldsm_x4_t(sV_l + off, vl4);
                mma_bf16(acc_o[n2 * 2 + 0], ph[kb], vh4[0], vh4[1]);
                mma_bf16(acc_o[n2 * 2 + 1], ph[kb], vh4[2], vh4[3]);
                mma_bf16(acc_o[n2 * 2 + 0], ph[kb], vl4[0], vl4[1]);
                mma_bf16(acc_o[n2 * 2 + 1], ph[kb], vl4[2], vl4[3]);
                mma_bf16(acc_o[n2 * 2 + 0], pl[kb], vh4[0], vh4[1]);
                mma_bf16(acc_o[n2 * 2 + 1], pl[kb], vh4[2], vh4[3]);
            }
        }

        __syncthreads();   // WAR guard: prefetch below writes the stage read above
        if (kt + 2 < SS / 64) {
            const size_t grow = (bS + (kt + 2) * 64 + crow) * (3 * HH) + hoff + srcoff;
            const uint32_t d = sbase + AST0 + (kt & 1) * ASTG + crow * APAD + cq0 * 16;
#pragma unroll
            for (int i = 0; i < 4; i++) {
                cp_async16(d + tile_h + i * 16, qh + grow + (cq0 + i) * 8);
                cp_async16(d + tile_l + i * 16, ql + grow + (cq0 + i) * 8);
            }
        }
        cp_commit();
    }

    l0 += __shfl_xor_sync(0xffffffffu, l0, 1);
    l0 += __shfl_xor_sync(0xffffffffu, l0, 2);
    l1 += __shfl_xor_sync(0xffffffffu, l1, 1);
    l1 += __shfl_xor_sync(0xffffffffu, l1, 2);
    const float inv0 = 1.0f / l0;
    const float inv1 = 1.0f / l1;

    const size_t r0 = bS + qt * 128 + wid * 16 + g;
    const size_t r1 = r0 + 8;
#pragma unroll
    for (int nb = 0; nb < 8; nb++) {
        const int col = hoff + nb * 8 + tg * 2;
        uint32_t hi, lo;
        split2(acc_o[nb][0] * inv0, acc_o[nb][1] * inv0, hi, lo);
        *(uint32_t*)(cth + r0 * HH + col) = hi;
        *(uint32_t*)(ctl + r0 * HH + col) = lo;
        split2(acc_o[nb][2] * inv1, acc_o[nb][3] * inv1, hi, lo);
        *(uint32_t*)(cth + r1 * HH + col) = hi;
        *(uint32_t*)(ctl + r1 * HH + col) = lo;
    }
}

// ---------------------------------------------------------------------------
// One-pass warp-per-row LayerNorm
// ---------------------------------------------------------------------------
__global__ void __launch_bounds__(256) ln_kernel(
    const float* __restrict__ in, const float* __restrict__ gamma,
    const float* __restrict__ beta, float* __restrict__ out,
    __nv_bfloat16* __restrict__ outh, __nv_bfloat16* __restrict__ outl,
    int doSplit)
{
    const int warp = threadIdx.x >> 5;
    const int lane = threadIdx.x & 31;
    const int row  = blockIdx.x * 8 + warp;
    const float* x = in + (size_t)row * HH;

    float v[32];
    float s = 0.0f;
#pragma unroll
    for (int k = 0; k < 8; k++) {
        const float4 t4 = *(const float4*)&x[(k * 32 + lane) * 4];
        v[k * 4 + 0] = t4.x; v[k * 4 + 1] = t4.y;
        v[k * 4 + 2] = t4.z; v[k * 4 + 3] = t4.w;
        s += (t4.x + t4.y) + (t4.z + t4.w);
    }
#pragma unroll
    for (int o = 16; o > 0; o >>= 1) s += __shfl_xor_sync(0xffffffffu, s, o);
    const float mean = s * (1.0f / HH);

    float var = 0.0f;
#pragma unroll
    for (int i = 0; i < 32; i++) {
        const float d = v[i] - mean;
        var += d * d;
    }
#pragma unroll
    for (int o = 16; o > 0; o >>= 1) var += __shfl_xor_sync(0xffffffffu, var, o);
    const float rstd = rsqrtf(var * (1.0f / HH) + 1e-5f);

#pragma unroll
    for (int k = 0; k < 8; k++) {
        const int i0 = (k * 32 + lane) * 4;
        const float4 gv = *(const float4*)&gamma[i0];
        const float4 bv = *(const float4*)&beta[i0];
        float4 o;
        o.x = (v[k * 4 + 0] - mean) * rstd * gv.x + bv.x;
        o.y = (v[k * 4 + 1] - mean) * rstd * gv.y + bv.y;
        o.z = (v[k * 4 + 2] - mean) * rstd * gv.z + bv.z;
        o.w = (v[k * 4 + 3] - mean) * rstd * gv.w + bv.w;
        *(float4*)&out[(size_t)row * HH + i0] = o;
        if (doSplit) {
            uint32_t h0, lo0, h1, lo1;
            split2(o.x, o.y, h0, lo0);
            split2(o.z, o.w, h1, lo1);
            uint2 hv; hv.x = h0; hv.y = h1;
            uint2 lv; lv.x = lo0; lv.y = lo1;
            *(uint2*)(outh + (size_t)row * HH + i0) = hv;
            *(uint2*)(outl + (size_t)row * HH + i0) = lv;
        }
    }
}

__global__ void __launch_bounds__(256) pool_kernel(
    const float* __restrict__ h, float* __restrict__ pooled)
{
    const int j = blockIdx.x * 256 + threadIdx.x;
    const int b = blockIdx.y;
    float s = 0.0f;
#pragma unroll 8
    for (int ss = 0; ss < SS; ss++)
        s += h[((size_t)b * SS + ss) * HH + j];
    pooled[b * HH + j] = s * (1.0f / SS);
}

__global__ void __launch_bounds__(256) final_gemm_kernel(
    const float* __restrict__ pooled, const float* __restrict__ W,
    const float* __restrict__ bias, float* __restrict__ out)
{
    __shared__ float pr[HH];
    const int b   = blockIdx.y;
    const int col = blockIdx.x * 256 + threadIdx.x;
    for (int i = threadIdx.x; i < HH; i += 256) pr[i] = pooled[b * HH + i];
    __syncthreads();
    float s = bias[col];
#pragma unroll 8
    for (int k = 0; k < HH; k++)
        s += pr[k] * W[(size_t)k * HH + col];
    out[b * HH + col] = s;
}

// ---------------------------------------------------------------------------
// Launch
// ---------------------------------------------------------------------------
extern "C" void kernel_launch(void* const* d_in, const int* in_sizes, int n_in,
                              void* d_out, int out_size)
{
    const float* x     = (const float*)d_in[0];
    const float* W_in  = (const float*)d_in[1];
    const float* b_in  = (const float*)d_in[2];
    const float* W_qkv = (const float*)d_in[3];
    const float* b_qkv = (const float*)d_in[4];
    const float* W_o   = (const float*)d_in[5];
    const float* b_o   = (const float*)d_in[6];
    const float* g1    = (const float*)d_in[7];
    const float* be1   = (const float*)d_in[8];
    const float* W_out = (const float*)d_in[9];
    const float* b_out = (const float*)d_in[10];
    const float* g2    = (const float*)d_in[11];
    const float* be2   = (const float*)d_in[12];
    float* out = (float*)d_out;

    float *h, *tmp, *pool, *fin;
    cudaGetSymbolAddress((void**)&h,    g_h);
    cudaGetSymbolAddress((void**)&tmp,  g_tmp);
    cudaGetSymbolAddress((void**)&pool, g_pool);
    cudaGetSymbolAddress((void**)&fin,  g_fin);

    __nv_bfloat16 *ah, *al, *hh, *hl, *qh, *ql, *ch, *cl, *wh, *wl;
    cudaGetSymbolAddress((void**)&ah, g_ah);
    cudaGetSymbolAddress((void**)&al, g_al);
    cudaGetSymbolAddress((void**)&hh, g_hh);
    cudaGetSymbolAddress((void**)&hl, g_hl);
    cudaGetSymbolAddress((void**)&qh, g_qh);
    cudaGetSymbolAddress((void**)&ql, g_ql);
    cudaGetSymbolAddress((void**)&ch, g_ch);
    cudaGetSymbolAddress((void**)&cl, g_cl);
    cudaGetSymbolAddress((void**)&wh, g_wh);
    cudaGetSymbolAddress((void**)&wl, g_wl);

    cudaFuncSetAttribute(mma_gemm_kernel, cudaFuncAttributeMaxDynamicSharedMemorySize, MM_SMEM);
    cudaFuncSetAttribute(attn_mma_kernel, cudaFuncAttributeMaxDynamicSharedMemorySize, AT_SMEM);

    // 0. batched weight transpose+split
    transpose_split_all<<<T_TOTAL, 256>>>(W_in, W_qkv, W_o, wh, wl);

    // 1. split x; in-proj -> h fp32 + split
    {
        const int n4 = MROWS * DIN / 4;
        split_act_kernel<<<(n4 + 255) / 256, 256>>>(x, ah, al, n4);
        mma_gemm_kernel<<<dim3(HH / MBN, MROWS / MBM), 256, MM_SMEM>>>(
            ah, al, wh + OFF_WIN, wl + OFF_WIN, b_in, nullptr,
            h, hh, hl, MROWS, HH, DIN, 0, 3);
    }

    // 2. layers
    for (int l = 0; l < NLAYER; l++) {
        const __nv_bfloat16* WqH = wh + OFF_WQKV + (size_t)l * 3 * HH * HH;
        const __nv_bfloat16* WqL = wl + OFF_WQKV + (size_t)l * 3 * HH * HH;
        const __nv_bfloat16* WoH = wh + OFF_WO + (size_t)l * HH * HH;
        const __nv_bfloat16* WoL = wl + OFF_WO + (size_t)l * HH * HH;
        const float* bq = b_qkv + (size_t)l * 3 * HH;
        const float* bo = b_o + (size_t)l * HH;
        const float* gg = g1 + (size_t)l * HH;
        const float* bb = be1 + (size_t)l * HH;

        mma_gemm_kernel<<<dim3(3 * HH / MBN, MROWS / MBM), 256, MM_SMEM>>>(
            hh, hl, WqH, WqL, bq, nullptr,
            nullptr, qh, ql, MROWS, 3 * HH, HH, 0, 2);

        attn_mma_kernel<<<dim3(SS / 128, NHEAD, BB), 256, AT_SMEM>>>(qh, ql, ch, cl);

        mma_gemm_kernel<<<dim3(HH / MBN, MROWS / MBM), 256, MM_SMEM>>>(
            ch, cl, WoH, WoL, bo, h,
            tmp, nullptr, nullptr, MROWS, HH, HH, 1, 1);

        ln_kernel<<<MROWS / 8, 256>>>(tmp, gg, bb, h, hh, hl, 1);
    }

    // 3. mean pool, final projection + LN
    pool_kernel<<<dim3(HH / 256, BB), 256>>>(h, pool);
    final_gemm_kernel<<<dim3(HH / 256, BB), 256>>>(pool, W_out, b_out, fin);
    ln_kernel<<<1, 256>>>(fin, g2, be2, out, nullptr, nullptr, 0);
}

// round 13
// speedup vs baseline: 1.4561x; 1.2471x over previous
#include <cuda_runtime.h>
#include <cuda_bf16.h>
#include <cuda_fp16.h>
#include <math.h>
#include <stdint.h>

// Problem constants
#define BB 8
#define SS 1024
#define DIN 512
#define HH 1024
#define NHEAD 16
#define HD 64
#define NLAYER 4
#define MROWS (BB * SS)   // 8192

// ---------------------------------------------------------------------------
// Scratch (device globals; no allocation allowed)
// ---------------------------------------------------------------------------
__device__ float g_h[MROWS * HH];          // fp32 residual stream
__device__ float g_tmp[MROWS * HH];
__device__ float g_pool[BB * HH];
__device__ float g_fin[BB * HH];

__device__ __half g_x16[MROWS * DIN];      // x as fp16 (GEMM A)
__device__ __half g_h16[MROWS * HH];       // h as fp16 (GEMM A)
__device__ __half g_c16[MROWS * HH];       // ctx as fp16 (GEMM A)
__device__ __nv_bfloat16 g_qh[MROWS * 3 * HH];   // qkv split hi (attention)
__device__ __nv_bfloat16 g_ql[MROWS * 3 * HH];   // qkv split lo (attention)

#define W_TOTAL (DIN * HH + NLAYER * HH * 3 * HH + NLAYER * HH * HH)
__device__ __half g_wh[W_TOTAL];
__device__ __half g_wl[W_TOTAL];

#define OFF_WIN  0
#define OFF_WQKV ((size_t)DIN * HH)
#define OFF_WO   (OFF_WQKV + (size_t)NLAYER * HH * 3 * HH)

// ---------------------------------------------------------------------------
// PTX wrappers (sm_80-portable)
// ---------------------------------------------------------------------------
__device__ __forceinline__ uint32_t smem_u32(const void* p) {
    uint32_t a;
    asm("{ .reg .u64 t; cvta.to.shared.u64 t, %1; cvt.u32.u64 %0, t; }"
        : "=r"(a) : "l"(p));
    return a;
}
__device__ __forceinline__ void cp_async16(uint32_t dst, const void* src) {
    asm volatile("cp.async.cg.shared.global [%0], [%1], 16;" :: "r"(dst), "l"(src));
}
__device__ __forceinline__ void cp_commit() {
    asm volatile("cp.async.commit_group;");
}
template <int N>
__device__ __forceinline__ void cp_wait() {
    asm volatile("cp.async.wait_group %0;" :: "n"(N));
}
__device__ __forceinline__ void ldsm_x4(uint32_t addr, uint32_t r[4]) {
    asm volatile("ldmatrix.sync.aligned.m8n8.x4.shared.b16 {%0,%1,%2,%3}, [%4];"
                 : "=r"(r[0]), "=r"(r[1]), "=r"(r[2]), "=r"(r[3]) : "r"(addr));
}
__device__ __forceinline__ void ldsm_x4_t(uint32_t addr, uint32_t r[4]) {
    asm volatile("ldmatrix.sync.aligned.m8n8.x4.trans.shared.b16 {%0,%1,%2,%3}, [%4];"
                 : "=r"(r[0]), "=r"(r[1]), "=r"(r[2]), "=r"(r[3]) : "r"(addr));
}
// bf16 MMA (attention)
__device__ __forceinline__ void mma_bf16(
    float c[4], const uint32_t a[4], const uint32_t b0, const uint32_t b1)
{
    asm volatile(
        "mma.sync.aligned.m16n8k16.row.col.f32.bf16.bf16.f32 "
        "{%0,%1,%2,%3}, {%4,%5,%6,%7}, {%8,%9}, {%0,%1,%2,%3};"
        : "+f"(c[0]), "+f"(c[1]), "+f"(c[2]), "+f"(c[3])
        : "r"(a[0]), "r"(a[1]), "r"(a[2]), "r"(a[3]), "r"(b0), "r"(b1));
}
// fp16 MMA (linear GEMMs)
__device__ __forceinline__ void mma_fp16(
    float c[4], const uint32_t a[4], const uint32_t b0, const uint32_t b1)
{
    asm volatile(
        "mma.sync.aligned.m16n8k16.row.col.f32.f16.f16.f32 "
        "{%0,%1,%2,%3}, {%4,%5,%6,%7}, {%8,%9}, {%0,%1,%2,%3};"
        : "+f"(c[0]), "+f"(c[1]), "+f"(c[2]), "+f"(c[3])
        : "r"(a[0]), "r"(a[1]), "r"(a[2]), "r"(a[3]), "r"(b0), "r"(b1));
}
__device__ __forceinline__ float ex2f(float x) {
    float r;
    asm("ex2.approx.f32 %0, %1;" : "=f"(r) : "f"(x));
    return r;
}
// bf16 split (attention P/Q/K path)
__device__ __forceinline__ void split2(float a, float b, uint32_t& hi, uint32_t& lo) {
    __nv_bfloat16 ha = __float2bfloat16(a), hb = __float2bfloat16(b);
    __nv_bfloat162 h2; h2.x = ha; h2.y = hb;
    hi = *(uint32_t*)&h2;
    __nv_bfloat162 l2;
    l2.x = __float2bfloat16(a - __bfloat162float(ha));
    l2.y = __float2bfloat16(b - __bfloat162float(hb));
    lo = *(uint32_t*)&l2;
}
__device__ __forceinline__ uint32_t pack_h2(float a, float b) {
    __half2 h = __floats2half2_rn(a, b);
    return *(uint32_t*)&h;
}

// ---------------------------------------------------------------------------
// Batched weight transpose + fp16 hi/lo split (single launch, 9 matrices)
// ---------------------------------------------------------------------------
#define T_WIN   512
#define T_WQKV  3072
#define T_WO    1024
#define T_TOTAL (T_WIN + NLAYER * T_WQKV + NLAYER * T_WO)

__global__ void __launch_bounds__(256) transpose_split_all(
    const float* __restrict__ W_in, const float* __restrict__ W_qkv,
    const float* __restrict__ W_o,
    __half* __restrict__ wh, __half* __restrict__ wl)
{
    __shared__ float tile[32][33];
    int idx = blockIdx.x;
    const float* W;
    int K, N, t;
    size_t woff;
    if (idx < T_WIN) {
        W = W_in; K = DIN; N = HH; woff = OFF_WIN; t = idx;
    } else if (idx < T_WIN + NLAYER * T_WQKV) {
        const int l = (idx - T_WIN) / T_WQKV;
        t = (idx - T_WIN) % T_WQKV;
        W = W_qkv + (size_t)l * HH * 3 * HH;
        K = HH; N = 3 * HH;
        woff = OFF_WQKV + (size_t)l * 3 * HH * HH;
    } else {
        const int l = (idx - T_WIN - NLAYER * T_WQKV) / T_WO;
        t = (idx - T_WIN - NLAYER * T_WQKV) % T_WO;
        W = W_o + (size_t)l * HH * HH;
        K = HH; N = HH;
        woff = OFF_WO + (size_t)l * HH * HH;
    }
    const int tpr = N / 32;
    const int n0 = (t % tpr) * 32;
    const int k0 = (t / tpr) * 32;
    const int tx = threadIdx.x & 31;
    const int ty = threadIdx.x >> 5;

#pragma unroll
    for (int r = 0; r < 32; r += 8)
        tile[ty + r][tx] = W[(size_t)(k0 + ty + r) * N + n0 + tx];
    __syncthreads();
#pragma unroll
    for (int r = 0; r < 32; r += 8) {
        const float v = tile[tx][ty + r];
        const __half h = __float2half_rn(v);
        const float lo = v - __half2float(h);
        const size_t o = woff + (size_t)(n0 + ty + r) * K + k0 + tx;
        wh[o] = h;
        wl[o] = __float2half_rn(lo);
    }
}

// ---------------------------------------------------------------------------
// Activation to fp16 (x only)
// ---------------------------------------------------------------------------
__global__ void split_act_kernel(
    const float* __restrict__ in, __half* __restrict__ o16, int n4)
{
    const int i = blockIdx.x * 256 + threadIdx.x;
    if (i >= n4) return;
    const float4 v = ((const float4*)in)[i];
    uint2 p;
    p.x = pack_h2(v.x, v.y);
    p.y = pack_h2(v.z, v.w);
    ((uint2*)o16)[i] = p;
}

// ---------------------------------------------------------------------------
// 2-pass fp16 HMMA GEMM: C = A16[M,K] @ (Bh+Bl)[N,K]^T + bias (+res)
// 64x32 warp tiles, 8 warps, 2-stage/2-barrier (R9-verified schedule).
// Per chunk: A 1 tile, B 2 tiles (3 tiles/stage, 30KB; 60KB total).
// mode bit0: fp32 Cf; bit1: bf16 split Ch/Cl; bit2: fp16 C16.
// ---------------------------------------------------------------------------
#define MBM 128
#define MBN 128
#define MBK 32
#define MSTR 40
#define MTILE (128 * MSTR * 2)    // 10240 B
#define MSTAGE (3 * MTILE)        // A, Bh, Bl = 30720 B
#define MM_SMEM (2 * MSTAGE)      // 61440 B

__global__ void __launch_bounds__(256, 2)
mma_gemm_kernel(
    const __half* __restrict__ Af,
    const __half* __restrict__ Bh, const __half* __restrict__ Bl,
    const float* __restrict__ bias, const float* __restrict__ res,
    float* __restrict__ Cf,
    __nv_bfloat16* __restrict__ Ch, __nv_bfloat16* __restrict__ Cl,
    __half* __restrict__ C16,
    int M, int N, int K, int hasRes, int mode)
{
    extern __shared__ __align__(16) char smem[];
    const uint32_t sbase = smem_u32(smem);

    const int t    = threadIdx.x;
    const int wid  = t >> 5;
    const int lane = t & 31;
    const int m0 = blockIdx.y * MBM;
    const int n0 = blockIdx.x * MBN;

    const int warp_m = (wid >> 2) * 64;
    const int warp_n = (wid & 3) * 32;

    const int crow  = t >> 1;
    const int cq    = (t & 1) * 2;

    const __half* gsrc[3];
    gsrc[0] = Af + (size_t)(m0 + crow) * K;
    gsrc[1] = Bh + (size_t)(n0 + crow) * K;
    gsrc[2] = Bl + (size_t)(n0 + crow) * K;
    const uint32_t sdst_row = crow * (MSTR * 2);

    const int nc = K / MBK;

    {
#pragma unroll
        for (int tl = 0; tl < 3; tl++) {
            const uint32_t d = sbase + tl * MTILE + sdst_row;
            cp_async16(d + (cq + 0) * 16, gsrc[tl] + (cq + 0) * 8);
            cp_async16(d + (cq + 1) * 16, gsrc[tl] + (cq + 1) * 8);
        }
        cp_commit();
    }

    float acc[4][4][4];
#pragma unroll
    for (int mi = 0; mi < 4; mi++)
#pragma unroll
        for (int ni = 0; ni < 4; ni++)
#pragma unroll
            for (int r = 0; r < 4; r++) acc[mi][ni][r] = 0.0f;

    const int lrow = lane & 15;
    const int lcolq = (lane >> 4) << 3;

    for (int c = 0; c < nc; c++) {
        const int st = c & 1;
        if (c + 1 < nc) {
            const int k0 = (c + 1) * MBK;
            const uint32_t so = ((c + 1) & 1) * MSTAGE;
#pragma unroll
            for (int tl = 0; tl < 3; tl++) {
                const uint32_t d = sbase + so + tl * MTILE + sdst_row;
                cp_async16(d + (cq + 0) * 16, gsrc[tl] + k0 + (cq + 0) * 8);
                cp_async16(d + (cq + 1) * 16, gsrc[tl] + k0 + (cq + 1) * 8);
            }
            cp_commit();
            cp_wait<1>();
        } else {
            cp_wait<0>();
        }
        __syncthreads();

        const uint32_t sA  = sbase + st * MSTAGE + 0 * MTILE;
        const uint32_t sBh = sbase + st * MSTAGE + 1 * MTILE;
        const uint32_t sBl = sbase + st * MSTAGE + 2 * MTILE;

#pragma unroll
        for (int ks = 0; ks < 2; ks++) {
            const int col = ks * 16 + lcolq;
            uint32_t af[4][4];
#pragma unroll
            for (int mi = 0; mi < 4; mi++) {
                const uint32_t off =
                    (uint32_t)(warp_m + mi * 16 + lrow) * (MSTR * 2) + col * 2;
                ldsm_x4(sA + off, af[mi]);
            }
            uint32_t bfh[4][2], bfl[4][2];
#pragma unroll
            for (int n2 = 0; n2 < 2; n2++) {
                const uint32_t off =
                    (uint32_t)(warp_n + n2 * 16 + lrow) * (MSTR * 2) + col * 2;
                uint32_t r4[4];
                ldsm_x4(sBh + off, r4);
                bfh[n2 * 2 + 0][0] = r4[0]; bfh[n2 * 2 + 1][0] = r4[1];
                bfh[n2 * 2 + 0][1] = r4[2]; bfh[n2 * 2 + 1][1] = r4[3];
                ldsm_x4(sBl + off, r4);
                bfl[n2 * 2 + 0][0] = r4[0]; bfl[n2 * 2 + 1][0] = r4[1];
                bfl[n2 * 2 + 0][1] = r4[2]; bfl[n2 * 2 + 1][1] = r4[3];
            }
#pragma unroll
            for (int mi = 0; mi < 4; mi++)
#pragma unroll
                for (int ni = 0; ni < 4; ni++) {
                    mma_fp16(acc[mi][ni], af[mi], bfh[ni][0], bfh[ni][1]);
                    mma_fp16(acc[mi][ni], af[mi], bfl[ni][0], bfl[ni][1]);
                }
        }
        __syncthreads();   // WAR guard on the recycled stage
    }

    const int g  = lane >> 2;
    const int tg = lane & 3;
#pragma unroll
    for (int mi = 0; mi < 4; mi++) {
#pragma unroll
        for (int ni = 0; ni < 4; ni++) {
            const int colg = n0 + warp_n + ni * 8 + tg * 2;
            const float bx = bias[colg], by = bias[colg + 1];
            const int r0 = m0 + warp_m + mi * 16 + g;
            const int r1 = r0 + 8;
            float2 o0, o1;
            o0.x = acc[mi][ni][0] + bx; o0.y = acc[mi][ni][1] + by;
            o1.x = acc[mi][ni][2] + bx; o1.y = acc[mi][ni][3] + by;
            if (hasRes) {
                const float2 v0 = *(const float2*)(res + (size_t)r0 * N + colg);
                const float2 v1 = *(const float2*)(res + (size_t)r1 * N + colg);
                o0.x += v0.x; o0.y += v0.y;
                o1.x += v1.x; o1.y += v1.y;
            }
            if (mode & 1) {
                *(float2*)(Cf + (size_t)r0 * N + colg) = o0;
                *(float2*)(Cf + (size_t)r1 * N + colg) = o1;
            }
            if (mode & 2) {
                uint32_t hi, lo;
                split2(o0.x, o0.y, hi, lo);
                *(uint32_t*)(Ch + (size_t)r0 * N + colg) = hi;
                *(uint32_t*)(Cl + (size_t)r0 * N + colg) = lo;
                split2(o1.x, o1.y, hi, lo);
                *(uint32_t*)(Ch + (size_t)r1 * N + colg) = hi;
                *(uint32_t*)(Cl + (size_t)r1 * N + colg) = lo;
            }
            if (mode & 4) {
                *(uint32_t*)(C16 + (size_t)r0 * N + colg) = pack_h2(o0.x, o0.y);
                *(uint32_t*)(C16 + (size_t)r1 * N + colg) = pack_h2(o1.x, o1.y);
            }
        }
    }
}

// ---------------------------------------------------------------------------
// Tensor-core flash attention, split-bf16 operands (proven path).
// 128-row Q tiles, 256 threads, base-2 softmax. Output: ctx fp16 single.
// ---------------------------------------------------------------------------
#define APAD 144
#define ATILE (64 * APAD)
#define AQTILE (128 * APAD)
#define AQ_H 0
#define AQ_L AQTILE
#define AST0 (2 * AQTILE)
#define ASTG (4 * ATILE)
#define AT_SMEM (2 * AQTILE + 2 * ASTG)      // 110592

__global__ void __launch_bounds__(256)
attn_mma_kernel(
    const __nv_bfloat16* __restrict__ qh, const __nv_bfloat16* __restrict__ ql,
    __half* __restrict__ ct16)
{
    extern __shared__ __align__(16) char smem[];
    const uint32_t sbase = smem_u32(smem);

    const int b  = blockIdx.z;
    const int nh = blockIdx.y;
    const int qt = blockIdx.x;
    const int t  = threadIdx.x;
    const int wid  = t >> 5;
    const int lane = t & 31;
    const int g  = lane >> 2;
    const int tg = lane & 3;
    const int lrow  = lane & 15;
    const int lcolq = (lane >> 4) << 3;

    const size_t bS = (size_t)b * SS;
    const int hoff = nh * HD;

    {
        const int crw = t >> 1;
        const int cqq = (t & 1) * 4;
        const size_t grow = (bS + qt * 128 + crw) * (3 * HH) + hoff;
        const uint32_t d = sbase + crw * APAD + cqq * 16;
#pragma unroll
        for (int i = 0; i < 4; i++) {
            cp_async16(d + AQ_H + i * 16, qh + grow + (cqq + i) * 8);
            cp_async16(d + AQ_L + i * 16, ql + grow + (cqq + i) * 8);
        }
    }

    const int tt   = t & 127;
    const int kv   = t >> 7;
    const int crow = tt >> 1;
    const int cq0  = (tt & 1) * 4;
    const int srcoff = (kv + 1) * HH;
    const uint32_t tile_h = (kv * 2 + 0) * ATILE;
    const uint32_t tile_l = (kv * 2 + 1) * ATILE;

#pragma unroll
    for (int p = 0; p < 2; p++) {
        const size_t grow = (bS + p * 64 + crow) * (3 * HH) + hoff + srcoff;
        const uint32_t d = sbase + AST0 + p * ASTG + crow * APAD + cq0 * 16;
#pragma unroll
        for (int i = 0; i < 4; i++) {
            cp_async16(d + tile_h + i * 16, qh + grow + (cq0 + i) * 8);
            cp_async16(d + tile_l + i * 16, ql + grow + (cq0 + i) * 8);
        }
        cp_commit();
    }

    float acc_o[8][4];
#pragma unroll
    for (int nb = 0; nb < 8; nb++)
#pragma unroll
        for (int r = 0; r < 4; r++) acc_o[nb][r] = 0.0f;

    uint32_t aqh[4][4], aql[4][4];
    float m0 = -INFINITY, m1 = -INFINITY;
    float l0 = 0.0f, l1 = 0.0f;
    const float SC2 = 0.125f * 1.4426950408889634f;   // SCALE * log2(e)

    for (int kt = 0; kt < SS / 64; kt++) {
        if (kt == SS / 64 - 1) { cp_wait<0>(); } else { cp_wait<1>(); }
        __syncthreads();

        if (kt == 0) {
#pragma unroll
            for (int kb = 0; kb < 4; kb++) {
                const uint32_t off =
                    (uint32_t)(wid * 16 + lrow) * APAD + (kb * 16 + lcolq) * 2;
                ldsm_x4(sbase + AQ_H + off, aqh[kb]);
                ldsm_x4(sbase + AQ_L + off, aql[kb]);
            }
        }

        const uint32_t sK_h = sbase + AST0 + (kt & 1) * ASTG + 0 * ATILE;
        const uint32_t sK_l = sbase + AST0 + (kt & 1) * ASTG + 1 * ATILE;
        const uint32_t sV_h = sbase + AST0 + (kt & 1) * ASTG + 2 * ATILE;
        const uint32_t sV_l = sbase + AST0 + (kt & 1) * ASTG + 3 * ATILE;

        float s[8][4];
#pragma unroll
        for (int nb = 0; nb < 8; nb++)
#pragma unroll
            for (int r = 0; r < 4; r++) s[nb][r] = 0.0f;

#pragma unroll
        for (int n2 = 0; n2 < 4; n2++) {
#pragma unroll
            for (int kb = 0; kb < 4; kb++) {
                const uint32_t off =
                    (uint32_t)(n2 * 16 + lrow) * APAD + (kb * 16 + lcolq) * 2;
                uint32_t kh4[4], kl4[4];
                ldsm_x4(sK_h + off, kh4);
                ldsm_x4(sK_l + off, kl4);
                mma_bf16(s[n2 * 2 + 0], aqh[kb], kh4[0], kh4[2]);
                mma_bf16(s[n2 * 2 + 1], aqh[kb], kh4[1], kh4[3]);
                mma_bf16(s[n2 * 2 + 0], aqh[kb], kl4[0], kl4[2]);
                mma_bf16(s[n2 * 2 + 1], aqh[kb], kl4[1], kl4[3]);
                mma_bf16(s[n2 * 2 + 0], aql[kb], kh4[0], kh4[2]);
                mma_bf16(s[n2 * 2 + 1], aql[kb], kh4[1], kh4[3]);
            }
        }

        // base-2 online softmax
        float mx0 = -INFINITY, mx1 = -INFINITY;
#pragma unroll
        for (int nb = 0; nb < 8; nb++) {
            s[nb][0] *= SC2; s[nb][1] *= SC2; s[nb][2] *= SC2; s[nb][3] *= SC2;
            mx0 = fmaxf(mx0, fmaxf(s[nb][0], s[nb][1]));
            mx1 = fmaxf(mx1, fmaxf(s[nb][2], s[nb][3]));
        }
        mx0 = fmaxf(mx0, __shfl_xor_sync(0xffffffffu, mx0, 1));
        mx0 = fmaxf(mx0, __shfl_xor_sync(0xffffffffu, mx0, 2));
        mx1 = fmaxf(mx1, __shfl_xor_sync(0xffffffffu, mx1, 1));
        mx1 = fmaxf(mx1, __shfl_xor_sync(0xffffffffu, mx1, 2));
        const float mn0 = fmaxf(m0, mx0);
        const float mn1 = fmaxf(m1, mx1);
        const float f0 = ex2f(m0 - mn0);
        const float f1 = ex2f(m1 - mn1);
        m0 = mn0; m1 = mn1;
        l0 *= f0; l1 *= f1;
#pragma unroll
        for (int nb = 0; nb < 8; nb++) {
            s[nb][0] = ex2f(s[nb][0] - mn0);
            s[nb][1] = ex2f(s[nb][1] - mn0);
            s[nb][2] = ex2f(s[nb][2] - mn1);
            s[nb][3] = ex2f(s[nb][3] - mn1);
            l0 += s[nb][0] + s[nb][1];
            l1 += s[nb][2] + s[nb][3];
            acc_o[nb][0] *= f0; acc_o[nb][1] *= f0;
            acc_o[nb][2] *= f1; acc_o[nb][3] *= f1;
        }

        uint32_t ph[4][4], pl[4][4];
#pragma unroll
        for (int kb = 0; kb < 4; kb++) {
            split2(s[2 * kb][0],     s[2 * kb][1],     ph[kb][0], pl[kb][0]);
            split2(s[2 * kb][2],     s[2 * kb][3],     ph[kb][1], pl[kb][1]);
            split2(s[2 * kb + 1][0], s[2 * kb + 1][1], ph[kb][2], pl[kb][2]);
            split2(s[2 * kb + 1][2], s[2 * kb + 1][3], ph[kb][3], pl[kb][3]);
        }

#pragma unroll
        for (int kb = 0; kb < 4; kb++) {
#pragma unroll
            for (int n2 = 0; n2 < 4; n2++) {
                const uint32_t off =
                    (uint32_t)(kb * 16 + lrow) * APAD + (n2 * 16 + lcolq) * 2;
                uint32_t vh4[4], vl4[4];
                ldsm_x4_t(sV_h + off, vh4);
                ldsm_x4_t(sV_l + off, vl4);
                mma_bf16(acc_o[n2 * 2 + 0], ph[kb], vh4[0], vh4[1]);
                mma_bf16(acc_o[n2 * 2 + 1], ph[kb], vh4[2], vh4[3]);
                mma_bf16(acc_o[n2 * 2 + 0], ph[kb], vl4[0], vl4[1]);
                mma_bf16(acc_o[n2 * 2 + 1], ph[kb], vl4[2], vl4[3]);
                mma_bf16(acc_o[n2 * 2 + 0], pl[kb], vh4[0], vh4[1]);
                mma_bf16(acc_o[n2 * 2 + 1], pl[kb], vh4[2], vh4[3]);
            }
        }

        __syncthreads();   // WAR guard: prefetch below writes the stage read above
        if (kt + 2 < SS / 64) {
            const size_t grow = (bS + (kt + 2) * 64 + crow) * (3 * HH) + hoff + srcoff;
            const uint32_t d = sbase + AST0 + (kt & 1) * ASTG + crow * APAD + cq0 * 16;
#pragma unroll
            for (int i = 0; i < 4; i++) {
                cp_async16(d + tile_h + i * 16, qh + grow + (cq0 + i) * 8);
                cp_async16(d + tile_l + i * 16, ql + grow + (cq0 + i) * 8);
            }
        }
        cp_commit();
    }

    l0 += __shfl_xor_sync(0xffffffffu, l0, 1);
    l0 += __shfl_xor_sync(0xffffffffu, l0, 2);
    l1 += __shfl_xor_sync(0xffffffffu, l1, 1);
    l1 += __shfl_xor_sync(0xffffffffu, l1, 2);
    const float inv0 = 1.0f / l0;
    const float inv1 = 1.0f / l1;

    const size_t r0 = bS + qt * 128 + wid * 16 + g;
    const size_t r1 = r0 + 8;
#pragma unroll
    for (int nb = 0; nb < 8; nb++) {
        const int col = hoff + nb * 8 + tg * 2;
        *(uint32_t*)(ct16 + r0 * HH + col) =
            pack_h2(acc_o[nb][0] * inv0, acc_o[nb][1] * inv0);
        *(uint32_t*)(ct16 + r1 * HH + col) =
            pack_h2(acc_o[nb][2] * inv1, acc_o[nb][3] * inv1);
    }
}

// ---------------------------------------------------------------------------
// One-pass warp-per-row LayerNorm; emits fp32 + optional fp16
// ---------------------------------------------------------------------------
__global__ void __launch_bounds__(256) ln_kernel(
    const float* __restrict__ in, const float* __restrict__ gamma,
    const float* __restrict__ beta, float* __restrict__ out,
    __half* __restrict__ out16, int do16)
{
    const int warp = threadIdx.x >> 5;
    const int lane = threadIdx.x & 31;
    const int row  = blockIdx.x * 8 + warp;
    const float* x = in + (size_t)row * HH;

    float v[32];
    float s = 0.0f;
#pragma unroll
    for (int k = 0; k < 8; k++) {
        const float4 t4 = *(const float4*)&x[(k * 32 + lane) * 4];
        v[k * 4 + 0] = t4.x; v[k * 4 + 1] = t4.y;
        v[k * 4 + 2] = t4.z; v[k * 4 + 3] = t4.w;
        s += (t4.x + t4.y) + (t4.z + t4.w);
    }
#pragma unroll
    for (int o = 16; o > 0; o >>= 1) s += __shfl_xor_sync(0xffffffffu, s, o);
    const float mean = s * (1.0f / HH);

    float var = 0.0f;
#pragma unroll
    for (int i = 0; i < 32; i++) {
        const float d = v[i] - mean;
        var += d * d;
    }
#pragma unroll
    for (int o = 16; o > 0; o >>= 1) var += __shfl_xor_sync(0xffffffffu, var, o);
    const float rstd = rsqrtf(var * (1.0f / HH) + 1e-5f);

#pragma unroll
    for (int k = 0; k < 8; k++) {
        const int i0 = (k * 32 + lane) * 4;
        const float4 gv = *(const float4*)&gamma[i0];
        const float4 bv = *(const float4*)&beta[i0];
        float4 o;
        o.x = (v[k * 4 + 0] - mean) * rstd * gv.x + bv.x;
        o.y = (v[k * 4 + 1] - mean) * rstd * gv.y + bv.y;
        o.z = (v[k * 4 + 2] - mean) * rstd * gv.z + bv.z;
        o.w = (v[k * 4 + 3] - mean) * rstd * gv.w + bv.w;
        *(float4*)&out[(size_t)row * HH + i0] = o;
        if (do16) {
            uint2 p;
            p.x = pack_h2(o.x, o.y);
            p.y = pack_h2(o.z, o.w);
            *(uint2*)(out16 + (size_t)row * HH + i0) = p;
        }
    }
}

__global__ void __launch_bounds__(256) pool_kernel(
    const float* __restrict__ h, float* __restrict__ pooled)
{
    const int j = blockIdx.x * 256 + threadIdx.x;
    const int b = blockIdx.y;
    float s = 0.0f;
#pragma unroll 8
    for (int ss = 0; ss < SS; ss++)
        s += h[((size_t)b * SS + ss) * HH + j];
    pooled[b * HH + j] = s * (1.0f / SS);
}

__global__ void __launch_bounds__(256) final_gemm_kernel(
    const float* __restrict__ pooled, const float* __restrict__ W,
    const float* __restrict__ bias, float* __restrict__ out)
{
    __shared__ float pr[HH];
    const int b   = blockIdx.y;
    const int col = blockIdx.x * 256 + threadIdx.x;
    for (int i = threadIdx.x; i < HH; i += 256) pr[i] = pooled[b * HH + i];
    __syncthreads();
    float s = bias[col];
#pragma unroll 8
    for (int k = 0; k < HH; k++)
        s += pr[k] * W[(size_t)k * HH + col];
    out[b * HH + col] = s;
}

// ---------------------------------------------------------------------------
// Launch
// ---------------------------------------------------------------------------
extern "C" void kernel_launch(void* const* d_in, const int* in_sizes, int n_in,
                              void* d_out, int out_size)
{
    const float* x     = (const float*)d_in[0];
    const float* W_in  = (const float*)d_in[1];
    const float* b_in  = (const float*)d_in[2];
    const float* W_qkv = (const float*)d_in[3];
    const float* b_qkv = (const float*)d_in[4];
    const float* W_o   = (const float*)d_in[5];
    const float* b_o   = (const float*)d_in[6];
    const float* g1    = (const float*)d_in[7];
    const float* be1   = (const float*)d_in[8];
    const float* W_out = (const float*)d_in[9];
    const float* b_out = (const float*)d_in[10];
    const float* g2    = (const float*)d_in[11];
    const float* be2   = (const float*)d_in[12];
    float* out = (float*)d_out;

    float *h, *tmp, *pool, *fin;
    cudaGetSymbolAddress((void**)&h,    g_h);
    cudaGetSymbolAddress((void**)&tmp,  g_tmp);
    cudaGetSymbolAddress((void**)&pool, g_pool);
    cudaGetSymbolAddress((void**)&fin,  g_fin);

    __half *x16, *h16, *c16, *wh, *wl;
    __nv_bfloat16 *qh, *ql;
    cudaGetSymbolAddress((void**)&x16, g_x16);
    cudaGetSymbolAddress((void**)&h16, g_h16);
    cudaGetSymbolAddress((void**)&c16, g_c16);
    cudaGetSymbolAddress((void**)&qh,  g_qh);
    cudaGetSymbolAddress((void**)&ql,  g_ql);
    cudaGetSymbolAddress((void**)&wh,  g_wh);
    cudaGetSymbolAddress((void**)&wl,  g_wl);

    cudaFuncSetAttribute(mma_gemm_kernel, cudaFuncAttributeMaxDynamicSharedMemorySize, MM_SMEM);
    cudaFuncSetAttribute(attn_mma_kernel, cudaFuncAttributeMaxDynamicSharedMemorySize, AT_SMEM);

    // 0. batched weight transpose + fp16 split
    transpose_split_all<<<T_TOTAL, 256>>>(W_in, W_qkv, W_o, wh, wl);

    // 1. x -> fp16; in-proj -> h fp32 + h16 (mode 5)
    {
        const int n4 = MROWS * DIN / 4;
        split_act_kernel<<<(n4 + 255) / 256, 256>>>(x, x16, n4);
        mma_gemm_kernel<<<dim3(HH / MBN, MROWS / MBM), 256, MM_SMEM>>>(
            x16, wh + OFF_WIN, wl + OFF_WIN, b_in, nullptr,
            h, nullptr, nullptr, h16, MROWS, HH, DIN, 0, 5);
    }

    // 2. layers
    for (int l = 0; l < NLAYER; l++) {
        const __half* WqH = wh + OFF_WQKV + (size_t)l * 3 * HH * HH;
        const __half* WqL = wl + OFF_WQKV + (size_t)l * 3 * HH * HH;
        const __half* WoH = wh + OFF_WO + (size_t)l * HH * HH;
        const __half* WoL = wl + OFF_WO + (size_t)l * HH * HH;
        const float* bq = b_qkv + (size_t)l * 3 * HH;
        const float* bo = b_o + (size_t)l * HH;
        const float* gg = g1 + (size_t)l * HH;
        const float* bb = be1 + (size_t)l * HH;

        // qkv: bf16 split out for attention (mode 2)
        mma_gemm_kernel<<<dim3(3 * HH / MBN, MROWS / MBM), 256, MM_SMEM>>>(
            h16, WqH, WqL, bq, nullptr,
            nullptr, qh, ql, nullptr, MROWS, 3 * HH, HH, 0, 2);

        // attention -> ctx fp16
        attn_mma_kernel<<<dim3(SS / 128, NHEAD, BB), 256, AT_SMEM>>>(qh, ql, c16);

        // o-proj + residual -> fp32 tmp (mode 1)
        mma_gemm_kernel<<<dim3(HH / MBN, MROWS / MBM), 256, MM_SMEM>>>(
            c16, WoH, WoL, bo, h,
            tmp, nullptr, nullptr, nullptr, MROWS, HH, HH, 1, 1);

        // layernorm -> h fp32 + h16
        ln_kernel<<<MROWS / 8, 256>>>(tmp, gg, bb, h, h16, 1);
    }

    // 3. mean pool, final projection + LN
    pool_kernel<<<dim3(HH / 256, BB), 256>>>(h, pool);
    final_gemm_kernel<<<dim3(HH / 256, BB), 256>>>(pool, W_out, b_out, fin);
    ln_kernel<<<1, 256>>>(fin, g2, be2, out, nullptr, 0);
}

// round 14
// speedup vs baseline: 1.7159x; 1.1784x over previous
#include <cuda_runtime.h>
#include <cuda_bf16.h>
#include <cuda_fp16.h>
#include <math.h>
#include <stdint.h>

// Problem constants
#define BB 8
#define SS 1024
#define DIN 512
#define HH 1024
#define NHEAD 16
#define HD 64
#define NLAYER 4
#define MROWS (BB * SS)   // 8192

// ---------------------------------------------------------------------------
// Scratch (device globals; no allocation allowed)
// ---------------------------------------------------------------------------
__device__ float g_h[MROWS * HH];          // fp32 residual stream
__device__ float g_tmp[MROWS * HH];
__device__ float g_pool[BB * HH];
__device__ float g_fin[BB * HH];

__device__ __half g_x16[MROWS * DIN];      // x as fp16 (GEMM A)
__device__ __half g_h16[MROWS * HH];       // h as fp16 (GEMM A)
__device__ __half g_c16[MROWS * HH];       // ctx as fp16 (GEMM A)
__device__ __half g_qh[MROWS * 3 * HH];    // qkv fp16 hi (attention)
__device__ __half g_ql[MROWS * 3 * HH];    // qkv fp16 lo (attention)

#define W_TOTAL (DIN * HH + NLAYER * HH * 3 * HH + NLAYER * HH * HH)
__device__ __half g_wh[W_TOTAL];
__device__ __half g_wl[W_TOTAL];

#define OFF_WIN  0
#define OFF_WQKV ((size_t)DIN * HH)
#define OFF_WO   (OFF_WQKV + (size_t)NLAYER * HH * 3 * HH)

// ---------------------------------------------------------------------------
// PTX wrappers (sm_80-portable)
// ---------------------------------------------------------------------------
__device__ __forceinline__ uint32_t smem_u32(const void* p) {
    uint32_t a;
    asm("{ .reg .u64 t; cvta.to.shared.u64 t, %1; cvt.u32.u64 %0, t; }"
        : "=r"(a) : "l"(p));
    return a;
}
__device__ __forceinline__ void cp_async16(uint32_t dst, const void* src) {
    asm volatile("cp.async.cg.shared.global [%0], [%1], 16;" :: "r"(dst), "l"(src));
}
__device__ __forceinline__ void cp_commit() {
    asm volatile("cp.async.commit_group;");
}
template <int N>
__device__ __forceinline__ void cp_wait() {
    asm volatile("cp.async.wait_group %0;" :: "n"(N));
}
__device__ __forceinline__ void ldsm_x4(uint32_t addr, uint32_t r[4]) {
    asm volatile("ldmatrix.sync.aligned.m8n8.x4.shared.b16 {%0,%1,%2,%3}, [%4];"
                 : "=r"(r[0]), "=r"(r[1]), "=r"(r[2]), "=r"(r[3]) : "r"(addr));
}
__device__ __forceinline__ void ldsm_x4_t(uint32_t addr, uint32_t r[4]) {
    asm volatile("ldmatrix.sync.aligned.m8n8.x4.trans.shared.b16 {%0,%1,%2,%3}, [%4];"
                 : "=r"(r[0]), "=r"(r[1]), "=r"(r[2]), "=r"(r[3]) : "r"(addr));
}
__device__ __forceinline__ void mma_fp16(
    float c[4], const uint32_t a[4], const uint32_t b0, const uint32_t b1)
{
    asm volatile(
        "mma.sync.aligned.m16n8k16.row.col.f32.f16.f16.f32 "
        "{%0,%1,%2,%3}, {%4,%5,%6,%7}, {%8,%9}, {%0,%1,%2,%3};"
        : "+f"(c[0]), "+f"(c[1]), "+f"(c[2]), "+f"(c[3])
        : "r"(a[0]), "r"(a[1]), "r"(a[2]), "r"(a[3]), "r"(b0), "r"(b1));
}
__device__ __forceinline__ float ex2f(float x) {
    float r;
    asm("ex2.approx.f32 %0, %1;" : "=f"(r) : "f"(x));
    return r;
}
__device__ __forceinline__ uint32_t pack_h2(float a, float b) {
    __half2 h = __floats2half2_rn(a, b);
    return *(uint32_t*)&h;
}
// fp16 hi/lo split of a float pair
__device__ __forceinline__ void split2h(float a, float b, uint32_t& hi, uint32_t& lo) {
    const __half ha = __float2half_rn(a), hb = __float2half_rn(b);
    __half2 h2; h2.x = ha; h2.y = hb;
    hi = *(uint32_t*)&h2;
    __half2 l2;
    l2.x = __float2half_rn(a - __half2float(ha));
    l2.y = __float2half_rn(b - __half2float(hb));
    lo = *(uint32_t*)&l2;
}

// ---------------------------------------------------------------------------
// Batched weight transpose + fp16 hi/lo split (single launch, 9 matrices)
// ---------------------------------------------------------------------------
#define T_WIN   512
#define T_WQKV  3072
#define T_WO    1024
#define T_TOTAL (T_WIN + NLAYER * T_WQKV + NLAYER * T_WO)

__global__ void __launch_bounds__(256) transpose_split_all(
    const float* __restrict__ W_in, const float* __restrict__ W_qkv,
    const float* __restrict__ W_o,
    __half* __restrict__ wh, __half* __restrict__ wl)
{
    __shared__ float tile[32][33];
    int idx = blockIdx.x;
    const float* W;
    int K, N, t;
    size_t woff;
    if (idx < T_WIN) {
        W = W_in; K = DIN; N = HH; woff = OFF_WIN; t = idx;
    } else if (idx < T_WIN + NLAYER * T_WQKV) {
        const int l = (idx - T_WIN) / T_WQKV;
        t = (idx - T_WIN) % T_WQKV;
        W = W_qkv + (size_t)l * HH * 3 * HH;
        K = HH; N = 3 * HH;
        woff = OFF_WQKV + (size_t)l * 3 * HH * HH;
    } else {
        const int l = (idx - T_WIN - NLAYER * T_WQKV) / T_WO;
        t = (idx - T_WIN - NLAYER * T_WQKV) % T_WO;
        W = W_o + (size_t)l * HH * HH;
        K = HH; N = HH;
        woff = OFF_WO + (size_t)l * HH * HH;
    }
    const int tpr = N / 32;
    const int n0 = (t % tpr) * 32;
    const int k0 = (t / tpr) * 32;
    const int tx = threadIdx.x & 31;
    const int ty = threadIdx.x >> 5;

#pragma unroll
    for (int r = 0; r < 32; r += 8)
        tile[ty + r][tx] = W[(size_t)(k0 + ty + r) * N + n0 + tx];
    __syncthreads();
#pragma unroll
    for (int r = 0; r < 32; r += 8) {
        const float v = tile[tx][ty + r];
        const __half h = __float2half_rn(v);
        const float lo = v - __half2float(h);
        const size_t o = woff + (size_t)(n0 + ty + r) * K + k0 + tx;
        wh[o] = h;
        wl[o] = __float2half_rn(lo);
    }
}

// ---------------------------------------------------------------------------
// Activation to fp16 (x only)
// ---------------------------------------------------------------------------
__global__ void split_act_kernel(
    const float* __restrict__ in, __half* __restrict__ o16, int n4)
{
    const int i = blockIdx.x * 256 + threadIdx.x;
    if (i >= n4) return;
    const float4 v = ((const float4*)in)[i];
    uint2 p;
    p.x = pack_h2(v.x, v.y);
    p.y = pack_h2(v.z, v.w);
    ((uint2*)o16)[i] = p;
}

// ---------------------------------------------------------------------------
// 2-pass fp16 HMMA GEMM: C = A16[M,K] @ (Bh+Bl)[N,K]^T + bias (+res)
// mode bit0: fp32 Cf; bit1: fp16 hi/lo split Ch/Cl; bit2: fp16 C16.
// ---------------------------------------------------------------------------
#define MBM 128
#define MBN 128
#define MBK 32
#define MSTR 40
#define MTILE (128 * MSTR * 2)    // 10240 B
#define MSTAGE (3 * MTILE)        // A, Bh, Bl
#define MM_SMEM (2 * MSTAGE)      // 61440 B

__global__ void __launch_bounds__(256, 2)
mma_gemm_kernel(
    const __half* __restrict__ Af,
    const __half* __restrict__ Bh, const __half* __restrict__ Bl,
    const float* __restrict__ bias, const float* __restrict__ res,
    float* __restrict__ Cf,
    __half* __restrict__ Ch, __half* __restrict__ Cl,
    __half* __restrict__ C16,
    int M, int N, int K, int hasRes, int mode)
{
    extern __shared__ __align__(16) char smem[];
    const uint32_t sbase = smem_u32(smem);

    const int t    = threadIdx.x;
    const int wid  = t >> 5;
    const int lane = t & 31;
    const int m0 = blockIdx.y * MBM;
    const int n0 = blockIdx.x * MBN;

    const int warp_m = (wid >> 2) * 64;
    const int warp_n = (wid & 3) * 32;

    const int crow  = t >> 1;
    const int cq    = (t & 1) * 2;

    const __half* gsrc[3];
    gsrc[0] = Af + (size_t)(m0 + crow) * K;
    gsrc[1] = Bh + (size_t)(n0 + crow) * K;
    gsrc[2] = Bl + (size_t)(n0 + crow) * K;
    const uint32_t sdst_row = crow * (MSTR * 2);

    const int nc = K / MBK;

    {
#pragma unroll
        for (int tl = 0; tl < 3; tl++) {
            const uint32_t d = sbase + tl * MTILE + sdst_row;
            cp_async16(d + (cq + 0) * 16, gsrc[tl] + (cq + 0) * 8);
            cp_async16(d + (cq + 1) * 16, gsrc[tl] + (cq + 1) * 8);
        }
        cp_commit();
    }

    float acc[4][4][4];
#pragma unroll
    for (int mi = 0; mi < 4; mi++)
#pragma unroll
        for (int ni = 0; ni < 4; ni++)
#pragma unroll
            for (int r = 0; r < 4; r++) acc[mi][ni][r] = 0.0f;

    const int lrow = lane & 15;
    const int lcolq = (lane >> 4) << 3;

    for (int c = 0; c < nc; c++) {
        const int st = c & 1;
        if (c + 1 < nc) {
            const int k0 = (c + 1) * MBK;
            const uint32_t so = ((c + 1) & 1) * MSTAGE;
#pragma unroll
            for (int tl = 0; tl < 3; tl++) {
                const uint32_t d = sbase + so + tl * MTILE + sdst_row;
                cp_async16(d + (cq + 0) * 16, gsrc[tl] + k0 + (cq + 0) * 8);
                cp_async16(d + (cq + 1) * 16, gsrc[tl] + k0 + (cq + 1) * 8);
            }
            cp_commit();
            cp_wait<1>();
        } else {
            cp_wait<0>();
        }
        __syncthreads();

        const uint32_t sA  = sbase + st * MSTAGE + 0 * MTILE;
        const uint32_t sBh = sbase + st * MSTAGE + 1 * MTILE;
        const uint32_t sBl = sbase + st * MSTAGE + 2 * MTILE;

#pragma unroll
        for (int ks = 0; ks < 2; ks++) {
            const int col = ks * 16 + lcolq;
            uint32_t af[4][4];
#pragma unroll
            for (int mi = 0; mi < 4; mi++) {
                const uint32_t off =
                    (uint32_t)(warp_m + mi * 16 + lrow) * (MSTR * 2) + col * 2;
                ldsm_x4(sA + off, af[mi]);
            }
            uint32_t bfh[4][2], bfl[4][2];
#pragma unroll
            for (int n2 = 0; n2 < 2; n2++) {
                const uint32_t off =
                    (uint32_t)(warp_n + n2 * 16 + lrow) * (MSTR * 2) + col * 2;
                uint32_t r4[4];
                ldsm_x4(sBh + off, r4);
                bfh[n2 * 2 + 0][0] = r4[0]; bfh[n2 * 2 + 1][0] = r4[1];
                bfh[n2 * 2 + 0][1] = r4[2]; bfh[n2 * 2 + 1][1] = r4[3];
                ldsm_x4(sBl + off, r4);
                bfl[n2 * 2 + 0][0] = r4[0]; bfl[n2 * 2 + 1][0] = r4[1];
                bfl[n2 * 2 + 0][1] = r4[2]; bfl[n2 * 2 + 1][1] = r4[3];
            }
#pragma unroll
            for (int mi = 0; mi < 4; mi++)
#pragma unroll
                for (int ni = 0; ni < 4; ni++) {
                    mma_fp16(acc[mi][ni], af[mi], bfh[ni][0], bfh[ni][1]);
                    mma_fp16(acc[mi][ni], af[mi], bfl[ni][0], bfl[ni][1]);
                }
        }
        __syncthreads();   // WAR guard on the recycled stage
    }

    const int g  = lane >> 2;
    const int tg = lane & 3;
#pragma unroll
    for (int mi = 0; mi < 4; mi++) {
#pragma unroll
        for (int ni = 0; ni < 4; ni++) {
            const int colg = n0 + warp_n + ni * 8 + tg * 2;
            const float bx = bias[colg], by = bias[colg + 1];
            const int r0 = m0 + warp_m + mi * 16 + g;
            const int r1 = r0 + 8;
            float2 o0, o1;
            o0.x = acc[mi][ni][0] + bx; o0.y = acc[mi][ni][1] + by;
            o1.x = acc[mi][ni][2] + bx; o1.y = acc[mi][ni][3] + by;
            if (hasRes) {
                const float2 v0 = *(const float2*)(res + (size_t)r0 * N + colg);
                const float2 v1 = *(const float2*)(res + (size_t)r1 * N + colg);
                o0.x += v0.x; o0.y += v0.y;
                o1.x += v1.x; o1.y += v1.y;
            }
            if (mode & 1) {
                *(float2*)(Cf + (size_t)r0 * N + colg) = o0;
                *(float2*)(Cf + (size_t)r1 * N + colg) = o1;
            }
            if (mode & 2) {
                uint32_t hi, lo;
                split2h(o0.x, o0.y, hi, lo);
                *(uint32_t*)(Ch + (size_t)r0 * N + colg) = hi;
                *(uint32_t*)(Cl + (size_t)r0 * N + colg) = lo;
                split2h(o1.x, o1.y, hi, lo);
                *(uint32_t*)(Ch + (size_t)r1 * N + colg) = hi;
                *(uint32_t*)(Cl + (size_t)r1 * N + colg) = lo;
            }
            if (mode & 4) {
                *(uint32_t*)(C16 + (size_t)r0 * N + colg) = pack_h2(o0.x, o0.y);
                *(uint32_t*)(C16 + (size_t)r1 * N + colg) = pack_h2(o1.x, o1.y);
            }
        }
    }
}

// ---------------------------------------------------------------------------
// Tensor-core flash attention, all-fp16 operands:
// Q single fp16, K fp16 hi/lo, P single fp16, V fp16 hi/lo.
// 128-row Q tiles, 256 threads, base-2 softmax. Output: ctx fp16.
// ---------------------------------------------------------------------------
#define APAD 144
#define ATILE (64 * APAD)                    // K/V tile: 64 rows
#define AQTILE (128 * APAD)                  // Q tile (hi only): 18432
#define AST0 AQTILE
#define ASTG (4 * ATILE)                     // Kh,Kl,Vh,Vl = 36864
#define AT_SMEM (AQTILE + 2 * ASTG)          // 92160

__global__ void __launch_bounds__(256)
attn_mma_kernel(
    const __half* __restrict__ qh, const __half* __restrict__ ql,
    __half* __restrict__ ct16)
{
    extern __shared__ __align__(16) char smem[];
    const uint32_t sbase = smem_u32(smem);

    const int b  = blockIdx.z;
    const int nh = blockIdx.y;
    const int qt = blockIdx.x;
    const int t  = threadIdx.x;
    const int wid  = t >> 5;
    const int lane = t & 31;
    const int g  = lane >> 2;
    const int tg = lane & 3;
    const int lrow  = lane & 15;
    const int lcolq = (lane >> 4) << 3;

    const size_t bS = (size_t)b * SS;
    const int hoff = nh * HD;

    // Q tile (hi only)
    {
        const int crw = t >> 1;
        const int cqq = (t & 1) * 4;
        const size_t grow = (bS + qt * 128 + crw) * (3 * HH) + hoff;
        const uint32_t d = sbase + crw * APAD + cqq * 16;
#pragma unroll
        for (int i = 0; i < 4; i++)
            cp_async16(d + i * 16, qh + grow + (cqq + i) * 8);
    }

    const int tt   = t & 127;
    const int kv   = t >> 7;
    const int crow = tt >> 1;
    const int cq0  = (tt & 1) * 4;
    const int srcoff = (kv + 1) * HH;
    const uint32_t tile_h = (kv * 2 + 0) * ATILE;
    const uint32_t tile_l = (kv * 2 + 1) * ATILE;

#pragma unroll
    for (int p = 0; p < 2; p++) {
        const size_t grow = (bS + p * 64 + crow) * (3 * HH) + hoff + srcoff;
        const uint32_t d = sbase + AST0 + p * ASTG + crow * APAD + cq0 * 16;
#pragma unroll
        for (int i = 0; i < 4; i++) {
            cp_async16(d + tile_h + i * 16, qh + grow + (cq0 + i) * 8);
            cp_async16(d + tile_l + i * 16, ql + grow + (cq0 + i) * 8);
        }
        cp_commit();
    }

    float acc_o[8][4];
#pragma unroll
    for (int nb = 0; nb < 8; nb++)
#pragma unroll
        for (int r = 0; r < 4; r++) acc_o[nb][r] = 0.0f;

    uint32_t aq[4][4];
    float m0 = -INFINITY, m1 = -INFINITY;
    float l0 = 0.0f, l1 = 0.0f;
    const float SC2 = 0.125f * 1.4426950408889634f;   // SCALE * log2(e)

    for (int kt = 0; kt < SS / 64; kt++) {
        if (kt == SS / 64 - 1) { cp_wait<0>(); } else { cp_wait<1>(); }
        __syncthreads();

        if (kt == 0) {
#pragma unroll
            for (int kb = 0; kb < 4; kb++) {
                const uint32_t off =
                    (uint32_t)(wid * 16 + lrow) * APAD + (kb * 16 + lcolq) * 2;
                ldsm_x4(sbase + off, aq[kb]);
            }
        }

        const uint32_t sK_h = sbase + AST0 + (kt & 1) * ASTG + 0 * ATILE;
        const uint32_t sK_l = sbase + AST0 + (kt & 1) * ASTG + 1 * ATILE;
        const uint32_t sV_h = sbase + AST0 + (kt & 1) * ASTG + 2 * ATILE;
        const uint32_t sV_l = sbase + AST0 + (kt & 1) * ASTG + 3 * ATILE;

        float s[8][4];
#pragma unroll
        for (int nb = 0; nb < 8; nb++)
#pragma unroll
            for (int r = 0; r < 4; r++) s[nb][r] = 0.0f;

#pragma unroll
        for (int n2 = 0; n2 < 4; n2++) {
#pragma unroll
            for (int kb = 0; kb < 4; kb++) {
                const uint32_t off =
                    (uint32_t)(n2 * 16 + lrow) * APAD + (kb * 16 + lcolq) * 2;
                uint32_t kh4[4], kl4[4];
                ldsm_x4(sK_h + off, kh4);
                ldsm_x4(sK_l + off, kl4);
                mma_fp16(s[n2 * 2 + 0], aq[kb], kh4[0], kh4[2]);
                mma_fp16(s[n2 * 2 + 1], aq[kb], kh4[1], kh4[3]);
                mma_fp16(s[n2 * 2 + 0], aq[kb], kl4[0], kl4[2]);
                mma_fp16(s[n2 * 2 + 1], aq[kb], kl4[1], kl4[3]);
            }
        }

        // base-2 online softmax
        float mx0 = -INFINITY, mx1 = -INFINITY;
#pragma unroll
        for (int nb = 0; nb < 8; nb++) {
            s[nb][0] *= SC2; s[nb][1] *= SC2; s[nb][2] *= SC2; s[nb][3] *= SC2;
            mx0 = fmaxf(mx0, fmaxf(s[nb][0], s[nb][1]));
            mx1 = fmaxf(mx1, fmaxf(s[nb][2], s[nb][3]));
        }
        mx0 = fmaxf(mx0, __shfl_xor_sync(0xffffffffu, mx0, 1));
        mx0 = fmaxf(mx0, __shfl_xor_sync(0xffffffffu, mx0, 2));
        mx1 = fmaxf(mx1, __shfl_xor_sync(0xffffffffu, mx1, 1));
        mx1 = fmaxf(mx1, __shfl_xor_sync(0xffffffffu, mx1, 2));
        const float mn0 = fmaxf(m0, mx0);
        const float mn1 = fmaxf(m1, mx1);
        const float f0 = ex2f(m0 - mn0);
        const float f1 = ex2f(m1 - mn1);
        m0 = mn0; m1 = mn1;
        l0 *= f0; l1 *= f1;
#pragma unroll
        for (int nb = 0; nb < 8; nb++) {
            s[nb][0] = ex2f(s[nb][0] - mn0);
            s[nb][1] = ex2f(s[nb][1] - mn0);
            s[nb][2] = ex2f(s[nb][2] - mn1);
            s[nb][3] = ex2f(s[nb][3] - mn1);
            l0 += s[nb][0] + s[nb][1];
            l1 += s[nb][2] + s[nb][3];
            acc_o[nb][0] *= f0; acc_o[nb][1] *= f0;
            acc_o[nb][2] *= f1; acc_o[nb][3] *= f1;
        }

        // P fragments: single fp16
        uint32_t ph[4][4];
#pragma unroll
        for (int kb = 0; kb < 4; kb++) {
            ph[kb][0] = pack_h2(s[2 * kb][0],     s[2 * kb][1]);
            ph[kb][1] = pack_h2(s[2 * kb][2],     s[2 * kb][3]);
            ph[kb][2] = pack_h2(s[2 * kb + 1][0], s[2 * kb + 1][1]);
            ph[kb][3] = pack_h2(s[2 * kb + 1][2], s[2 * kb + 1][3]);
        }

#pragma unroll
        for (int kb = 0; kb < 4; kb++) {
#pragma unroll
            for (int n2 = 0; n2 < 4; n2++) {
                const uint32_t off =
                    (uint32_t)(kb * 16 + lrow) * APAD + (n2 * 16 + lcolq) * 2;
                uint32_t vh4[4], vl4[4];
                ldsm_x4_t(sV_h + off, vh4);
                ldsm_x4_t(sV_l + off, vl4);
                mma_fp16(acc_o[n2 * 2 + 0], ph[kb], vh4[0], vh4[1]);
                mma_fp16(acc_o[n2 * 2 + 1], ph[kb], vh4[2], vh4[3]);
                mma_fp16(acc_o[n2 * 2 + 0], ph[kb], vl4[0], vl4[1]);
                mma_fp16(acc_o[n2 * 2 + 1], ph[kb], vl4[2], vl4[3]);
            }
        }

        __syncthreads();   // WAR guard: prefetch below writes the stage read above
        if (kt + 2 < SS / 64) {
            const size_t grow = (bS + (kt + 2) * 64 + crow) * (3 * HH) + hoff + srcoff;
            const uint32_t d = sbase + AST0 + (kt & 1) * ASTG + crow * APAD + cq0 * 16;
#pragma unroll
            for (int i = 0; i < 4; i++) {
                cp_async16(d + tile_h + i * 16, qh + grow + (cq0 + i) * 8);
                cp_async16(d + tile_l + i * 16, ql + grow + (cq0 + i) * 8);
            }
        }
        cp_commit();
    }

    l0 += __shfl_xor_sync(0xffffffffu, l0, 1);
    l0 += __shfl_xor_sync(0xffffffffu, l0, 2);
    l1 += __shfl_xor_sync(0xffffffffu, l1, 1);
    l1 += __shfl_xor_sync(0xffffffffu, l1, 2);
    const float inv0 = 1.0f / l0;
    const float inv1 = 1.0f / l1;

    const size_t r0 = bS + qt * 128 + wid * 16 + g;
    const size_t r1 = r0 + 8;
#pragma unroll
    for (int nb = 0; nb < 8; nb++) {
        const int col = hoff + nb * 8 + tg * 2;
        *(uint32_t*)(ct16 + r0 * HH + col) =
            pack_h2(acc_o[nb][0] * inv0, acc_o[nb][1] * inv0);
        *(uint32_t*)(ct16 + r1 * HH + col) =
            pack_h2(acc_o[nb][2] * inv1, acc_o[nb][3] * inv1);
    }
}

// ---------------------------------------------------------------------------
// One-pass warp-per-row LayerNorm; emits fp32 + optional fp16
// ---------------------------------------------------------------------------
__global__ void __launch_bounds__(256) ln_kernel(
    const float* __restrict__ in, const float* __restrict__ gamma,
    const float* __restrict__ beta, float* __restrict__ out,
    __half* __restrict__ out16, int do16)
{
    const int warp = threadIdx.x >> 5;
    const int lane = threadIdx.x & 31;
    const int row  = blockIdx.x * 8 + warp;
    const float* x = in + (size_t)row * HH;

    float v[32];
    float s = 0.0f;
#pragma unroll
    for (int k = 0; k < 8; k++) {
        const float4 t4 = *(const float4*)&x[(k * 32 + lane) * 4];
        v[k * 4 + 0] = t4.x; v[k * 4 + 1] = t4.y;
        v[k * 4 + 2] = t4.z; v[k * 4 + 3] = t4.w;
        s += (t4.x + t4.y) + (t4.z + t4.w);
    }
#pragma unroll
    for (int o = 16; o > 0; o >>= 1) s += __shfl_xor_sync(0xffffffffu, s, o);
    const float mean = s * (1.0f / HH);

    float var = 0.0f;
#pragma unroll
    for (int i = 0; i < 32; i++) {
        const float d = v[i] - mean;
        var += d * d;
    }
#pragma unroll
    for (int o = 16; o > 0; o >>= 1) var += __shfl_xor_sync(0xffffffffu, var, o);
    const float rstd = rsqrtf(var * (1.0f / HH) + 1e-5f);

#pragma unroll
    for (int k = 0; k < 8; k++) {
        const int i0 = (k * 32 + lane) * 4;
        const float4 gv = *(const float4*)&gamma[i0];
        const float4 bv = *(const float4*)&beta[i0];
        float4 o;
        o.x = (v[k * 4 + 0] - mean) * rstd * gv.x + bv.x;
        o.y = (v[k * 4 + 1] - mean) * rstd * gv.y + bv.y;
        o.z = (v[k * 4 + 2] - mean) * rstd * gv.z + bv.z;
        o.w = (v[k * 4 + 3] - mean) * rstd * gv.w + bv.w;
        *(float4*)&out[(size_t)row * HH + i0] = o;
        if (do16) {
            uint2 p;
            p.x = pack_h2(o.x, o.y);
            p.y = pack_h2(o.z, o.w);
            *(uint2*)(out16 + (size_t)row * HH + i0) = p;
        }
    }
}

__global__ void __launch_bounds__(256) pool_kernel(
    const float* __restrict__ h, float* __restrict__ pooled)
{
    const int j = blockIdx.x * 256 + threadIdx.x;
    const int b = blockIdx.y;
    float s = 0.0f;
#pragma unroll 8
    for (int ss = 0; ss < SS; ss++)
        s += h[((size_t)b * SS + ss) * HH + j];
    pooled[b * HH + j] = s * (1.0f / SS);
}

__global__ void __launch_bounds__(256) final_gemm_kernel(
    const float* __restrict__ pooled, const float* __restrict__ W,
    const float* __restrict__ bias, float* __restrict__ out)
{
    __shared__ float pr[HH];
    const int b   = blockIdx.y;
    const int col = blockIdx.x * 256 + threadIdx.x;
    for (int i = threadIdx.x; i < HH; i += 256) pr[i] = pooled[b * HH + i];
    __syncthreads();
    float s = bias[col];
#pragma unroll 8
    for (int k = 0; k < HH; k++)
        s += pr[k] * W[(size_t)k * HH + col];
    out[b * HH + col] = s;
}

// ---------------------------------------------------------------------------
// Launch
// ---------------------------------------------------------------------------
extern "C" void kernel_launch(void* const* d_in, const int* in_sizes, int n_in,
                              void* d_out, int out_size)
{
    const float* x     = (const float*)d_in[0];
    const float* W_in  = (const float*)d_in[1];
    const float* b_in  = (const float*)d_in[2];
    const float* W_qkv = (const float*)d_in[3];
    const float* b_qkv = (const float*)d_in[4];
    const float* W_o   = (const float*)d_in[5];
    const float* b_o   = (const float*)d_in[6];
    const float* g1    = (const float*)d_in[7];
    const float* be1   = (const float*)d_in[8];
    const float* W_out = (const float*)d_in[9];
    const float* b_out = (const float*)d_in[10];
    const float* g2    = (const float*)d_in[11];
    const float* be2   = (const float*)d_in[12];
    float* out = (float*)d_out;

    float *h, *tmp, *pool, *fin;
    cudaGetSymbolAddress((void**)&h,    g_h);
    cudaGetSymbolAddress((void**)&tmp,  g_tmp);
    cudaGetSymbolAddress((void**)&pool, g_pool);
    cudaGetSymbolAddress((void**)&fin,  g_fin);

    __half *x16, *h16, *c16, *qh, *ql, *wh, *wl;
    cudaGetSymbolAddress((void**)&x16, g_x16);
    cudaGetSymbolAddress((void**)&h16, g_h16);
    cudaGetSymbolAddress((void**)&c16, g_c16);
    cudaGetSymbolAddress((void**)&qh,  g_qh);
    cudaGetSymbolAddress((void**)&ql,  g_ql);
    cudaGetSymbolAddress((void**)&wh,  g_wh);
    cudaGetSymbolAddress((void**)&wl,  g_wl);

    cudaFuncSetAttribute(mma_gemm_kernel, cudaFuncAttributeMaxDynamicSharedMemorySize, MM_SMEM);
    cudaFuncSetAttribute(attn_mma_kernel, cudaFuncAttributeMaxDynamicSharedMemorySize, AT_SMEM);

    // 0. batched weight transpose + fp16 split
    transpose_split_all<<<T_TOTAL, 256>>>(W_in, W_qkv, W_o, wh, wl);

    // 1. x -> fp16; in-proj -> h fp32 + h16 (mode 5)
    {
        const int n4 = MROWS * DIN / 4;
        split_act_kernel<<<(n4 + 255) / 256, 256>>>(x, x16, n4);
        mma_gemm_kernel<<<dim3(HH / MBN, MROWS / MBM), 256, MM_SMEM>>>(
            x16, wh + OFF_WIN, wl + OFF_WIN, b_in, nullptr,
            h, nullptr, nullptr, h16, MROWS, HH, DIN, 0, 5);
    }

    // 2. layers
    for (int l = 0; l < NLAYER; l++) {
        const __half* WqH = wh + OFF_WQKV + (size_t)l * 3 * HH * HH;
        const __half* WqL = wl + OFF_WQKV + (size_t)l * 3 * HH * HH;
        const __half* WoH = wh + OFF_WO + (size_t)l * HH * HH;
        const __half* WoL = wl + OFF_WO + (size_t)l * HH * HH;
        const float* bq = b_qkv + (size_t)l * 3 * HH;
        const float* bo = b_o + (size_t)l * HH;
        const float* gg = g1 + (size_t)l * HH;
        const float* bb = be1 + (size_t)l * HH;

        // qkv: fp16 hi/lo split out for attention (mode 2)
        mma_gemm_kernel<<<dim3(3 * HH / MBN, MROWS / MBM), 256, MM_SMEM>>>(
            h16, WqH, WqL, bq, nullptr,
            nullptr, qh, ql, nullptr, MROWS, 3 * HH, HH, 0, 2);

        // attention -> ctx fp16
        attn_mma_kernel<<<dim3(SS / 128, NHEAD, BB), 256, AT_SMEM>>>(qh, ql, c16);

        // o-proj + residual -> fp32 tmp (mode 1)
        mma_gemm_kernel<<<dim3(HH / MBN, MROWS / MBM), 256, MM_SMEM>>>(
            c16, WoH, WoL, bo, h,
            tmp, nullptr, nullptr, nullptr, MROWS, HH, HH, 1, 1);

        // layernorm -> h fp32 + h16
        ln_kernel<<<MROWS / 8, 256>>>(tmp, gg, bb, h, h16, 1);
    }

    // 3. mean pool, final projection + LN
    pool_kernel<<<dim3(HH / 256, BB), 256>>>(h, pool);
    final_gemm_kernel<<<dim3(HH / 256, BB), 256>>>(pool, W_out, b_out, fin);
    ln_kernel<<<1, 256>>>(fin, g2, be2, out, nullptr, 0);
}

// round 15
// speedup vs baseline: 2.2375x; 1.3040x over previous
#include <cuda_runtime.h>
#include <cuda_bf16.h>
#include <cuda_fp16.h>
#include <math.h>
#include <stdint.h>

// Problem constants
#define BB 8
#define SS 1024
#define DIN 512
#define HH 1024
#define NHEAD 16
#define HD 64
#define NLAYER 4
#define MROWS (BB * SS)   // 8192

// ---------------------------------------------------------------------------
// Scratch (device globals; no allocation allowed)
// ---------------------------------------------------------------------------
__device__ float g_h[MROWS * HH];          // fp32 residual stream
__device__ float g_tmp[MROWS * HH];
__device__ float g_pool[BB * HH];
__device__ float g_fin[BB * HH];

__device__ __half g_x16[MROWS * DIN];      // x as fp16 (GEMM A)
__device__ __half g_h16[MROWS * HH];       // h as fp16 (GEMM A)
__device__ __half g_c16[MROWS * HH];       // ctx as fp16 (GEMM A)
__device__ __half g_qh[MROWS * 3 * HH];    // qkv fp16 hi (attention)
__device__ __half g_ql[MROWS * 3 * HH];    // qkv fp16 lo (attention)

#define W_TOTAL (DIN * HH + NLAYER * HH * 3 * HH + NLAYER * HH * HH)
__device__ __half g_wh[W_TOTAL];           // weights single fp16

#define OFF_WIN  0
#define OFF_WQKV ((size_t)DIN * HH)
#define OFF_WO   (OFF_WQKV + (size_t)NLAYER * HH * 3 * HH)

// ---------------------------------------------------------------------------
// PTX wrappers (sm_80-portable)
// ---------------------------------------------------------------------------
__device__ __forceinline__ uint32_t smem_u32(const void* p) {
    uint32_t a;
    asm("{ .reg .u64 t; cvta.to.shared.u64 t, %1; cvt.u32.u64 %0, t; }"
        : "=r"(a) : "l"(p));
    return a;
}
__device__ __forceinline__ void cp_async16(uint32_t dst, const void* src) {
    asm volatile("cp.async.cg.shared.global [%0], [%1], 16;" :: "r"(dst), "l"(src));
}
__device__ __forceinline__ void cp_commit() {
    asm volatile("cp.async.commit_group;");
}
template <int N>
__device__ __forceinline__ void cp_wait() {
    asm volatile("cp.async.wait_group %0;" :: "n"(N));
}
__device__ __forceinline__ void ldsm_x4(uint32_t addr, uint32_t r[4]) {
    asm volatile("ldmatrix.sync.aligned.m8n8.x4.shared.b16 {%0,%1,%2,%3}, [%4];"
                 : "=r"(r[0]), "=r"(r[1]), "=r"(r[2]), "=r"(r[3]) : "r"(addr));
}
__device__ __forceinline__ void ldsm_x4_t(uint32_t addr, uint32_t r[4]) {
    asm volatile("ldmatrix.sync.aligned.m8n8.x4.trans.shared.b16 {%0,%1,%2,%3}, [%4];"
                 : "=r"(r[0]), "=r"(r[1]), "=r"(r[2]), "=r"(r[3]) : "r"(addr));
}
__device__ __forceinline__ void mma_fp16(
    float c[4], const uint32_t a[4], const uint32_t b0, const uint32_t b1)
{
    asm volatile(
        "mma.sync.aligned.m16n8k16.row.col.f32.f16.f16.f32 "
        "{%0,%1,%2,%3}, {%4,%5,%6,%7}, {%8,%9}, {%0,%1,%2,%3};"
        : "+f"(c[0]), "+f"(c[1]), "+f"(c[2]), "+f"(c[3])
        : "r"(a[0]), "r"(a[1]), "r"(a[2]), "r"(a[3]), "r"(b0), "r"(b1));
}
__device__ __forceinline__ float ex2f(float x) {
    float r;
    asm("ex2.approx.f32 %0, %1;" : "=f"(r) : "f"(x));
    return r;
}
__device__ __forceinline__ uint32_t pack_h2(float a, float b) {
    __half2 h = __floats2half2_rn(a, b);
    return *(uint32_t*)&h;
}
__device__ __forceinline__ void split2h(float a, float b, uint32_t& hi, uint32_t& lo) {
    const __half ha = __float2half_rn(a), hb = __float2half_rn(b);
    __half2 h2; h2.x = ha; h2.y = hb;
    hi = *(uint32_t*)&h2;
    __half2 l2;
    l2.x = __float2half_rn(a - __half2float(ha));
    l2.y = __float2half_rn(b - __half2float(hb));
    lo = *(uint32_t*)&l2;
}

// ---------------------------------------------------------------------------
// Batched weight transpose to fp16 (single precision pass)
// ---------------------------------------------------------------------------
#define T_WIN   512
#define T_WQKV  3072
#define T_WO    1024
#define T_TOTAL (T_WIN + NLAYER * T_WQKV + NLAYER * T_WO)

__global__ void __launch_bounds__(256) transpose_split_all(
    const float* __restrict__ W_in, const float* __restrict__ W_qkv,
    const float* __restrict__ W_o, __half* __restrict__ wh)
{
    __shared__ float tile[32][33];
    int idx = blockIdx.x;
    const float* W;
    int K, N, t;
    size_t woff;
    if (idx < T_WIN) {
        W = W_in; K = DIN; N = HH; woff = OFF_WIN; t = idx;
    } else if (idx < T_WIN + NLAYER * T_WQKV) {
        const int l = (idx - T_WIN) / T_WQKV;
        t = (idx - T_WIN) % T_WQKV;
        W = W_qkv + (size_t)l * HH * 3 * HH;
        K = HH; N = 3 * HH;
        woff = OFF_WQKV + (size_t)l * 3 * HH * HH;
    } else {
        const int l = (idx - T_WIN - NLAYER * T_WQKV) / T_WO;
        t = (idx - T_WIN - NLAYER * T_WQKV) % T_WO;
        W = W_o + (size_t)l * HH * HH;
        K = HH; N = HH;
        woff = OFF_WO + (size_t)l * HH * HH;
    }
    const int tpr = N / 32;
    const int n0 = (t % tpr) * 32;
    const int k0 = (t / tpr) * 32;
    const int tx = threadIdx.x & 31;
    const int ty = threadIdx.x >> 5;

#pragma unroll
    for (int r = 0; r < 32; r += 8)
        tile[ty + r][tx] = W[(size_t)(k0 + ty + r) * N + n0 + tx];
    __syncthreads();
#pragma unroll
    for (int r = 0; r < 32; r += 8) {
        const float v = tile[tx][ty + r];
        wh[woff + (size_t)(n0 + ty + r) * K + k0 + tx] = __float2half_rn(v);
    }
}

// ---------------------------------------------------------------------------
// Activation to fp16 (x only)
// ---------------------------------------------------------------------------
__global__ void split_act_kernel(
    const float* __restrict__ in, __half* __restrict__ o16, int n4)
{
    const int i = blockIdx.x * 256 + threadIdx.x;
    if (i >= n4) return;
    const float4 v = ((const float4*)in)[i];
    uint2 p;
    p.x = pack_h2(v.x, v.y);
    p.y = pack_h2(v.z, v.w);
    ((uint2*)o16)[i] = p;
}

// ---------------------------------------------------------------------------
// Single-pass fp16 HMMA GEMM: C = A16[M,K] @ B16[N,K]^T + bias (+res)
// 64x32 warp tiles, 8 warps, 2-stage/2-barrier (verified schedule).
// Per stage: A + B = 20KB; 40KB total -> 2 CTAs/SM comfortably.
// mode bit0: fp32 Cf; bit1: fp16 hi/lo split Ch/Cl; bit2: fp16 C16.
// ---------------------------------------------------------------------------
#define MBM 128
#define MBN 128
#define MBK 32
#define MSTR 40
#define MTILE (128 * MSTR * 2)    // 10240 B
#define MSTAGE (2 * MTILE)        // A, B = 20480 B
#define MM_SMEM (2 * MSTAGE)      // 40960 B

__global__ void __launch_bounds__(256, 2)
mma_gemm_kernel(
    const __half* __restrict__ Af, const __half* __restrict__ Bf,
    const float* __restrict__ bias, const float* __restrict__ res,
    float* __restrict__ Cf,
    __half* __restrict__ Ch, __half* __restrict__ Cl,
    __half* __restrict__ C16,
    int M, int N, int K, int hasRes, int mode)
{
    extern __shared__ __align__(16) char smem[];
    const uint32_t sbase = smem_u32(smem);

    const int t    = threadIdx.x;
    const int wid  = t >> 5;
    const int lane = t & 31;
    const int m0 = blockIdx.y * MBM;
    const int n0 = blockIdx.x * MBN;

    const int warp_m = (wid >> 2) * 64;
    const int warp_n = (wid & 3) * 32;

    const int crow  = t >> 1;
    const int cq    = (t & 1) * 2;

    const __half* gsrc[2];
    gsrc[0] = Af + (size_t)(m0 + crow) * K;
    gsrc[1] = Bf + (size_t)(n0 + crow) * K;
    const uint32_t sdst_row = crow * (MSTR * 2);

    const int nc = K / MBK;

    {
#pragma unroll
        for (int tl = 0; tl < 2; tl++) {
            const uint32_t d = sbase + tl * MTILE + sdst_row;
            cp_async16(d + (cq + 0) * 16, gsrc[tl] + (cq + 0) * 8);
            cp_async16(d + (cq + 1) * 16, gsrc[tl] + (cq + 1) * 8);
        }
        cp_commit();
    }

    float acc[4][4][4];
#pragma unroll
    for (int mi = 0; mi < 4; mi++)
#pragma unroll
        for (int ni = 0; ni < 4; ni++)
#pragma unroll
            for (int r = 0; r < 4; r++) acc[mi][ni][r] = 0.0f;

    const int lrow = lane & 15;
    const int lcolq = (lane >> 4) << 3;

    for (int c = 0; c < nc; c++) {
        const int st = c & 1;
        if (c + 1 < nc) {
            const int k0 = (c + 1) * MBK;
            const uint32_t so = ((c + 1) & 1) * MSTAGE;
#pragma unroll
            for (int tl = 0; tl < 2; tl++) {
                const uint32_t d = sbase + so + tl * MTILE + sdst_row;
                cp_async16(d + (cq + 0) * 16, gsrc[tl] + k0 + (cq + 0) * 8);
                cp_async16(d + (cq + 1) * 16, gsrc[tl] + k0 + (cq + 1) * 8);
            }
            cp_commit();
            cp_wait<1>();
        } else {
            cp_wait<0>();
        }
        __syncthreads();

        const uint32_t sA = sbase + st * MSTAGE + 0 * MTILE;
        const uint32_t sB = sbase + st * MSTAGE + 1 * MTILE;

#pragma unroll
        for (int ks = 0; ks < 2; ks++) {
            const int col = ks * 16 + lcolq;
            uint32_t af[4][4];
#pragma unroll
            for (int mi = 0; mi < 4; mi++) {
                const uint32_t off =
                    (uint32_t)(warp_m + mi * 16 + lrow) * (MSTR * 2) + col * 2;
                ldsm_x4(sA + off, af[mi]);
            }
            uint32_t bf[4][2];
#pragma unroll
            for (int n2 = 0; n2 < 2; n2++) {
                const uint32_t off =
                    (uint32_t)(warp_n + n2 * 16 + lrow) * (MSTR * 2) + col * 2;
                uint32_t r4[4];
                ldsm_x4(sB + off, r4);
                bf[n2 * 2 + 0][0] = r4[0]; bf[n2 * 2 + 1][0] = r4[1];
                bf[n2 * 2 + 0][1] = r4[2]; bf[n2 * 2 + 1][1] = r4[3];
            }
#pragma unroll
            for (int mi = 0; mi < 4; mi++)
#pragma unroll
                for (int ni = 0; ni < 4; ni++)
                    mma_fp16(acc[mi][ni], af[mi], bf[ni][0], bf[ni][1]);
        }
        __syncthreads();   // WAR guard on the recycled stage
    }

    const int g  = lane >> 2;
    const int tg = lane & 3;
#pragma unroll
    for (int mi = 0; mi < 4; mi++) {
#pragma unroll
        for (int ni = 0; ni < 4; ni++) {
            const int colg = n0 + warp_n + ni * 8 + tg * 2;
            const float bx = bias[colg], by = bias[colg + 1];
            const int r0 = m0 + warp_m + mi * 16 + g;
            const int r1 = r0 + 8;
            float2 o0, o1;
            o0.x = acc[mi][ni][0] + bx; o0.y = acc[mi][ni][1] + by;
            o1.x = acc[mi][ni][2] + bx; o1.y = acc[mi][ni][3] + by;
            if (hasRes) {
                const float2 v0 = *(const float2*)(res + (size_t)r0 * N + colg);
                const float2 v1 = *(const float2*)(res + (size_t)r1 * N + colg);
                o0.x += v0.x; o0.y += v0.y;
                o1.x += v1.x; o1.y += v1.y;
            }
            if (mode & 1) {
                *(float2*)(Cf + (size_t)r0 * N + colg) = o0;
                *(float2*)(Cf + (size_t)r1 * N + colg) = o1;
            }
            if (mode & 2) {
                uint32_t hi, lo;
                split2h(o0.x, o0.y, hi, lo);
                *(uint32_t*)(Ch + (size_t)r0 * N + colg) = hi;
                *(uint32_t*)(Cl + (size_t)r0 * N + colg) = lo;
                split2h(o1.x, o1.y, hi, lo);
                *(uint32_t*)(Ch + (size_t)r1 * N + colg) = hi;
                *(uint32_t*)(Cl + (size_t)r1 * N + colg) = lo;
            }
            if (mode & 4) {
                *(uint32_t*)(C16 + (size_t)r0 * N + colg) = pack_h2(o0.x, o0.y);
                *(uint32_t*)(C16 + (size_t)r1 * N + colg) = pack_h2(o1.x, o1.y);
            }
        }
    }
}

// ---------------------------------------------------------------------------
// Tensor-core flash attention (R14 config — verified):
// Q single fp16, K fp16 hi/lo, P single fp16, V fp16 hi/lo.
// ---------------------------------------------------------------------------
#define APAD 144
#define ATILE (64 * APAD)
#define AQTILE (128 * APAD)
#define AST0 AQTILE
#define ASTG (4 * ATILE)
#define AT_SMEM (AQTILE + 2 * ASTG)          // 92160

__global__ void __launch_bounds__(256)
attn_mma_kernel(
    const __half* __restrict__ qh, const __half* __restrict__ ql,
    __half* __restrict__ ct16)
{
    extern __shared__ __align__(16) char smem[];
    const uint32_t sbase = smem_u32(smem);

    const int b  = blockIdx.z;
    const int nh = blockIdx.y;
    const int qt = blockIdx.x;
    const int t  = threadIdx.x;
    const int wid  = t >> 5;
    const int lane = t & 31;
    const int g  = lane >> 2;
    const int tg = lane & 3;
    const int lrow  = lane & 15;
    const int lcolq = (lane >> 4) << 3;

    const size_t bS = (size_t)b * SS;
    const int hoff = nh * HD;

    {
        const int crw = t >> 1;
        const int cqq = (t & 1) * 4;
        const size_t grow = (bS + qt * 128 + crw) * (3 * HH) + hoff;
        const uint32_t d = sbase + crw * APAD + cqq * 16;
#pragma unroll
        for (int i = 0; i < 4; i++)
            cp_async16(d + i * 16, qh + grow + (cqq + i) * 8);
    }

    const int tt   = t & 127;
    const int kv   = t >> 7;
    const int crow = tt >> 1;
    const int cq0  = (tt & 1) * 4;
    const int srcoff = (kv + 1) * HH;
    const uint32_t tile_h = (kv * 2 + 0) * ATILE;
    const uint32_t tile_l = (kv * 2 + 1) * ATILE;

#pragma unroll
    for (int p = 0; p < 2; p++) {
        const size_t grow = (bS + p * 64 + crow) * (3 * HH) + hoff + srcoff;
        const uint32_t d = sbase + AST0 + p * ASTG + crow * APAD + cq0 * 16;
#pragma unroll
        for (int i = 0; i < 4; i++) {
            cp_async16(d + tile_h + i * 16, qh + grow + (cq0 + i) * 8);
            cp_async16(d + tile_l + i * 16, ql + grow + (cq0 + i) * 8);
        }
        cp_commit();
    }

    float acc_o[8][4];
#pragma unroll
    for (int nb = 0; nb < 8; nb++)
#pragma unroll
        for (int r = 0; r < 4; r++) acc_o[nb][r] = 0.0f;

    uint32_t aq[4][4];
    float m0 = -INFINITY, m1 = -INFINITY;
    float l0 = 0.0f, l1 = 0.0f;
    const float SC2 = 0.125f * 1.4426950408889634f;

    for (int kt = 0; kt < SS / 64; kt++) {
        if (kt == SS / 64 - 1) { cp_wait<0>(); } else { cp_wait<1>(); }
        __syncthreads();

        if (kt == 0) {
#pragma unroll
            for (int kb = 0; kb < 4; kb++) {
                const uint32_t off =
                    (uint32_t)(wid * 16 + lrow) * APAD + (kb * 16 + lcolq) * 2;
                ldsm_x4(sbase + off, aq[kb]);
            }
        }

        const uint32_t sK_h = sbase + AST0 + (kt & 1) * ASTG + 0 * ATILE;
        const uint32_t sK_l = sbase + AST0 + (kt & 1) * ASTG + 1 * ATILE;
        const uint32_t sV_h = sbase + AST0 + (kt & 1) * ASTG + 2 * ATILE;
        const uint32_t sV_l = sbase + AST0 + (kt & 1) * ASTG + 3 * ATILE;

        float s[8][4];
#pragma unroll
        for (int nb = 0; nb < 8; nb++)
#pragma unroll
            for (int r = 0; r < 4; r++) s[nb][r] = 0.0f;

#pragma unroll
        for (int n2 = 0; n2 < 4; n2++) {
#pragma unroll
            for (int kb = 0; kb < 4; kb++) {
                const uint32_t off =
                    (uint32_t)(n2 * 16 + lrow) * APAD + (kb * 16 + lcolq) * 2;
                uint32_t kh4[4], kl4[4];
                ldsm_x4(sK_h + off, kh4);
                ldsm_x4(sK_l + off, kl4);
                mma_fp16(s[n2 * 2 + 0], aq[kb], kh4[0], kh4[2]);
                mma_fp16(s[n2 * 2 + 1], aq[kb], kh4[1], kh4[3]);
                mma_fp16(s[n2 * 2 + 0], aq[kb], kl4[0], kl4[2]);
                mma_fp16(s[n2 * 2 + 1], aq[kb], kl4[1], kl4[3]);
            }
        }

        float mx0 = -INFINITY, mx1 = -INFINITY;
#pragma unroll
        for (int nb = 0; nb < 8; nb++) {
            s[nb][0] *= SC2; s[nb][1] *= SC2; s[nb][2] *= SC2; s[nb][3] *= SC2;
            mx0 = fmaxf(mx0, fmaxf(s[nb][0], s[nb][1]));
            mx1 = fmaxf(mx1, fmaxf(s[nb][2], s[nb][3]));
        }
        mx0 = fmaxf(mx0, __shfl_xor_sync(0xffffffffu, mx0, 1));
        mx0 = fmaxf(mx0, __shfl_xor_sync(0xffffffffu, mx0, 2));
        mx1 = fmaxf(mx1, __shfl_xor_sync(0xffffffffu, mx1, 1));
        mx1 = fmaxf(mx1, __shfl_xor_sync(0xffffffffu, mx1, 2));
        const float mn0 = fmaxf(m0, mx0);
        const float mn1 = fmaxf(m1, mx1);
        const float f0 = ex2f(m0 - mn0);
        const float f1 = ex2f(m1 - mn1);
        m0 = mn0; m1 = mn1;
        l0 *= f0; l1 *= f1;
#pragma unroll
        for (int nb = 0; nb < 8; nb++) {
            s[nb][0] = ex2f(s[nb][0] - mn0);
            s[nb][1] = ex2f(s[nb][1] - mn0);
            s[nb][2] = ex2f(s[nb][2] - mn1);
            s[nb][3] = ex2f(s[nb][3] - mn1);
            l0 += s[nb][0] + s[nb][1];
            l1 += s[nb][2] + s[nb][3];
            acc_o[nb][0] *= f0; acc_o[nb][1] *= f0;
            acc_o[nb][2] *= f1; acc_o[nb][3] *= f1;
        }

        uint32_t ph[4][4];
#pragma unroll
        for (int kb = 0; kb < 4; kb++) {
            ph[kb][0] = pack_h2(s[2 * kb][0],     s[2 * kb][1]);
            ph[kb][1] = pack_h2(s[2 * kb][2],     s[2 * kb][3]);
            ph[kb][2] = pack_h2(s[2 * kb + 1][0], s[2 * kb + 1][1]);
            ph[kb][3] = pack_h2(s[2 * kb + 1][2], s[2 * kb + 1][3]);
        }

#pragma unroll
        for (int kb = 0; kb < 4; kb++) {
#pragma unroll
            for (int n2 = 0; n2 < 4; n2++) {
                const uint32_t off =
                    (uint32_t)(kb * 16 + lrow) * APAD + (n2 * 16 + lcolq) * 2;
                uint32_t vh4[4], vl4[4];
                ldsm_x4_t(sV_h + off, vh4);
                ldsm_x4_t(sV_l + off, vl4);
                mma_fp16(acc_o[n2 * 2 + 0], ph[kb], vh4[0], vh4[1]);
                mma_fp16(acc_o[n2 * 2 + 1], ph[kb], vh4[2], vh4[3]);
                mma_fp16(acc_o[n2 * 2 + 0], ph[kb], vl4[0], vl4[1]);
                mma_fp16(acc_o[n2 * 2 + 1], ph[kb], vl4[2], vl4[3]);
            }
        }

        __syncthreads();
        if (kt + 2 < SS / 64) {
            const size_t grow = (bS + (kt + 2) * 64 + crow) * (3 * HH) + hoff + srcoff;
            const uint32_t d = sbase + AST0 + (kt & 1) * ASTG + crow * APAD + cq0 * 16;
#pragma unroll
            for (int i = 0; i < 4; i++) {
                cp_async16(d + tile_h + i * 16, qh + grow + (cq0 + i) * 8);
                cp_async16(d + tile_l + i * 16, ql + grow + (cq0 + i) * 8);
            }
        }
        cp_commit();
    }

    l0 += __shfl_xor_sync(0xffffffffu, l0, 1);
    l0 += __shfl_xor_sync(0xffffffffu, l0, 2);
    l1 += __shfl_xor_sync(0xffffffffu, l1, 1);
    l1 += __shfl_xor_sync(0xffffffffu, l1, 2);
    const float inv0 = 1.0f / l0;
    const float inv1 = 1.0f / l1;

    const size_t r0 = bS + qt * 128 + wid * 16 + g;
    const size_t r1 = r0 + 8;
#pragma unroll
    for (int nb = 0; nb < 8; nb++) {
        const int col = hoff + nb * 8 + tg * 2;
        *(uint32_t*)(ct16 + r0 * HH + col) =
            pack_h2(acc_o[nb][0] * inv0, acc_o[nb][1] * inv0);
        *(uint32_t*)(ct16 + r1 * HH + col) =
            pack_h2(acc_o[nb][2] * inv1, acc_o[nb][3] * inv1);
    }
}

// ---------------------------------------------------------------------------
// One-pass warp-per-row LayerNorm; emits fp32 + optional fp16
// ---------------------------------------------------------------------------
__global__ void __launch_bounds__(256) ln_kernel(
    const float* __restrict__ in, const float* __restrict__ gamma,
    const float* __restrict__ beta, float* __restrict__ out,
    __half* __restrict__ out16, int do16)
{
    const int warp = threadIdx.x >> 5;
    const int lane = threadIdx.x & 31;
    const int row  = blockIdx.x * 8 + warp;
    const float* x = in + (size_t)row * HH;

    float v[32];
    float s = 0.0f;
#pragma unroll
    for (int k = 0; k < 8; k++) {
        const float4 t4 = *(const float4*)&x[(k * 32 + lane) * 4];
        v[k * 4 + 0] = t4.x; v[k * 4 + 1] = t4.y;
        v[k * 4 + 2] = t4.z; v[k * 4 + 3] = t4.w;
        s += (t4.x + t4.y) + (t4.z + t4.w);
    }
#pragma unroll
    for (int o = 16; o > 0; o >>= 1) s += __shfl_xor_sync(0xffffffffu, s, o);
    const float mean = s * (1.0f / HH);

    float var = 0.0f;
#pragma unroll
    for (int i = 0; i < 32; i++) {
        const float d = v[i] - mean;
        var += d * d;
    }
#pragma unroll
    for (int o = 16; o > 0; o >>= 1) var += __shfl_xor_sync(0xffffffffu, var, o);
    const float rstd = rsqrtf(var * (1.0f / HH) + 1e-5f);

#pragma unroll
    for (int k = 0; k < 8; k++) {
        const int i0 = (k * 32 + lane) * 4;
        const float4 gv = *(const float4*)&gamma[i0];
        const float4 bv = *(const float4*)&beta[i0];
        float4 o;
        o.x = (v[k * 4 + 0] - mean) * rstd * gv.x + bv.x;
        o.y = (v[k * 4 + 1] - mean) * rstd * gv.y + bv.y;
        o.z = (v[k * 4 + 2] - mean) * rstd * gv.z + bv.z;
        o.w = (v[k * 4 + 3] - mean) * rstd * gv.w + bv.w;
        *(float4*)&out[(size_t)row * HH + i0] = o;
        if (do16) {
            uint2 p;
            p.x = pack_h2(o.x, o.y);
            p.y = pack_h2(o.z, o.w);
            *(uint2*)(out16 + (size_t)row * HH + i0) = p;
        }
    }
}

__global__ void __launch_bounds__(256) pool_kernel(
    const float* __restrict__ h, float* __restrict__ pooled)
{
    const int j = blockIdx.x * 256 + threadIdx.x;
    const int b = blockIdx.y;
    float s = 0.0f;
#pragma unroll 8
    for (int ss = 0; ss < SS; ss++)
        s += h[((size_t)b * SS + ss) * HH + j];
    pooled[b * HH + j] = s * (1.0f / SS);
}

__global__ void __launch_bounds__(256) final_gemm_kernel(
    const float* __restrict__ pooled, const float* __restrict__ W,
    const float* __restrict__ bias, float* __restrict__ out)
{
    __shared__ float pr[HH];
    const int b   = blockIdx.y;
    const int col = blockIdx.x * 256 + threadIdx.x;
    for (int i = threadIdx.x; i < HH; i += 256) pr[i] = pooled[b * HH + i];
    __syncthreads();
    float s = bias[col];
#pragma unroll 8
    for (int k = 0; k < HH; k++)
        s += pr[k] * W[(size_t)k * HH + col];
    out[b * HH + col] = s;
}

// ---------------------------------------------------------------------------
// Launch
// ---------------------------------------------------------------------------
extern "C" void kernel_launch(void* const* d_in, const int* in_sizes, int n_in,
                              void* d_out, int out_size)
{
    const float* x     = (const float*)d_in[0];
    const float* W_in  = (const float*)d_in[1];
    const float* b_in  = (const float*)d_in[2];
    const float* W_qkv = (const float*)d_in[3];
    const float* b_qkv = (const float*)d_in[4];
    const float* W_o   = (const float*)d_in[5];
    const float* b_o   = (const float*)d_in[6];
    const float* g1    = (const float*)d_in[7];
    const float* be1   = (const float*)d_in[8];
    const float* W_out = (const float*)d_in[9];
    const float* b_out = (const float*)d_in[10];
    const float* g2    = (const float*)d_in[11];
    const float* be2   = (const float*)d_in[12];
    float* out = (float*)d_out;

    float *h, *tmp, *pool, *fin;
    cudaGetSymbolAddress((void**)&h,    g_h);
    cudaGetSymbolAddress((void**)&tmp,  g_tmp);
    cudaGetSymbolAddress((void**)&pool, g_pool);
    cudaGetSymbolAddress((void**)&fin,  g_fin);

    __half *x16, *h16, *c16, *qh, *ql, *wh;
    cudaGetSymbolAddress((void**)&x16, g_x16);
    cudaGetSymbolAddress((void**)&h16, g_h16);
    cudaGetSymbolAddress((void**)&c16, g_c16);
    cudaGetSymbolAddress((void**)&qh,  g_qh);
    cudaGetSymbolAddress((void**)&ql,  g_ql);
    cudaGetSymbolAddress((void**)&wh,  g_wh);

    cudaFuncSetAttribute(mma_gemm_kernel, cudaFuncAttributeMaxDynamicSharedMemorySize, MM_SMEM);
    cudaFuncSetAttribute(attn_mma_kernel, cudaFuncAttributeMaxDynamicSharedMemorySize, AT_SMEM);

    // 0. batched weight transpose to fp16
    transpose_split_all<<<T_TOTAL, 256>>>(W_in, W_qkv, W_o, wh);

    // 1. x -> fp16; in-proj -> h fp32 + h16 (mode 5)
    {
        const int n4 = MROWS * DIN / 4;
        split_act_kernel<<<(n4 + 255) / 256, 256>>>(x, x16, n4);
        mma_gemm_kernel<<<dim3(HH / MBN, MROWS / MBM), 256, MM_SMEM>>>(
            x16, wh + OFF_WIN, b_in, nullptr,
            h, nullptr, nullptr, h16, MROWS, HH, DIN, 0, 5);
    }

    // 2. layers
    for (int l = 0; l < NLAYER; l++) {
        const __half* Wq = wh + OFF_WQKV + (size_t)l * 3 * HH * HH;
        const __half* Wo = wh + OFF_WO + (size_t)l * HH * HH;
        const float* bq = b_qkv + (size_t)l * 3 * HH;
        const float* bo = b_o + (size_t)l * HH;
        const float* gg = g1 + (size_t)l * HH;
        const float* bb = be1 + (size_t)l * HH;

        // qkv: fp16 hi/lo split out for attention (mode 2)
        mma_gemm_kernel<<<dim3(3 * HH / MBN, MROWS / MBM), 256, MM_SMEM>>>(
            h16, Wq, bq, nullptr,
            nullptr, qh, ql, nullptr, MROWS, 3 * HH, HH, 0, 2);

        // attention -> ctx fp16
        attn_mma_kernel<<<dim3(SS / 128, NHEAD, BB), 256, AT_SMEM>>>(qh, ql, c16);

        // o-proj + residual -> fp32 tmp (mode 1)
        mma_gemm_kernel<<<dim3(HH / MBN, MROWS / MBM), 256, MM_SMEM>>>(
            c16, Wo, bo, h,
            tmp, nullptr, nullptr, nullptr, MROWS, HH, HH, 1, 1);

        // layernorm -> h fp32 + h16
        ln_kernel<<<MROWS / 8, 256>>>(tmp, gg, bb, h, h16, 1);
    }

    // 3. mean pool, final projection + LN
    pool_kernel<<<dim3(HH / 256, BB), 256>>>(h, pool);
    final_gemm_kernel<<<dim3(HH / 256, BB), 256>>>(pool, W_out, b_out, fin);
    ln_kernel<<<1, 256>>>(fin, g2, be2, out, nullptr, 0);
}

// round 16
// speedup vs baseline: 2.7531x; 1.2304x over previous
#include <cuda_runtime.h>
#include <cuda_bf16.h>
#include <cuda_fp16.h>
#include <math.h>
#include <stdint.h>

// Problem constants
#define BB 8
#define SS 1024
#define DIN 512
#define HH 1024
#define NHEAD 16
#define HD 64
#define NLAYER 4
#define MROWS (BB * SS)   // 8192

// ---------------------------------------------------------------------------
// Scratch (device globals; no allocation allowed)
// ---------------------------------------------------------------------------
__device__ float g_h[MROWS * HH];          // fp32 residual stream
__device__ float g_tmp[MROWS * HH];
__device__ float g_pool[BB * HH];
__device__ float g_fin[BB * HH];

__device__ __half g_x16[MROWS * DIN];      // x as fp16 (GEMM A)
__device__ __half g_h16[MROWS * HH];       // h as fp16 (GEMM A)
__device__ __half g_c16[MROWS * HH];       // ctx as fp16 (GEMM A)
__device__ __half g_qkv16[MROWS * 3 * HH]; // qkv fp16 (attention)

#define W_TOTAL (DIN * HH + NLAYER * HH * 3 * HH + NLAYER * HH * HH)
__device__ __half g_wh[W_TOTAL];           // weights fp16

#define OFF_WIN  0
#define OFF_WQKV ((size_t)DIN * HH)
#define OFF_WO   (OFF_WQKV + (size_t)NLAYER * HH * 3 * HH)

// ---------------------------------------------------------------------------
// PTX wrappers (sm_80-portable)
// ---------------------------------------------------------------------------
__device__ __forceinline__ uint32_t smem_u32(const void* p) {
    uint32_t a;
    asm("{ .reg .u64 t; cvta.to.shared.u64 t, %1; cvt.u32.u64 %0, t; }"
        : "=r"(a) : "l"(p));
    return a;
}
__device__ __forceinline__ void cp_async16(uint32_t dst, const void* src) {
    asm volatile("cp.async.cg.shared.global [%0], [%1], 16;" :: "r"(dst), "l"(src));
}
__device__ __forceinline__ void cp_commit() {
    asm volatile("cp.async.commit_group;");
}
template <int N>
__device__ __forceinline__ void cp_wait() {
    asm volatile("cp.async.wait_group %0;" :: "n"(N));
}
__device__ __forceinline__ void ldsm_x4(uint32_t addr, uint32_t r[4]) {
    asm volatile("ldmatrix.sync.aligned.m8n8.x4.shared.b16 {%0,%1,%2,%3}, [%4];"
                 : "=r"(r[0]), "=r"(r[1]), "=r"(r[2]), "=r"(r[3]) : "r"(addr));
}
__device__ __forceinline__ void ldsm_x4_t(uint32_t addr, uint32_t r[4]) {
    asm volatile("ldmatrix.sync.aligned.m8n8.x4.trans.shared.b16 {%0,%1,%2,%3}, [%4];"
                 : "=r"(r[0]), "=r"(r[1]), "=r"(r[2]), "=r"(r[3]) : "r"(addr));
}
__device__ __forceinline__ void mma_fp16(
    float c[4], const uint32_t a[4], const uint32_t b0, const uint32_t b1)
{
    asm volatile(
        "mma.sync.aligned.m16n8k16.row.col.f32.f16.f16.f32 "
        "{%0,%1,%2,%3}, {%4,%5,%6,%7}, {%8,%9}, {%0,%1,%2,%3};"
        : "+f"(c[0]), "+f"(c[1]), "+f"(c[2]), "+f"(c[3])
        : "r"(a[0]), "r"(a[1]), "r"(a[2]), "r"(a[3]), "r"(b0), "r"(b1));
}
__device__ __forceinline__ float ex2f(float x) {
    float r;
    asm("ex2.approx.f32 %0, %1;" : "=f"(r) : "f"(x));
    return r;
}
__device__ __forceinline__ uint32_t pack_h2(float a, float b) {
    __half2 h = __floats2half2_rn(a, b);
    return *(uint32_t*)&h;
}

// ---------------------------------------------------------------------------
// Batched weight transpose to fp16
// ---------------------------------------------------------------------------
#define T_WIN   512
#define T_WQKV  3072
#define T_WO    1024
#define T_TOTAL (T_WIN + NLAYER * T_WQKV + NLAYER * T_WO)

__global__ void __launch_bounds__(256) transpose_split_all(
    const float* __restrict__ W_in, const float* __restrict__ W_qkv,
    const float* __restrict__ W_o, __half* __restrict__ wh)
{
    __shared__ float tile[32][33];
    int idx = blockIdx.x;
    const float* W;
    int K, N, t;
    size_t woff;
    if (idx < T_WIN) {
        W = W_in; K = DIN; N = HH; woff = OFF_WIN; t = idx;
    } else if (idx < T_WIN + NLAYER * T_WQKV) {
        const int l = (idx - T_WIN) / T_WQKV;
        t = (idx - T_WIN) % T_WQKV;
        W = W_qkv + (size_t)l * HH * 3 * HH;
        K = HH; N = 3 * HH;
        woff = OFF_WQKV + (size_t)l * 3 * HH * HH;
    } else {
        const int l = (idx - T_WIN - NLAYER * T_WQKV) / T_WO;
        t = (idx - T_WIN - NLAYER * T_WQKV) % T_WO;
        W = W_o + (size_t)l * HH * HH;
        K = HH; N = HH;
        woff = OFF_WO + (size_t)l * HH * HH;
    }
    const int tpr = N / 32;
    const int n0 = (t % tpr) * 32;
    const int k0 = (t / tpr) * 32;
    const int tx = threadIdx.x & 31;
    const int ty = threadIdx.x >> 5;

#pragma unroll
    for (int r = 0; r < 32; r += 8)
        tile[ty + r][tx] = W[(size_t)(k0 + ty + r) * N + n0 + tx];
    __syncthreads();
#pragma unroll
    for (int r = 0; r < 32; r += 8) {
        const float v = tile[tx][ty + r];
        wh[woff + (size_t)(n0 + ty + r) * K + k0 + tx] = __float2half_rn(v);
    }
}

// ---------------------------------------------------------------------------
// Activation to fp16 (x only)
// ---------------------------------------------------------------------------
__global__ void split_act_kernel(
    const float* __restrict__ in, __half* __restrict__ o16, int n4)
{
    const int i = blockIdx.x * 256 + threadIdx.x;
    if (i >= n4) return;
    const float4 v = ((const float4*)in)[i];
    uint2 p;
    p.x = pack_h2(v.x, v.y);
    p.y = pack_h2(v.z, v.w);
    ((uint2*)o16)[i] = p;
}

// ---------------------------------------------------------------------------
// Single-pass fp16 HMMA GEMM: C = A16[M,K] @ B16[N,K]^T + bias (+res)
// mode bit0: fp32 Cf; bit2: fp16 C16.
// ---------------------------------------------------------------------------
#define MBM 128
#define MBN 128
#define MBK 32
#define MSTR 40
#define MTILE (128 * MSTR * 2)    // 10240 B
#define MSTAGE (2 * MTILE)        // A, B
#define MM_SMEM (2 * MSTAGE)      // 40960 B

__global__ void __launch_bounds__(256, 2)
mma_gemm_kernel(
    const __half* __restrict__ Af, const __half* __restrict__ Bf,
    const float* __restrict__ bias, const float* __restrict__ res,
    float* __restrict__ Cf, __half* __restrict__ C16,
    int M, int N, int K, int hasRes, int mode)
{
    extern __shared__ __align__(16) char smem[];
    const uint32_t sbase = smem_u32(smem);

    const int t    = threadIdx.x;
    const int wid  = t >> 5;
    const int lane = t & 31;
    const int m0 = blockIdx.y * MBM;
    const int n0 = blockIdx.x * MBN;

    const int warp_m = (wid >> 2) * 64;
    const int warp_n = (wid & 3) * 32;

    const int crow  = t >> 1;
    const int cq    = (t & 1) * 2;

    const __half* gsrc[2];
    gsrc[0] = Af + (size_t)(m0 + crow) * K;
    gsrc[1] = Bf + (size_t)(n0 + crow) * K;
    const uint32_t sdst_row = crow * (MSTR * 2);

    const int nc = K / MBK;

    {
#pragma unroll
        for (int tl = 0; tl < 2; tl++) {
            const uint32_t d = sbase + tl * MTILE + sdst_row;
            cp_async16(d + (cq + 0) * 16, gsrc[tl] + (cq + 0) * 8);
            cp_async16(d + (cq + 1) * 16, gsrc[tl] + (cq + 1) * 8);
        }
        cp_commit();
    }

    float acc[4][4][4];
#pragma unroll
    for (int mi = 0; mi < 4; mi++)
#pragma unroll
        for (int ni = 0; ni < 4; ni++)
#pragma unroll
            for (int r = 0; r < 4; r++) acc[mi][ni][r] = 0.0f;

    const int lrow = lane & 15;
    const int lcolq = (lane >> 4) << 3;

    for (int c = 0; c < nc; c++) {
        const int st = c & 1;
        if (c + 1 < nc) {
            const int k0 = (c + 1) * MBK;
            const uint32_t so = ((c + 1) & 1) * MSTAGE;
#pragma unroll
            for (int tl = 0; tl < 2; tl++) {
                const uint32_t d = sbase + so + tl * MTILE + sdst_row;
                cp_async16(d + (cq + 0) * 16, gsrc[tl] + k0 + (cq + 0) * 8);
                cp_async16(d + (cq + 1) * 16, gsrc[tl] + k0 + (cq + 1) * 8);
            }
            cp_commit();
            cp_wait<1>();
        } else {
            cp_wait<0>();
        }
        __syncthreads();

        const uint32_t sA = sbase + st * MSTAGE + 0 * MTILE;
        const uint32_t sB = sbase + st * MSTAGE + 1 * MTILE;

#pragma unroll
        for (int ks = 0; ks < 2; ks++) {
            const int col = ks * 16 + lcolq;
            uint32_t af[4][4];
#pragma unroll
            for (int mi = 0; mi < 4; mi++) {
                const uint32_t off =
                    (uint32_t)(warp_m + mi * 16 + lrow) * (MSTR * 2) + col * 2;
                ldsm_x4(sA + off, af[mi]);
            }
            uint32_t bf[4][2];
#pragma unroll
            for (int n2 = 0; n2 < 2; n2++) {
                const uint32_t off =
                    (uint32_t)(warp_n + n2 * 16 + lrow) * (MSTR * 2) + col * 2;
                uint32_t r4[4];
                ldsm_x4(sB + off, r4);
                bf[n2 * 2 + 0][0] = r4[0]; bf[n2 * 2 + 1][0] = r4[1];
                bf[n2 * 2 + 0][1] = r4[2]; bf[n2 * 2 + 1][1] = r4[3];
            }
#pragma unroll
            for (int mi = 0; mi < 4; mi++)
#pragma unroll
                for (int ni = 0; ni < 4; ni++)
                    mma_fp16(acc[mi][ni], af[mi], bf[ni][0], bf[ni][1]);
        }
        __syncthreads();   // WAR guard on the recycled stage
    }

    const int g  = lane >> 2;
    const int tg = lane & 3;
#pragma unroll
    for (int mi = 0; mi < 4; mi++) {
#pragma unroll
        for (int ni = 0; ni < 4; ni++) {
            const int colg = n0 + warp_n + ni * 8 + tg * 2;
            const float bx = bias[colg], by = bias[colg + 1];
            const int r0 = m0 + warp_m + mi * 16 + g;
            const int r1 = r0 + 8;
            float2 o0, o1;
            o0.x = acc[mi][ni][0] + bx; o0.y = acc[mi][ni][1] + by;
            o1.x = acc[mi][ni][2] + bx; o1.y = acc[mi][ni][3] + by;
            if (hasRes) {
                const float2 v0 = *(const float2*)(res + (size_t)r0 * N + colg);
                const float2 v1 = *(const float2*)(res + (size_t)r1 * N + colg);
                o0.x += v0.x; o0.y += v0.y;
                o1.x += v1.x; o1.y += v1.y;
            }
            if (mode & 1) {
                *(float2*)(Cf + (size_t)r0 * N + colg) = o0;
                *(float2*)(Cf + (size_t)r1 * N + colg) = o1;
            }
            if (mode & 4) {
                *(uint32_t*)(C16 + (size_t)r0 * N + colg) = pack_h2(o0.x, o0.y);
                *(uint32_t*)(C16 + (size_t)r1 * N + colg) = pack_h2(o1.x, o1.y);
            }
        }
    }
}

// ---------------------------------------------------------------------------
// Tensor-core flash attention — all single fp16 (Q, K, P, V).
// 128-row Q tiles, 256 threads, base-2 softmax. Output: ctx fp16.
// ---------------------------------------------------------------------------
#define APAD 144
#define ATILE (64 * APAD)
#define AQTILE (128 * APAD)
#define AST0 AQTILE
#define ASTG (2 * ATILE)                     // K, V = 18432
#define AT_SMEM (AQTILE + 2 * ASTG)          // 55296

__global__ void __launch_bounds__(256)
attn_mma_kernel(
    const __half* __restrict__ qkv, __half* __restrict__ ct16)
{
    extern __shared__ __align__(16) char smem[];
    const uint32_t sbase = smem_u32(smem);

    const int b  = blockIdx.z;
    const int nh = blockIdx.y;
    const int qt = blockIdx.x;
    const int t  = threadIdx.x;
    const int wid  = t >> 5;
    const int lane = t & 31;
    const int g  = lane >> 2;
    const int tg = lane & 3;
    const int lrow  = lane & 15;
    const int lcolq = (lane >> 4) << 3;

    const size_t bS = (size_t)b * SS;
    const int hoff = nh * HD;

    // Q tile
    {
        const int crw = t >> 1;
        const int cqq = (t & 1) * 4;
        const size_t grow = (bS + qt * 128 + crw) * (3 * HH) + hoff;
        const uint32_t d = sbase + crw * APAD + cqq * 16;
#pragma unroll
        for (int i = 0; i < 4; i++)
            cp_async16(d + i * 16, qkv + grow + (cqq + i) * 8);
    }

    // K/V copy: threads 0-127 -> K, 128-255 -> V; 2 threads/row, 4 granules
    const int tt   = t & 127;
    const int kv   = t >> 7;
    const int crow = tt >> 1;
    const int cq0  = (tt & 1) * 4;
    const int srcoff = (kv + 1) * HH;
    const uint32_t tile_o = kv * ATILE;

#pragma unroll
    for (int p = 0; p < 2; p++) {
        const size_t grow = (bS + p * 64 + crow) * (3 * HH) + hoff + srcoff;
        const uint32_t d = sbase + AST0 + p * ASTG + tile_o + crow * APAD + cq0 * 16;
#pragma unroll
        for (int i = 0; i < 4; i++)
            cp_async16(d + i * 16, qkv + grow + (cq0 + i) * 8);
        cp_commit();
    }

    float acc_o[8][4];
#pragma unroll
    for (int nb = 0; nb < 8; nb++)
#pragma unroll
        for (int r = 0; r < 4; r++) acc_o[nb][r] = 0.0f;

    uint32_t aq[4][4];
    float m0 = -INFINITY, m1 = -INFINITY;
    float l0 = 0.0f, l1 = 0.0f;
    const float SC2 = 0.125f * 1.4426950408889634f;

    for (int kt = 0; kt < SS / 64; kt++) {
        if (kt == SS / 64 - 1) { cp_wait<0>(); } else { cp_wait<1>(); }
        __syncthreads();

        if (kt == 0) {
#pragma unroll
            for (int kb = 0; kb < 4; kb++) {
                const uint32_t off =
                    (uint32_t)(wid * 16 + lrow) * APAD + (kb * 16 + lcolq) * 2;
                ldsm_x4(sbase + off, aq[kb]);
            }
        }

        const uint32_t sK = sbase + AST0 + (kt & 1) * ASTG + 0 * ATILE;
        const uint32_t sV = sbase + AST0 + (kt & 1) * ASTG + 1 * ATILE;

        float s[8][4];
#pragma unroll
        for (int nb = 0; nb < 8; nb++)
#pragma unroll
            for (int r = 0; r < 4; r++) s[nb][r] = 0.0f;

#pragma unroll
        for (int n2 = 0; n2 < 4; n2++) {
#pragma unroll
            for (int kb = 0; kb < 4; kb++) {
                const uint32_t off =
                    (uint32_t)(n2 * 16 + lrow) * APAD + (kb * 16 + lcolq) * 2;
                uint32_t k4[4];
                ldsm_x4(sK + off, k4);
                mma_fp16(s[n2 * 2 + 0], aq[kb], k4[0], k4[2]);
                mma_fp16(s[n2 * 2 + 1], aq[kb], k4[1], k4[3]);
            }
        }

        // base-2 online softmax
        float mx0 = -INFINITY, mx1 = -INFINITY;
#pragma unroll
        for (int nb = 0; nb < 8; nb++) {
            s[nb][0] *= SC2; s[nb][1] *= SC2; s[nb][2] *= SC2; s[nb][3] *= SC2;
            mx0 = fmaxf(mx0, fmaxf(s[nb][0], s[nb][1]));
            mx1 = fmaxf(mx1, fmaxf(s[nb][2], s[nb][3]));
        }
        mx0 = fmaxf(mx0, __shfl_xor_sync(0xffffffffu, mx0, 1));
        mx0 = fmaxf(mx0, __shfl_xor_sync(0xffffffffu, mx0, 2));
        mx1 = fmaxf(mx1, __shfl_xor_sync(0xffffffffu, mx1, 1));
        mx1 = fmaxf(mx1, __shfl_xor_sync(0xffffffffu, mx1, 2));
        const float mn0 = fmaxf(m0, mx0);
        const float mn1 = fmaxf(m1, mx1);
        const float f0 = ex2f(m0 - mn0);
        const float f1 = ex2f(m1 - mn1);
        m0 = mn0; m1 = mn1;
        l0 *= f0; l1 *= f1;
#pragma unroll
        for (int nb = 0; nb < 8; nb++) {
            s[nb][0] = ex2f(s[nb][0] - mn0);
            s[nb][1] = ex2f(s[nb][1] - mn0);
            s[nb][2] = ex2f(s[nb][2] - mn1);
            s[nb][3] = ex2f(s[nb][3] - mn1);
            l0 += s[nb][0] + s[nb][1];
            l1 += s[nb][2] + s[nb][3];
            acc_o[nb][0] *= f0; acc_o[nb][1] *= f0;
            acc_o[nb][2] *= f1; acc_o[nb][3] *= f1;
        }

        uint32_t ph[4][4];
#pragma unroll
        for (int kb = 0; kb < 4; kb++) {
            ph[kb][0] = pack_h2(s[2 * kb][0],     s[2 * kb][1]);
            ph[kb][1] = pack_h2(s[2 * kb][2],     s[2 * kb][3]);
            ph[kb][2] = pack_h2(s[2 * kb + 1][0], s[2 * kb + 1][1]);
            ph[kb][3] = pack_h2(s[2 * kb + 1][2], s[2 * kb + 1][3]);
        }

#pragma unroll
        for (int kb = 0; kb < 4; kb++) {
#pragma unroll
            for (int n2 = 0; n2 < 4; n2++) {
                const uint32_t off =
                    (uint32_t)(kb * 16 + lrow) * APAD + (n2 * 16 + lcolq) * 2;
                uint32_t v4[4];
                ldsm_x4_t(sV + off, v4);
                mma_fp16(acc_o[n2 * 2 + 0], ph[kb], v4[0], v4[1]);
                mma_fp16(acc_o[n2 * 2 + 1], ph[kb], v4[2], v4[3]);
            }
        }

        __syncthreads();   // WAR guard: prefetch below writes the stage read above
        if (kt + 2 < SS / 64) {
            const size_t grow = (bS + (kt + 2) * 64 + crow) * (3 * HH) + hoff + srcoff;
            const uint32_t d = sbase + AST0 + (kt & 1) * ASTG + tile_o + crow * APAD + cq0 * 16;
#pragma unroll
            for (int i = 0; i < 4; i++)
                cp_async16(d + i * 16, qkv + grow + (cq0 + i) * 8);
        }
        cp_commit();
    }

    l0 += __shfl_xor_sync(0xffffffffu, l0, 1);
    l0 += __shfl_xor_sync(0xffffffffu, l0, 2);
    l1 += __shfl_xor_sync(0xffffffffu, l1, 1);
    l1 += __shfl_xor_sync(0xffffffffu, l1, 2);
    const float inv0 = 1.0f / l0;
    const float inv1 = 1.0f / l1;

    const size_t r0 = bS + qt * 128 + wid * 16 + g;
    const size_t r1 = r0 + 8;
#pragma unroll
    for (int nb = 0; nb < 8; nb++) {
        const int col = hoff + nb * 8 + tg * 2;
        *(uint32_t*)(ct16 + r0 * HH + col) =
            pack_h2(acc_o[nb][0] * inv0, acc_o[nb][1] * inv0);
        *(uint32_t*)(ct16 + r1 * HH + col) =
            pack_h2(acc_o[nb][2] * inv1, acc_o[nb][3] * inv1);
    }
}

// ---------------------------------------------------------------------------
// One-pass warp-per-row LayerNorm; emits fp32 + optional fp16
// ---------------------------------------------------------------------------
__global__ void __launch_bounds__(256) ln_kernel(
    const float* __restrict__ in, const float* __restrict__ gamma,
    const float* __restrict__ beta, float* __restrict__ out,
    __half* __restrict__ out16, int do16)
{
    const int warp = threadIdx.x >> 5;
    const int lane = threadIdx.x & 31;
    const int row  = blockIdx.x * 8 + warp;
    const float* x = in + (size_t)row * HH;

    float v[32];
    float s = 0.0f;
#pragma unroll
    for (int k = 0; k < 8; k++) {
        const float4 t4 = *(const float4*)&x[(k * 32 + lane) * 4];
        v[k * 4 + 0] = t4.x; v[k * 4 + 1] = t4.y;
        v[k * 4 + 2] = t4.z; v[k * 4 + 3] = t4.w;
        s += (t4.x + t4.y) + (t4.z + t4.w);
    }
#pragma unroll
    for (int o = 16; o > 0; o >>= 1) s += __shfl_xor_sync(0xffffffffu, s, o);
    const float mean = s * (1.0f / HH);

    float var = 0.0f;
#pragma unroll
    for (int i = 0; i < 32; i++) {
        const float d = v[i] - mean;
        var += d * d;
    }
#pragma unroll
    for (int o = 16; o > 0; o >>= 1) var += __shfl_xor_sync(0xffffffffu, var, o);
    const float rstd = rsqrtf(var * (1.0f / HH) + 1e-5f);

#pragma unroll
    for (int k = 0; k < 8; k++) {
        const int i0 = (k * 32 + lane) * 4;
        const float4 gv = *(const float4*)&gamma[i0];
        const float4 bv = *(const float4*)&beta[i0];
        float4 o;
        o.x = (v[k * 4 + 0] - mean) * rstd * gv.x + bv.x;
        o.y = (v[k * 4 + 1] - mean) * rstd * gv.y + bv.y;
        o.z = (v[k * 4 + 2] - mean) * rstd * gv.z + bv.z;
        o.w = (v[k * 4 + 3] - mean) * rstd * gv.w + bv.w;
        *(float4*)&out[(size_t)row * HH + i0] = o;
        if (do16) {
            uint2 p;
            p.x = pack_h2(o.x, o.y);
            p.y = pack_h2(o.z, o.w);
            *(uint2*)(out16 + (size_t)row * HH + i0) = p;
        }
    }
}

__global__ void __launch_bounds__(256) pool_kernel(
    const float* __restrict__ h, float* __restrict__ pooled)
{
    const int j = blockIdx.x * 256 + threadIdx.x;
    const int b = blockIdx.y;
    float s = 0.0f;
#pragma unroll 8
    for (int ss = 0; ss < SS; ss++)
        s += h[((size_t)b * SS + ss) * HH + j];
    pooled[b * HH + j] = s * (1.0f / SS);
}

__global__ void __launch_bounds__(256) final_gemm_kernel(
    const float* __restrict__ pooled, const float* __restrict__ W,
    const float* __restrict__ bias, float* __restrict__ out)
{
    __shared__ float pr[HH];
    const int b   = blockIdx.y;
    const int col = blockIdx.x * 256 + threadIdx.x;
    for (int i = threadIdx.x; i < HH; i += 256) pr[i] = pooled[b * HH + i];
    __syncthreads();
    float s = bias[col];
#pragma unroll 8
    for (int k = 0; k < HH; k++)
        s += pr[k] * W[(size_t)k * HH + col];
    out[b * HH + col] = s;
}

// ---------------------------------------------------------------------------
// Launch
// ---------------------------------------------------------------------------
extern "C" void kernel_launch(void* const* d_in, const int* in_sizes, int n_in,
                              void* d_out, int out_size)
{
    const float* x     = (const float*)d_in[0];
    const float* W_in  = (const float*)d_in[1];
    const float* b_in  = (const float*)d_in[2];
    const float* W_qkv = (const float*)d_in[3];
    const float* b_qkv = (const float*)d_in[4];
    const float* W_o   = (const float*)d_in[5];
    const float* b_o   = (const float*)d_in[6];
    const float* g1    = (const float*)d_in[7];
    const float* be1   = (const float*)d_in[8];
    const float* W_out = (const float*)d_in[9];
    const float* b_out = (const float*)d_in[10];
    const float* g2    = (const float*)d_in[11];
    const float* be2   = (const float*)d_in[12];
    float* out = (float*)d_out;

    float *h, *tmp, *pool, *fin;
    cudaGetSymbolAddress((void**)&h,    g_h);
    cudaGetSymbolAddress((void**)&tmp,  g_tmp);
    cudaGetSymbolAddress((void**)&pool, g_pool);
    cudaGetSymbolAddress((void**)&fin,  g_fin);

    __half *x16, *h16, *c16, *qkv16, *wh;
    cudaGetSymbolAddress((void**)&x16,   g_x16);
    cudaGetSymbolAddress((void**)&h16,   g_h16);
    cudaGetSymbolAddress((void**)&c16,   g_c16);
    cudaGetSymbolAddress((void**)&qkv16, g_qkv16);
    cudaGetSymbolAddress((void**)&wh,    g_wh);

    cudaFuncSetAttribute(mma_gemm_kernel, cudaFuncAttributeMaxDynamicSharedMemorySize, MM_SMEM);
    cudaFuncSetAttribute(attn_mma_kernel, cudaFuncAttributeMaxDynamicSharedMemorySize, AT_SMEM);

    // 0. batched weight transpose to fp16
    transpose_split_all<<<T_TOTAL, 256>>>(W_in, W_qkv, W_o, wh);

    // 1. x -> fp16; in-proj -> h fp32 + h16 (mode 5)
    {
        const int n4 = MROWS * DIN / 4;
        split_act_kernel<<<(n4 + 255) / 256, 256>>>(x, x16, n4);
        mma_gemm_kernel<<<dim3(HH / MBN, MROWS / MBM), 256, MM_SMEM>>>(
            x16, wh + OFF_WIN, b_in, nullptr,
            h, h16, MROWS, HH, DIN, 0, 5);
    }

    // 2. layers
    for (int l = 0; l < NLAYER; l++) {
        const __half* Wq = wh + OFF_WQKV + (size_t)l * 3 * HH * HH;
        const __half* Wo = wh + OFF_WO + (size_t)l * HH * HH;
        const float* bq = b_qkv + (size_t)l * 3 * HH;
        const float* bo = b_o + (size_t)l * HH;
        const float* gg = g1 + (size_t)l * HH;
        const float* bb = be1 + (size_t)l * HH;

        // qkv: single fp16 out (mode 4)
        mma_gemm_kernel<<<dim3(3 * HH / MBN, MROWS / MBM), 256, MM_SMEM>>>(
            h16, Wq, bq, nullptr,
            nullptr, qkv16, MROWS, 3 * HH, HH, 0, 4);

        // attention -> ctx fp16
        attn_mma_kernel<<<dim3(SS / 128, NHEAD, BB), 256, AT_SMEM>>>(qkv16, c16);

        // o-proj + residual -> fp32 tmp (mode 1)
        mma_gemm_kernel<<<dim3(HH / MBN, MROWS / MBM), 256, MM_SMEM>>>(
            c16, Wo, bo, h,
            tmp, nullptr, MROWS, HH, HH, 1, 1);

        // layernorm -> h fp32 + h16
        ln_kernel<<<MROWS / 8, 256>>>(tmp, gg, bb, h, h16, 1);
    }

    // 3. mean pool, final projection + LN
    pool_kernel<<<dim3(HH / 256, BB), 256>>>(h, pool);
    final_gemm_kernel<<<dim3(HH / 256, BB), 256>>>(pool, W_out, b_out, fin);
    ln_kernel<<<1, 256>>>(fin, g2, be2, out, nullptr, 0);
}

// round 17
// speedup vs baseline: 2.9571x; 1.0741x over previous
#include <cuda_runtime.h>
#include <cuda_bf16.h>
#include <cuda_fp16.h>
#include <math.h>
#include <stdint.h>

// Problem constants
#define BB 8
#define SS 1024
#define DIN 512
#define HH 1024
#define NHEAD 16
#define HD 64
#define NLAYER 4
#define MROWS (BB * SS)   // 8192

// ---------------------------------------------------------------------------
// Scratch (device globals; no allocation allowed)
// ---------------------------------------------------------------------------
__device__ float g_h[MROWS * HH];          // fp32 residual stream
__device__ float g_tmp[MROWS * HH];
__device__ float g_pool[BB * HH];
__device__ float g_fin[BB * HH];

__device__ __half g_x16[MROWS * DIN];
__device__ __half g_h16[MROWS * HH];
__device__ __half g_c16[MROWS * HH];
__device__ __half g_qkv16[MROWS * 3 * HH];

#define W_TOTAL (DIN * HH + NLAYER * HH * 3 * HH + NLAYER * HH * HH)
__device__ __half g_wh[W_TOTAL];

#define OFF_WIN  0
#define OFF_WQKV ((size_t)DIN * HH)
#define OFF_WO   (OFF_WQKV + (size_t)NLAYER * HH * 3 * HH)

// ---------------------------------------------------------------------------
// PTX wrappers (sm_80-portable)
// ---------------------------------------------------------------------------
__device__ __forceinline__ uint32_t smem_u32(const void* p) {
    uint32_t a;
    asm("{ .reg .u64 t; cvta.to.shared.u64 t, %1; cvt.u32.u64 %0, t; }"
        : "=r"(a) : "l"(p));
    return a;
}
__device__ __forceinline__ void cp_async16(uint32_t dst, const void* src) {
    asm volatile("cp.async.cg.shared.global [%0], [%1], 16;" :: "r"(dst), "l"(src));
}
__device__ __forceinline__ void cp_commit() {
    asm volatile("cp.async.commit_group;");
}
template <int N>
__device__ __forceinline__ void cp_wait() {
    asm volatile("cp.async.wait_group %0;" :: "n"(N));
}
__device__ __forceinline__ void ldsm_x4(uint32_t addr, uint32_t r[4]) {
    asm volatile("ldmatrix.sync.aligned.m8n8.x4.shared.b16 {%0,%1,%2,%3}, [%4];"
                 : "=r"(r[0]), "=r"(r[1]), "=r"(r[2]), "=r"(r[3]) : "r"(addr));
}
__device__ __forceinline__ void ldsm_x4_t(uint32_t addr, uint32_t r[4]) {
    asm volatile("ldmatrix.sync.aligned.m8n8.x4.trans.shared.b16 {%0,%1,%2,%3}, [%4];"
                 : "=r"(r[0]), "=r"(r[1]), "=r"(r[2]), "=r"(r[3]) : "r"(addr));
}
__device__ __forceinline__ void mma_fp16(
    float c[4], const uint32_t a[4], const uint32_t b0, const uint32_t b1)
{
    asm volatile(
        "mma.sync.aligned.m16n8k16.row.col.f32.f16.f16.f32 "
        "{%0,%1,%2,%3}, {%4,%5,%6,%7}, {%8,%9}, {%0,%1,%2,%3};"
        : "+f"(c[0]), "+f"(c[1]), "+f"(c[2]), "+f"(c[3])
        : "r"(a[0]), "r"(a[1]), "r"(a[2]), "r"(a[3]), "r"(b0), "r"(b1));
}
__device__ __forceinline__ float ex2f(float x) {
    float r;
    asm("ex2.approx.f32 %0, %1;" : "=f"(r) : "f"(x));
    return r;
}
__device__ __forceinline__ uint32_t pack_h2(float a, float b) {
    __half2 h = __floats2half2_rn(a, b);
    return *(uint32_t*)&h;
}

// ---------------------------------------------------------------------------
// Batched weight transpose to fp16
// ---------------------------------------------------------------------------
#define T_WIN   512
#define T_WQKV  3072
#define T_WO    1024
#define T_TOTAL (T_WIN + NLAYER * T_WQKV + NLAYER * T_WO)

__global__ void __launch_bounds__(256) transpose_split_all(
    const float* __restrict__ W_in, const float* __restrict__ W_qkv,
    const float* __restrict__ W_o, __half* __restrict__ wh)
{
    __shared__ float tile[32][33];
    int idx = blockIdx.x;
    const float* W;
    int K, N, t;
    size_t woff;
    if (idx < T_WIN) {
        W = W_in; K = DIN; N = HH; woff = OFF_WIN; t = idx;
    } else if (idx < T_WIN + NLAYER * T_WQKV) {
        const int l = (idx - T_WIN) / T_WQKV;
        t = (idx - T_WIN) % T_WQKV;
        W = W_qkv + (size_t)l * HH * 3 * HH;
        K = HH; N = 3 * HH;
        woff = OFF_WQKV + (size_t)l * 3 * HH * HH;
    } else {
        const int l = (idx - T_WIN - NLAYER * T_WQKV) / T_WO;
        t = (idx - T_WIN - NLAYER * T_WQKV) % T_WO;
        W = W_o + (size_t)l * HH * HH;
        K = HH; N = HH;
        woff = OFF_WO + (size_t)l * HH * HH;
    }
    const int tpr = N / 32;
    const int n0 = (t % tpr) * 32;
    const int k0 = (t / tpr) * 32;
    const int tx = threadIdx.x & 31;
    const int ty = threadIdx.x >> 5;

#pragma unroll
    for (int r = 0; r < 32; r += 8)
        tile[ty + r][tx] = W[(size_t)(k0 + ty + r) * N + n0 + tx];
    __syncthreads();
#pragma unroll
    for (int r = 0; r < 32; r += 8) {
        const float v = tile[tx][ty + r];
        wh[woff + (size_t)(n0 + ty + r) * K + k0 + tx] = __float2half_rn(v);
    }
}

// ---------------------------------------------------------------------------
// Activation to fp16 (x only)
// ---------------------------------------------------------------------------
__global__ void split_act_kernel(
    const float* __restrict__ in, __half* __restrict__ o16, int n4)
{
    const int i = blockIdx.x * 256 + threadIdx.x;
    if (i >= n4) return;
    const float4 v = ((const float4*)in)[i];
    uint2 p;
    p.x = pack_h2(v.x, v.y);
    p.y = pack_h2(v.z, v.w);
    ((uint2*)o16)[i] = p;
}

// ---------------------------------------------------------------------------
// Single-pass fp16 HMMA GEMM — R17: 3-stage cp.async pipeline, ONE barrier
// per K-chunk (stage written at iter c was last read at iter c-1, before this
// iter's barrier). 60KB smem -> still 2 CTAs/SM at 128 regs.
// mode bit0: fp32 Cf; bit2: fp16 C16.
// ---------------------------------------------------------------------------
#define MBM 128
#define MBN 128
#define MBK 32
#define MSTR 40
#define MTILE (128 * MSTR * 2)    // 10240 B
#define MSTAGE (2 * MTILE)        // A, B = 20480 B
#define NSTG 3
#define MM_SMEM (NSTG * MSTAGE)   // 61440 B

__global__ void __launch_bounds__(256, 2)
mma_gemm_kernel(
    const __half* __restrict__ Af, const __half* __restrict__ Bf,
    const float* __restrict__ bias, const float* __restrict__ res,
    float* __restrict__ Cf, __half* __restrict__ C16,
    int M, int N, int K, int hasRes, int mode)
{
    extern __shared__ __align__(16) char smem[];
    const uint32_t sbase = smem_u32(smem);

    const int t    = threadIdx.x;
    const int wid  = t >> 5;
    const int lane = t & 31;
    const int m0 = blockIdx.y * MBM;
    const int n0 = blockIdx.x * MBN;

    const int warp_m = (wid >> 2) * 64;
    const int warp_n = (wid & 3) * 32;

    const int crow  = t >> 1;
    const int cq    = (t & 1) * 2;

    const __half* gsrc[2];
    gsrc[0] = Af + (size_t)(m0 + crow) * K;
    gsrc[1] = Bf + (size_t)(n0 + crow) * K;
    const uint32_t sdst_row = crow * (MSTR * 2);

    const int nc = K / MBK;

    // prologue: stages 0 and 1, one group each
#pragma unroll
    for (int p = 0; p < 2; p++) {
        const int k0 = p * MBK;
        const uint32_t so = p * MSTAGE;
#pragma unroll
        for (int tl = 0; tl < 2; tl++) {
            const uint32_t d = sbase + so + tl * MTILE + sdst_row;
            cp_async16(d + (cq + 0) * 16, gsrc[tl] + k0 + (cq + 0) * 8);
            cp_async16(d + (cq + 1) * 16, gsrc[tl] + k0 + (cq + 1) * 8);
        }
        cp_commit();
    }

    float acc[4][4][4];
#pragma unroll
    for (int mi = 0; mi < 4; mi++)
#pragma unroll
        for (int ni = 0; ni < 4; ni++)
#pragma unroll
            for (int r = 0; r < 4; r++) acc[mi][ni][r] = 0.0f;

    const int lrow = lane & 15;
    const int lcolq = (lane >> 4) << 3;

    int st = 0, wr = 2;
    for (int c = 0; c < nc; c++) {
        cp_wait<1>();          // chunk c's group complete (c+1 may pend)
        __syncthreads();       // all warps done with stage wr (read at c-1)

        if (c + 2 < nc) {
            const int k0 = (c + 2) * MBK;
            const uint32_t so = wr * MSTAGE;
#pragma unroll
            for (int tl = 0; tl < 2; tl++) {
                const uint32_t d = sbase + so + tl * MTILE + sdst_row;
                cp_async16(d + (cq + 0) * 16, gsrc[tl] + k0 + (cq + 0) * 8);
                cp_async16(d + (cq + 1) * 16, gsrc[tl] + k0 + (cq + 1) * 8);
            }
        }
        cp_commit();           // empty group near tail keeps accounting

        const uint32_t sA = sbase + st * MSTAGE + 0 * MTILE;
        const uint32_t sB = sbase + st * MSTAGE + 1 * MTILE;

#pragma unroll
        for (int ks = 0; ks < 2; ks++) {
            const int col = ks * 16 + lcolq;
            uint32_t af[4][4];
#pragma unroll
            for (int mi = 0; mi < 4; mi++) {
                const uint32_t off =
                    (uint32_t)(warp_m + mi * 16 + lrow) * (MSTR * 2) + col * 2;
                ldsm_x4(sA + off, af[mi]);
            }
            uint32_t bf[4][2];
#pragma unroll
            for (int n2 = 0; n2 < 2; n2++) {
                const uint32_t off =
                    (uint32_t)(warp_n + n2 * 16 + lrow) * (MSTR * 2) + col * 2;
                uint32_t r4[4];
                ldsm_x4(sB + off, r4);
                bf[n2 * 2 + 0][0] = r4[0]; bf[n2 * 2 + 1][0] = r4[1];
                bf[n2 * 2 + 0][1] = r4[2]; bf[n2 * 2 + 1][1] = r4[3];
            }
#pragma unroll
            for (int mi = 0; mi < 4; mi++)
#pragma unroll
                for (int ni = 0; ni < 4; ni++)
                    mma_fp16(acc[mi][ni], af[mi], bf[ni][0], bf[ni][1]);
        }
        st = (st == NSTG - 1) ? 0 : st + 1;
        wr = (wr == NSTG - 1) ? 0 : wr + 1;
    }

    const int g  = lane >> 2;
    const int tg = lane & 3;
#pragma unroll
    for (int mi = 0; mi < 4; mi++) {
#pragma unroll
        for (int ni = 0; ni < 4; ni++) {
            const int colg = n0 + warp_n + ni * 8 + tg * 2;
            const float bx = bias[colg], by = bias[colg + 1];
            const int r0 = m0 + warp_m + mi * 16 + g;
            const int r1 = r0 + 8;
            float2 o0, o1;
            o0.x = acc[mi][ni][0] + bx; o0.y = acc[mi][ni][1] + by;
            o1.x = acc[mi][ni][2] + bx; o1.y = acc[mi][ni][3] + by;
            if (hasRes) {
                const float2 v0 = *(const float2*)(res + (size_t)r0 * N + colg);
                const float2 v1 = *(const float2*)(res + (size_t)r1 * N + colg);
                o0.x += v0.x; o0.y += v0.y;
                o1.x += v1.x; o1.y += v1.y;
            }
            if (mode & 1) {
                *(float2*)(Cf + (size_t)r0 * N + colg) = o0;
                *(float2*)(Cf + (size_t)r1 * N + colg) = o1;
            }
            if (mode & 4) {
                *(uint32_t*)(C16 + (size_t)r0 * N + colg) = pack_h2(o0.x, o0.y);
                *(uint32_t*)(C16 + (size_t)r1 * N + colg) = pack_h2(o1.x, o1.y);
            }
        }
    }
}

// ---------------------------------------------------------------------------
// Tensor-core flash attention — all single fp16 (R16 config, verified).
// ---------------------------------------------------------------------------
#define APAD 144
#define ATILE (64 * APAD)
#define AQTILE (128 * APAD)
#define AST0 AQTILE
#define ASTG (2 * ATILE)
#define AT_SMEM (AQTILE + 2 * ASTG)          // 55296

__global__ void __launch_bounds__(256)
attn_mma_kernel(
    const __half* __restrict__ qkv, __half* __restrict__ ct16)
{
    extern __shared__ __align__(16) char smem[];
    const uint32_t sbase = smem_u32(smem);

    const int b  = blockIdx.z;
    const int nh = blockIdx.y;
    const int qt = blockIdx.x;
    const int t  = threadIdx.x;
    const int wid  = t >> 5;
    const int lane = t & 31;
    const int g  = lane >> 2;
    const int tg = lane & 3;
    const int lrow  = lane & 15;
    const int lcolq = (lane >> 4) << 3;

    const size_t bS = (size_t)b * SS;
    const int hoff = nh * HD;

    {
        const int crw = t >> 1;
        const int cqq = (t & 1) * 4;
        const size_t grow = (bS + qt * 128 + crw) * (3 * HH) + hoff;
        const uint32_t d = sbase + crw * APAD + cqq * 16;
#pragma unroll
        for (int i = 0; i < 4; i++)
            cp_async16(d + i * 16, qkv + grow + (cqq + i) * 8);
    }

    const int tt   = t & 127;
    const int kv   = t >> 7;
    const int crow = tt >> 1;
    const int cq0  = (tt & 1) * 4;
    const int srcoff = (kv + 1) * HH;
    const uint32_t tile_o = kv * ATILE;

#pragma unroll
    for (int p = 0; p < 2; p++) {
        const size_t grow = (bS + p * 64 + crow) * (3 * HH) + hoff + srcoff;
        const uint32_t d = sbase + AST0 + p * ASTG + tile_o + crow * APAD + cq0 * 16;
#pragma unroll
        for (int i = 0; i < 4; i++)
            cp_async16(d + i * 16, qkv + grow + (cq0 + i) * 8);
        cp_commit();
    }

    float acc_o[8][4];
#pragma unroll
    for (int nb = 0; nb < 8; nb++)
#pragma unroll
        for (int r = 0; r < 4; r++) acc_o[nb][r] = 0.0f;

    uint32_t aq[4][4];
    float m0 = -INFINITY, m1 = -INFINITY;
    float l0 = 0.0f, l1 = 0.0f;
    const float SC2 = 0.125f * 1.4426950408889634f;

    for (int kt = 0; kt < SS / 64; kt++) {
        if (kt == SS / 64 - 1) { cp_wait<0>(); } else { cp_wait<1>(); }
        __syncthreads();

        if (kt == 0) {
#pragma unroll
            for (int kb = 0; kb < 4; kb++) {
                const uint32_t off =
                    (uint32_t)(wid * 16 + lrow) * APAD + (kb * 16 + lcolq) * 2;
                ldsm_x4(sbase + off, aq[kb]);
            }
        }

        const uint32_t sK = sbase + AST0 + (kt & 1) * ASTG + 0 * ATILE;
        const uint32_t sV = sbase + AST0 + (kt & 1) * ASTG + 1 * ATILE;

        float s[8][4];
#pragma unroll
        for (int nb = 0; nb < 8; nb++)
#pragma unroll
            for (int r = 0; r < 4; r++) s[nb][r] = 0.0f;

#pragma unroll
        for (int n2 = 0; n2 < 4; n2++) {
#pragma unroll
            for (int kb = 0; kb < 4; kb++) {
                const uint32_t off =
                    (uint32_t)(n2 * 16 + lrow) * APAD + (kb * 16 + lcolq) * 2;
                uint32_t k4[4];
                ldsm_x4(sK + off, k4);
                mma_fp16(s[n2 * 2 + 0], aq[kb], k4[0], k4[2]);
                mma_fp16(s[n2 * 2 + 1], aq[kb], k4[1], k4[3]);
            }
        }

        float mx0 = -INFINITY, mx1 = -INFINITY;
#pragma unroll
        for (int nb = 0; nb < 8; nb++) {
            s[nb][0] *= SC2; s[nb][1] *= SC2; s[nb][2] *= SC2; s[nb][3] *= SC2;
            mx0 = fmaxf(mx0, fmaxf(s[nb][0], s[nb][1]));
            mx1 = fmaxf(mx1, fmaxf(s[nb][2], s[nb][3]));
        }
        mx0 = fmaxf(mx0, __shfl_xor_sync(0xffffffffu, mx0, 1));
        mx0 = fmaxf(mx0, __shfl_xor_sync(0xffffffffu, mx0, 2));
        mx1 = fmaxf(mx1, __shfl_xor_sync(0xffffffffu, mx1, 1));
        mx1 = fmaxf(mx1, __shfl_xor_sync(0xffffffffu, mx1, 2));
        const float mn0 = fmaxf(m0, mx0);
        const float mn1 = fmaxf(m1, mx1);
        const float f0 = ex2f(m0 - mn0);
        const float f1 = ex2f(m1 - mn1);
        m0 = mn0; m1 = mn1;
        l0 *= f0; l1 *= f1;
#pragma unroll
        for (int nb = 0; nb < 8; nb++) {
            s[nb][0] = ex2f(s[nb][0] - mn0);
            s[nb][1] = ex2f(s[nb][1] - mn0);
            s[nb][2] = ex2f(s[nb][2] - mn1);
            s[nb][3] = ex2f(s[nb][3] - mn1);
            l0 += s[nb][0] + s[nb][1];
            l1 += s[nb][2] + s[nb][3];
            acc_o[nb][0] *= f0; acc_o[nb][1] *= f0;
            acc_o[nb][2] *= f1; acc_o[nb][3] *= f1;
        }

        uint32_t ph[4][4];
#pragma unroll
        for (int kb = 0; kb < 4; kb++) {
            ph[kb][0] = pack_h2(s[2 * kb][0],     s[2 * kb][1]);
            ph[kb][1] = pack_h2(s[2 * kb][2],     s[2 * kb][3]);
            ph[kb][2] = pack_h2(s[2 * kb + 1][0], s[2 * kb + 1][1]);
            ph[kb][3] = pack_h2(s[2 * kb + 1][2], s[2 * kb + 1][3]);
        }

#pragma unroll
        for (int kb = 0; kb < 4; kb++) {
#pragma unroll
            for (int n2 = 0; n2 < 4; n2++) {
                const uint32_t off =
                    (uint32_t)(kb * 16 + lrow) * APAD + (n2 * 16 + lcolq) * 2;
                uint32_t v4[4];
                ldsm_x4_t(sV + off, v4);
                mma_fp16(acc_o[n2 * 2 + 0], ph[kb], v4[0], v4[1]);
                mma_fp16(acc_o[n2 * 2 + 1], ph[kb], v4[2], v4[3]);
            }
        }

        __syncthreads();   // WAR guard: prefetch below writes the stage read above
        if (kt + 2 < SS / 64) {
            const size_t grow = (bS + (kt + 2) * 64 + crow) * (3 * HH) + hoff + srcoff;
            const uint32_t d = sbase + AST0 + (kt & 1) * ASTG + tile_o + crow * APAD + cq0 * 16;
#pragma unroll
            for (int i = 0; i < 4; i++)
                cp_async16(d + i * 16, qkv + grow + (cq0 + i) * 8);
        }
        cp_commit();
    }

    l0 += __shfl_xor_sync(0xffffffffu, l0, 1);
    l0 += __shfl_xor_sync(0xffffffffu, l0, 2);
    l1 += __shfl_xor_sync(0xffffffffu, l1, 1);
    l1 += __shfl_xor_sync(0xffffffffu, l1, 2);
    const float inv0 = 1.0f / l0;
    const float inv1 = 1.0f / l1;

    const size_t r0 = bS + qt * 128 + wid * 16 + g;
    const size_t r1 = r0 + 8;
#pragma unroll
    for (int nb = 0; nb < 8; nb++) {
        const int col = hoff + nb * 8 + tg * 2;
        *(uint32_t*)(ct16 + r0 * HH + col) =
            pack_h2(acc_o[nb][0] * inv0, acc_o[nb][1] * inv0);
        *(uint32_t*)(ct16 + r1 * HH + col) =
            pack_h2(acc_o[nb][2] * inv1, acc_o[nb][3] * inv1);
    }
}

// ---------------------------------------------------------------------------
// One-pass warp-per-row LayerNorm; emits fp32 + optional fp16
// ---------------------------------------------------------------------------
__global__ void __launch_bounds__(256) ln_kernel(
    const float* __restrict__ in, const float* __restrict__ gamma,
    const float* __restrict__ beta, float* __restrict__ out,
    __half* __restrict__ out16, int do16)
{
    const int warp = threadIdx.x >> 5;
    const int lane = threadIdx.x & 31;
    const int row  = blockIdx.x * 8 + warp;
    const float* x = in + (size_t)row * HH;

    float v[32];
    float s = 0.0f;
#pragma unroll
    for (int k = 0; k < 8; k++) {
        const float4 t4 = *(const float4*)&x[(k * 32 + lane) * 4];
        v[k * 4 + 0] = t4.x; v[k * 4 + 1] = t4.y;
        v[k * 4 + 2] = t4.z; v[k * 4 + 3] = t4.w;
        s += (t4.x + t4.y) + (t4.z + t4.w);
    }
#pragma unroll
    for (int o = 16; o > 0; o >>= 1) s += __shfl_xor_sync(0xffffffffu, s, o);
    const float mean = s * (1.0f / HH);

    float var = 0.0f;
#pragma unroll
    for (int i = 0; i < 32; i++) {
        const float d = v[i] - mean;
        var += d * d;
    }
#pragma unroll
    for (int o = 16; o > 0; o >>= 1) var += __shfl_xor_sync(0xffffffffu, var, o);
    const float rstd = rsqrtf(var * (1.0f / HH) + 1e-5f);

#pragma unroll
    for (int k = 0; k < 8; k++) {
        const int i0 = (k * 32 + lane) * 4;
        const float4 gv = *(const float4*)&gamma[i0];
        const float4 bv = *(const float4*)&beta[i0];
        float4 o;
        o.x = (v[k * 4 + 0] - mean) * rstd * gv.x + bv.x;
        o.y = (v[k * 4 + 1] - mean) * rstd * gv.y + bv.y;
        o.z = (v[k * 4 + 2] - mean) * rstd * gv.z + bv.z;
        o.w = (v[k * 4 + 3] - mean) * rstd * gv.w + bv.w;
        *(float4*)&out[(size_t)row * HH + i0] = o;
        if (do16) {
            uint2 p;
            p.x = pack_h2(o.x, o.y);
            p.y = pack_h2(o.z, o.w);
            *(uint2*)(out16 + (size_t)row * HH + i0) = p;
        }
    }
}

__global__ void __launch_bounds__(256) pool_kernel(
    const float* __restrict__ h, float* __restrict__ pooled)
{
    const int j = blockIdx.x * 256 + threadIdx.x;
    const int b = blockIdx.y;
    float s = 0.0f;
#pragma unroll 8
    for (int ss = 0; ss < SS; ss++)
        s += h[((size_t)b * SS + ss) * HH + j];
    pooled[b * HH + j] = s * (1.0f / SS);
}

__global__ void __launch_bounds__(256) final_gemm_kernel(
    const float* __restrict__ pooled, const float* __restrict__ W,
    const float* __restrict__ bias, float* __restrict__ out)
{
    __shared__ float pr[HH];
    const int b   = blockIdx.y;
    const int col = blockIdx.x * 256 + threadIdx.x;
    for (int i = threadIdx.x; i < HH; i += 256) pr[i] = pooled[b * HH + i];
    __syncthreads();
    float s = bias[col];
#pragma unroll 8
    for (int k = 0; k < HH; k++)
        s += pr[k] * W[(size_t)k * HH + col];
    out[b * HH + col] = s;
}

// ---------------------------------------------------------------------------
// Launch
// ---------------------------------------------------------------------------
extern "C" void kernel_launch(void* const* d_in, const int* in_sizes, int n_in,
                              void* d_out, int out_size)
{
    const float* x     = (const float*)d_in[0];
    const float* W_in  = (const float*)d_in[1];
    const float* b_in  = (const float*)d_in[2];
    const float* W_qkv = (const float*)d_in[3];
    const float* b_qkv = (const float*)d_in[4];
    const float* W_o   = (const float*)d_in[5];
    const float* b_o   = (const float*)d_in[6];
    const float* g1    = (const float*)d_in[7];
    const float* be1   = (const float*)d_in[8];
    const float* W_out = (const float*)d_in[9];
    const float* b_out = (const float*)d_in[10];
    const float* g2    = (const float*)d_in[11];
    const float* be2   = (const float*)d_in[12];
    float* out = (float*)d_out;

    float *h, *tmp, *pool, *fin;
    cudaGetSymbolAddress((void**)&h,    g_h);
    cudaGetSymbolAddress((void**)&tmp,  g_tmp);
    cudaGetSymbolAddress((void**)&pool, g_pool);
    cudaGetSymbolAddress((void**)&fin,  g_fin);

    __half *x16, *h16, *c16, *qkv16, *wh;
    cudaGetSymbolAddress((void**)&x16,   g_x16);
    cudaGetSymbolAddress((void**)&h16,   g_h16);
    cudaGetSymbolAddress((void**)&c16,   g_c16);
    cudaGetSymbolAddress((void**)&qkv16, g_qkv16);
    cudaGetSymbolAddress((void**)&wh,    g_wh);

    cudaFuncSetAttribute(mma_gemm_kernel, cudaFuncAttributeMaxDynamicSharedMemorySize, MM_SMEM);
    cudaFuncSetAttribute(attn_mma_kernel, cudaFuncAttributeMaxDynamicSharedMemorySize, AT_SMEM);

    // 0. batched weight transpose to fp16
    transpose_split_all<<<T_TOTAL, 256>>>(W_in, W_qkv, W_o, wh);

    // 1. x -> fp16; in-proj -> h fp32 + h16 (mode 5)
    {
        const int n4 = MROWS * DIN / 4;
        split_act_kernel<<<(n4 + 255) / 256, 256>>>(x, x16, n4);
        mma_gemm_kernel<<<dim3(HH / MBN, MROWS / MBM), 256, MM_SMEM>>>(
            x16, wh + OFF_WIN, b_in, nullptr,
            h, h16, MROWS, HH, DIN, 0, 5);
    }

    // 2. layers
    for (int l = 0; l < NLAYER; l++) {
        const __half* Wq = wh + OFF_WQKV + (size_t)l * 3 * HH * HH;
        const __half* Wo = wh + OFF_WO + (size_t)l * HH * HH;
        const float* bq = b_qkv + (size_t)l * 3 * HH;
        const float* bo = b_o + (size_t)l * HH;
        const float* gg = g1 + (size_t)l * HH;
        const float* bb = be1 + (size_t)l * HH;

        // qkv: single fp16 out (mode 4)
        mma_gemm_kernel<<<dim3(3 * HH / MBN, MROWS / MBM), 256, MM_SMEM>>>(
            h16, Wq, bq, nullptr,
            nullptr, qkv16, MROWS, 3 * HH, HH, 0, 4);

        // attention -> ctx fp16
        attn_mma_kernel<<<dim3(SS / 128, NHEAD, BB), 256, AT_SMEM>>>(qkv16, c16);

        // o-proj + residual -> fp32 tmp (mode 1)
        mma_gemm_kernel<<<dim3(HH / MBN, MROWS / MBM), 256, MM_SMEM>>>(
            c16, Wo, bo, h,
            tmp, nullptr, MROWS, HH, HH, 1, 1);

        // layernorm -> h fp32 + h16
        ln_kernel<<<MROWS / 8, 256>>>(tmp, gg, bb, h, h16, 1);
    }

    // 3. mean pool, final projection + LN
    pool_kernel<<<dim3(HH / 256, BB), 256>>>(h, pool);
    final_gemm_kernel<<<dim3(HH / 256, BB), 256>>>(pool, W_out, b_out, fin);
    ln_kernel<<<1, 256>>>(fin, g2, be2, out, nullptr, 0);
}